// round 3
// baseline (speedup 1.0000x reference)
#include <cuda_runtime.h>
#include <cuda_bf16.h>
#include <cstdint>

#define B_   16
#define C_   512
#define NH   8
#define HD   64
#define N_   1024
#define G_   32
#define CPG  16
#define EPSV 1e-5f
#define KEXT 1536          // 3 * C_ (split-bf16 extended K)

// ---------------- scratch (device globals; no allocation allowed) -----------
__device__ float         g_qkv[(size_t)3 * B_ * NH * HD * N_];        // [s][b][h][d][n] fp32
__device__ __nv_bfloat16 g_hn_ext[(size_t)B_ * N_ * KEXT];            // [b][n][kext]: hi,hi,lo
__device__ __nv_bfloat16 g_obuf_ext[(size_t)B_ * N_ * KEXT];          // [b][n][kext]: hi,hi,lo
__device__ __nv_bfloat16 g_wqkv_ext[(size_t)(3*C_) * KEXT];           // [o][kext]: hi,lo,hi
__device__ __nv_bfloat16 g_wproj_ext[(size_t)C_ * KEXT];              // [o][kext]: hi,lo,hi

// ---------------- warp MMA helpers (baseline PTX, works on sm_103) ----------
__device__ __forceinline__ uint32_t smem_u32(const void* p) {
    uint32_t a;
    asm("{ .reg .u64 t; cvta.to.shared.u64 t, %1; cvt.u32.u64 %0, t; }" : "=r"(a) : "l"(p));
    return a;
}
__device__ __forceinline__ void ldsm_x4(uint32_t* r, uint32_t addr) {
    asm volatile("ldmatrix.sync.aligned.m8n8.x4.shared.b16 {%0,%1,%2,%3}, [%4];"
                 : "=r"(r[0]), "=r"(r[1]), "=r"(r[2]), "=r"(r[3]) : "r"(addr));
}
__device__ __forceinline__ void ldsm_x2(uint32_t* r, uint32_t addr) {
    asm volatile("ldmatrix.sync.aligned.m8n8.x2.shared.b16 {%0,%1}, [%2];"
                 : "=r"(r[0]), "=r"(r[1]) : "r"(addr));
}
__device__ __forceinline__ void mma_bf16(float* c, const uint32_t* a, const uint32_t* b) {
    asm volatile("mma.sync.aligned.m16n8k16.row.col.f32.bf16.bf16.f32 "
                 "{%0,%1,%2,%3}, {%4,%5,%6,%7}, {%8,%9}, {%0,%1,%2,%3};"
                 : "+f"(c[0]), "+f"(c[1]), "+f"(c[2]), "+f"(c[3])
                 : "r"(a[0]), "r"(a[1]), "r"(a[2]), "r"(a[3]), "r"(b[0]), "r"(b[1]));
}

// ---------------------------------------------------------------------------
// 0) Weight split: w[o][c] fp32 -> ext[o][kext] bf16 (hi, lo, hi)
// ---------------------------------------------------------------------------
__global__ void convw_kernel(const float* __restrict__ w, __nv_bfloat16* __restrict__ ext) {
    int r = blockIdx.x;
    for (int c = threadIdx.x; c < C_; c += 128) {
        float v = w[(size_t)r * C_ + c];
        __nv_bfloat16 hi = __float2bfloat16(v);
        __nv_bfloat16 lo = __float2bfloat16(v - __bfloat162float(hi));
        size_t base = (size_t)r * KEXT;
        ext[base + c]          = hi;
        ext[base + C_ + c]     = lo;
        ext[base + 2 * C_ + c] = hi;
    }
}

// ---------------------------------------------------------------------------
// 1) GroupNorm + transpose + bf16 split: x[b][c][n] -> g_hn_ext[b][n][kext]
// ---------------------------------------------------------------------------
__global__ __launch_bounds__(256) void gn_kernel(const float* __restrict__ x,
                                                 const float* __restrict__ w,
                                                 const float* __restrict__ bb) {
    extern __shared__ float gsm[];                 // 16 ch * 1024 n fp32 = 64KB
    int bg = blockIdx.x;                           // b*32 + g
    int g = bg & (G_ - 1), b = bg >> 5;
    const float4* x4 = (const float4*)(x + (size_t)bg * CPG * N_);
    float4* s4 = (float4*)gsm;
    int tid = threadIdx.x;

    float s = 0.f, s2 = 0.f;
    #pragma unroll 4
    for (int i = tid; i < 4096; i += 256) {
        float4 v = x4[i];
        s4[i] = v;
        s  += v.x + v.y + v.z + v.w;
        s2 += v.x*v.x + v.y*v.y + v.z*v.z + v.w*v.w;
    }
    __shared__ float rs[256], rs2[256];
    rs[tid] = s; rs2[tid] = s2;
    __syncthreads();
    for (int off = 128; off > 0; off >>= 1) {
        if (tid < off) { rs[tid] += rs[tid+off]; rs2[tid] += rs2[tid+off]; }
        __syncthreads();
    }
    float mean = rs[0] * (1.f/16384.f);
    float var  = rs2[0] * (1.f/16384.f) - mean*mean;
    float rstd = rsqrtf(var + EPSV);

    float sc[CPG], sh[CPG];
    #pragma unroll
    for (int c16 = 0; c16 < CPG; c16++) {
        int c = g*CPG + c16;
        sc[c16] = rstd * w[c];
        sh[c16] = bb[c] - mean * sc[c16];
    }

    union Pack { __nv_bfloat16 h[CPG]; uint4 v[2]; };
    for (int n = tid; n < N_; n += 256) {
        Pack hiP, loP;
        #pragma unroll
        for (int c16 = 0; c16 < CPG; c16++) {
            float v = gsm[c16 * N_ + n] * sc[c16] + sh[c16];
            __nv_bfloat16 hv = __float2bfloat16(v);
            hiP.h[c16] = hv;
            loP.h[c16] = __float2bfloat16(v - __bfloat162float(hv));
        }
        __nv_bfloat16* dst = g_hn_ext + ((size_t)b * N_ + n) * KEXT + g * CPG;
        *(uint4*)(dst)          = hiP.v[0]; *(uint4*)(dst + 8)          = hiP.v[1];
        *(uint4*)(dst + C_)     = hiP.v[0]; *(uint4*)(dst + C_ + 8)     = hiP.v[1];
        *(uint4*)(dst + 2*C_)   = loP.v[0]; *(uint4*)(dst + 2*C_ + 8)   = loP.v[1];
    }
}

// ---------------------------------------------------------------------------
// HMMA GEMM mainloop: D[128m][128n] = sum_k A[m][k]*B[n][k], K=KEXT, BK=64.
// 256 thr = 8 warps (2 m x 4 n), warp tile 64x32, m16n8k16 bf16 mma.
// ---------------------------------------------------------------------------
#define SSTR 88                       // smem row stride in bf16 (176B = 11*16B)
struct GemmSm {
    __nv_bfloat16 A[128 * SSTR];
    __nv_bfloat16 B[128 * SSTR];
};

__device__ __forceinline__ void gemm_mainloop(GemmSm* sm, float acc[4][4][4],
                                              const __nv_bfloat16* __restrict__ Abase,
                                              const __nv_bfloat16* __restrict__ Bbase) {
    int tid = threadIdx.x, wid = tid >> 5, lane = tid & 31;
    int wm = (wid >> 2) * 64;          // warp m offset
    int wn = (wid & 3) * 32;           // warp n offset

    uint32_t smA = smem_u32(sm->A), smB = smem_u32(sm->B);
    // ldmatrix per-lane address components
    int aRow = wm + (lane & 15), aCol = (lane >> 4) * 8;
    int bRow = wn + (lane & 7),  bCol = ((lane >> 3) & 1) * 8;

    int ldRow = tid >> 3;              // gmem->smem: 32 rows per pass (256thr/8seg)
    int ldSeg = tid & 7;               // 8 uint4 segments of 8 bf16 per 64-k row

    #pragma unroll 1
    for (int c = 0; c < KEXT / 64; c++) {
        int k0 = c * 64;
        __syncthreads();
        #pragma unroll
        for (int rr = 0; rr < 4; rr++) {
            int row = ldRow + rr * 32;
            *(uint4*)&sm->A[row * SSTR + ldSeg * 8] =
                *(const uint4*)(Abase + (size_t)row * KEXT + k0 + ldSeg * 8);
            *(uint4*)&sm->B[row * SSTR + ldSeg * 8] =
                *(const uint4*)(Bbase + (size_t)row * KEXT + k0 + ldSeg * 8);
        }
        __syncthreads();

        #pragma unroll
        for (int ks = 0; ks < 4; ks++) {
            uint32_t af[4][4], bf[4][2];
            #pragma unroll
            for (int mi = 0; mi < 4; mi++)
                ldsm_x4(af[mi], smA + ((aRow + mi*16) * SSTR + ks*16 + aCol) * 2);
            #pragma unroll
            for (int ni = 0; ni < 4; ni++)
                ldsm_x2(bf[ni], smB + ((bRow + ni*8) * SSTR + ks*16 + bCol) * 2);
            #pragma unroll
            for (int mi = 0; mi < 4; mi++)
                #pragma unroll
                for (int ni = 0; ni < 4; ni++)
                    mma_bf16(acc[mi][ni], af[mi], bf[ni]);
        }
    }
}

// ---------------------------------------------------------------------------
// 2) QKV GEMM -> g_qkv[s][b][h][d][n] (float2 stores, sector-aligned)
// ---------------------------------------------------------------------------
__global__ __launch_bounds__(256) void qkv_gemm(const float* __restrict__ bias) {
    __shared__ GemmSm sm;
    int n0 = blockIdx.x * 128, m0 = blockIdx.y * 128, b = blockIdx.z;

    float acc[4][4][4];
    #pragma unroll
    for (int i = 0; i < 4; i++)
        #pragma unroll
        for (int j = 0; j < 4; j++)
            { acc[i][j][0]=0.f; acc[i][j][1]=0.f; acc[i][j][2]=0.f; acc[i][j][3]=0.f; }

    gemm_mainloop(&sm, acc,
        g_wqkv_ext + (size_t)m0 * KEXT,
        g_hn_ext + ((size_t)b * N_ + n0) * KEXT);

    int wid = threadIdx.x >> 5, lane = threadIdx.x & 31;
    int wm = (wid >> 2) * 64, wn = (wid & 3) * 32;

    #pragma unroll
    for (int mi = 0; mi < 4; mi++) {
        #pragma unroll
        for (int half = 0; half < 2; half++) {
            int o = m0 + wm + mi*16 + (lane >> 2) + half*8;
            int s = o >> 9, rem = o & 511, h = rem >> 6, d = rem & 63;
            float bv = bias[o];
            float* dst = g_qkv + ((((size_t)s * B_ + b) * NH + h) * HD + d) * N_;
            #pragma unroll
            for (int ni = 0; ni < 4; ni++) {
                int n = n0 + wn + ni*8 + (lane & 3)*2;
                float2 v;
                v.x = acc[mi][ni][half*2 + 0] + bv;
                v.y = acc[mi][ni][half*2 + 1] + bv;
                *(float2*)&dst[n] = v;
            }
        }
    }
}

// ---------------------------------------------------------------------------
// 3) Flash attention (SIMT fp32) on [d][n] layout -> split-bf16 ext output
// ---------------------------------------------------------------------------
#define KVT 32
#define KSTR 36
__global__ __launch_bounds__(64) void attn_kernel() {
    int bh = blockIdx.x;            // b*8 + h
    int q0 = blockIdx.y * 64;
    int tid = threadIdx.x;

    const float* qb = g_qkv + ((size_t)(0 * B_ * NH + bh)) * HD * N_;
    const float* kb = g_qkv + ((size_t)(1 * B_ * NH + bh)) * HD * N_;
    const float* vb = g_qkv + ((size_t)(2 * B_ * NH + bh)) * HD * N_;

    __shared__ float Ks[HD * KSTR];
    __shared__ float Vs[HD * KSTR];

    float q[64], acc[64];
    const float scale = 0.125f;
    #pragma unroll
    for (int d = 0; d < 64; d++) {
        q[d] = qb[(size_t)d * N_ + q0 + tid] * scale;
        acc[d] = 0.f;
    }
    float m = -3.4e38f, l = 0.f;

    #pragma unroll 1
    for (int t = 0; t < N_ / KVT; t++) {
        __syncthreads();
        #pragma unroll
        for (int i = 0; i < 32; i++) {
            int idx = tid + i * 64;
            int d = idx >> 5, n = idx & 31;
            Ks[d * KSTR + n] = kb[(size_t)d * N_ + t * KVT + n];
            Vs[d * KSTR + n] = vb[(size_t)d * N_ + t * KVT + n];
        }
        __syncthreads();

        float s[KVT];
        #pragma unroll
        for (int j = 0; j < KVT; j++) s[j] = 0.f;

        #pragma unroll
        for (int d = 0; d < 64; d++) {
            float qd = q[d];
            const float4* kr = (const float4*)&Ks[d * KSTR];
            #pragma unroll
            for (int j4 = 0; j4 < 8; j4++) {
                float4 kk = kr[j4];
                s[j4*4+0] += qd * kk.x; s[j4*4+1] += qd * kk.y;
                s[j4*4+2] += qd * kk.z; s[j4*4+3] += qd * kk.w;
            }
        }

        float tmax = s[0];
        #pragma unroll
        for (int j = 1; j < KVT; j++) tmax = fmaxf(tmax, s[j]);
        float mn = fmaxf(m, tmax);
        float corr = __expf(m - mn);
        l *= corr;
        float ls = 0.f;
        #pragma unroll
        for (int j = 0; j < KVT; j++) {
            float p = __expf(s[j] - mn);
            ls += p;
            s[j] = p;
        }
        l += ls;
        m = mn;

        #pragma unroll
        for (int d = 0; d < 64; d++) {
            const float4* vr = (const float4*)&Vs[d * KSTR];
            float a = acc[d] * corr;
            #pragma unroll
            for (int j4 = 0; j4 < 8; j4++) {
                float4 vv = vr[j4];
                a += s[j4*4+0]*vv.x + s[j4*4+1]*vv.y + s[j4*4+2]*vv.z + s[j4*4+3]*vv.w;
            }
            acc[d] = a;
        }
    }

    float inv = 1.f / l;
    int b = bh >> 3, h = bh & 7;
    size_t eb = ((size_t)b * N_ + q0 + tid) * KEXT + h * HD;
    __nv_bfloat162* e0 = (__nv_bfloat162*)(g_obuf_ext + eb);
    __nv_bfloat162* e1 = (__nv_bfloat162*)(g_obuf_ext + eb + C_);
    __nv_bfloat162* e2 = (__nv_bfloat162*)(g_obuf_ext + eb + 2 * C_);
    #pragma unroll
    for (int i = 0; i < 32; i++) {
        float v0 = acc[2*i] * inv, v1 = acc[2*i+1] * inv;
        __nv_bfloat16 h0 = __float2bfloat16(v0), h1 = __float2bfloat16(v1);
        __nv_bfloat16 l0 = __float2bfloat16(v0 - __bfloat162float(h0));
        __nv_bfloat16 l1 = __float2bfloat16(v1 - __bfloat162float(h1));
        __nv_bfloat162 hp; hp.x = h0; hp.y = h1;
        __nv_bfloat162 lp; lp.x = l0; lp.y = l1;
        e0[i] = hp; e1[i] = hp; e2[i] = lp;
    }
}

// ---------------------------------------------------------------------------
// 4) Proj GEMM + bias + residual -> out[b][c][n] straight from fragments
// ---------------------------------------------------------------------------
__global__ __launch_bounds__(256) void proj_gemm(const float* __restrict__ bias,
                                                 const float* __restrict__ x,
                                                 float* __restrict__ out) {
    __shared__ GemmSm sm;
    int n0 = blockIdx.x * 128, m0 = blockIdx.y * 128, b = blockIdx.z;

    float acc[4][4][4];
    #pragma unroll
    for (int i = 0; i < 4; i++)
        #pragma unroll
        for (int j = 0; j < 4; j++)
            { acc[i][j][0]=0.f; acc[i][j][1]=0.f; acc[i][j][2]=0.f; acc[i][j][3]=0.f; }

    gemm_mainloop(&sm, acc,
        g_wproj_ext + (size_t)m0 * KEXT,
        g_obuf_ext + ((size_t)b * N_ + n0) * KEXT);

    int wid = threadIdx.x >> 5, lane = threadIdx.x & 31;
    int wm = (wid >> 2) * 64, wn = (wid & 3) * 32;

    #pragma unroll
    for (int mi = 0; mi < 4; mi++) {
        #pragma unroll
        for (int half = 0; half < 2; half++) {
            int ch = m0 + wm + mi*16 + (lane >> 2) + half*8;
            float bv = bias[ch];
            size_t rowbase = ((size_t)b * C_ + ch) * N_;
            #pragma unroll
            for (int ni = 0; ni < 4; ni++) {
                int n = n0 + wn + ni*8 + (lane & 3)*2;
                float2 xv = *(const float2*)&x[rowbase + n];
                float2 v;
                v.x = acc[mi][ni][half*2 + 0] + bv + xv.x;
                v.y = acc[mi][ni][half*2 + 1] + bv + xv.y;
                *(float2*)&out[rowbase + n] = v;
            }
        }
    }
}

// ---------------------------------------------------------------------------
extern "C" void kernel_launch(void* const* d_in, const int* in_sizes, int n_in,
                              void* d_out, int out_size) {
    const float* x      = (const float*)d_in[0];
    const float* norm_w = (const float*)d_in[1];
    const float* norm_b = (const float*)d_in[2];
    const float* qkv_w  = (const float*)d_in[3];
    const float* qkv_b  = (const float*)d_in[4];
    const float* proj_w = (const float*)d_in[5];
    const float* proj_b = (const float*)d_in[6];
    float* out = (float*)d_out;

    cudaFuncSetAttribute(gn_kernel, cudaFuncAttributeMaxDynamicSharedMemorySize, 65536);

    __nv_bfloat16 *wq, *wp;
    cudaGetSymbolAddress((void**)&wq, g_wqkv_ext);
    cudaGetSymbolAddress((void**)&wp, g_wproj_ext);

    convw_kernel<<<3 * C_, 128>>>(qkv_w, wq);
    convw_kernel<<<C_, 128>>>(proj_w, wp);
    gn_kernel<<<B_ * G_, 256, 65536>>>(x, norm_w, norm_b);
    qkv_gemm<<<dim3(N_ / 128, (3 * C_) / 128, B_), 256>>>(qkv_b);
    attn_kernel<<<dim3(B_ * NH, N_ / 64), 64>>>();
    proj_gemm<<<dim3(N_ / 128, C_ / 128, B_), 256>>>(proj_b, x, out);
}

// round 4
// speedup vs baseline: 3.8388x; 3.8388x over previous
#include <cuda_runtime.h>
#include <cuda_bf16.h>
#include <cstdint>

#define B_   16
#define C_   512
#define NH   8
#define HD   64
#define N_   1024
#define G_   32
#define CPG  16
#define EPSV 1e-5f
#define KEXT 1536          // 3 * C_ (split-bf16 extended K)
#define LOG2E 1.4426950408889634f

// ---------------- scratch (device globals; no allocation allowed) -----------
__device__ float         g_q[(size_t)B_ * NH * N_ * HD];              // [b][h][n][d] fp32
__device__ float         g_k[(size_t)B_ * NH * N_ * HD];              // [b][h][n][d] fp32
__device__ float         g_v[(size_t)B_ * NH * HD * N_];              // [b][h][d][n] fp32
__device__ __nv_bfloat16 g_hn_ext[(size_t)B_ * N_ * KEXT];            // [b][n][kext]: hi,hi,lo
__device__ __nv_bfloat16 g_obuf_ext[(size_t)B_ * N_ * KEXT];          // [b][n][kext]: hi,hi,lo
__device__ __nv_bfloat16 g_wqkv_ext[(size_t)(3*C_) * KEXT];           // [o][kext]: hi,lo,hi
__device__ __nv_bfloat16 g_wproj_ext[(size_t)C_ * KEXT];              // [o][kext]: hi,lo,hi

// ---------------- warp MMA helpers (baseline PTX, works on sm_103) ----------
__device__ __forceinline__ uint32_t smem_u32(const void* p) {
    uint32_t a;
    asm("{ .reg .u64 t; cvta.to.shared.u64 t, %1; cvt.u32.u64 %0, t; }" : "=r"(a) : "l"(p));
    return a;
}
__device__ __forceinline__ void ldsm_x4(uint32_t* r, uint32_t addr) {
    asm volatile("ldmatrix.sync.aligned.m8n8.x4.shared.b16 {%0,%1,%2,%3}, [%4];"
                 : "=r"(r[0]), "=r"(r[1]), "=r"(r[2]), "=r"(r[3]) : "r"(addr));
}
__device__ __forceinline__ void ldsm_x2(uint32_t* r, uint32_t addr) {
    asm volatile("ldmatrix.sync.aligned.m8n8.x2.shared.b16 {%0,%1}, [%2];"
                 : "=r"(r[0]), "=r"(r[1]) : "r"(addr));
}
__device__ __forceinline__ void mma_bf16(float* c, const uint32_t* a, const uint32_t* b) {
    asm volatile("mma.sync.aligned.m16n8k16.row.col.f32.bf16.bf16.f32 "
                 "{%0,%1,%2,%3}, {%4,%5,%6,%7}, {%8,%9}, {%0,%1,%2,%3};"
                 : "+f"(c[0]), "+f"(c[1]), "+f"(c[2]), "+f"(c[3])
                 : "r"(a[0]), "r"(a[1]), "r"(a[2]), "r"(a[3]), "r"(b[0]), "r"(b[1]));
}
__device__ __forceinline__ float ex2(float x) {
    float r; asm("ex2.approx.f32 %0, %1;" : "=f"(r) : "f"(x)); return r;
}
__device__ __forceinline__ uint32_t packbf2(float a, float b) {
    __nv_bfloat162 t; t.x = __float2bfloat16(a); t.y = __float2bfloat16(b);
    return *(uint32_t*)&t;
}

// ---------------------------------------------------------------------------
// 0) Weight split: w[o][c] fp32 -> ext[o][kext] bf16 (hi, lo, hi)
// ---------------------------------------------------------------------------
__global__ void convw_kernel(const float* __restrict__ w, __nv_bfloat16* __restrict__ ext) {
    int r = blockIdx.x;
    for (int c = threadIdx.x; c < C_; c += 128) {
        float v = w[(size_t)r * C_ + c];
        __nv_bfloat16 hi = __float2bfloat16(v);
        __nv_bfloat16 lo = __float2bfloat16(v - __bfloat162float(hi));
        size_t base = (size_t)r * KEXT;
        ext[base + c]          = hi;
        ext[base + C_ + c]     = lo;
        ext[base + 2 * C_ + c] = hi;
    }
}

// ---------------------------------------------------------------------------
// 1) GroupNorm + transpose + bf16 split: x[b][c][n] -> g_hn_ext[b][n][kext]
// ---------------------------------------------------------------------------
__global__ __launch_bounds__(256) void gn_kernel(const float* __restrict__ x,
                                                 const float* __restrict__ w,
                                                 const float* __restrict__ bb) {
    extern __shared__ float gsm[];                 // 16 ch * 1024 n fp32 = 64KB
    int bg = blockIdx.x;                           // b*32 + g
    int g = bg & (G_ - 1), b = bg >> 5;
    const float4* x4 = (const float4*)(x + (size_t)bg * CPG * N_);
    float4* s4 = (float4*)gsm;
    int tid = threadIdx.x;

    float s = 0.f, s2 = 0.f;
    #pragma unroll 4
    for (int i = tid; i < 4096; i += 256) {
        float4 v = x4[i];
        s4[i] = v;
        s  += v.x + v.y + v.z + v.w;
        s2 += v.x*v.x + v.y*v.y + v.z*v.z + v.w*v.w;
    }
    __shared__ float rs[256], rs2[256];
    rs[tid] = s; rs2[tid] = s2;
    __syncthreads();
    for (int off = 128; off > 0; off >>= 1) {
        if (tid < off) { rs[tid] += rs[tid+off]; rs2[tid] += rs2[tid+off]; }
        __syncthreads();
    }
    float mean = rs[0] * (1.f/16384.f);
    float var  = rs2[0] * (1.f/16384.f) - mean*mean;
    float rstd = rsqrtf(var + EPSV);

    float sc[CPG], sh[CPG];
    #pragma unroll
    for (int c16 = 0; c16 < CPG; c16++) {
        int c = g*CPG + c16;
        sc[c16] = rstd * w[c];
        sh[c16] = bb[c] - mean * sc[c16];
    }

    union Pack { __nv_bfloat16 h[CPG]; uint4 v[2]; };
    for (int n = tid; n < N_; n += 256) {
        Pack hiP, loP;
        #pragma unroll
        for (int c16 = 0; c16 < CPG; c16++) {
            float v = gsm[c16 * N_ + n] * sc[c16] + sh[c16];
            __nv_bfloat16 hv = __float2bfloat16(v);
            hiP.h[c16] = hv;
            loP.h[c16] = __float2bfloat16(v - __bfloat162float(hv));
        }
        __nv_bfloat16* dst = g_hn_ext + ((size_t)b * N_ + n) * KEXT + g * CPG;
        *(uint4*)(dst)          = hiP.v[0]; *(uint4*)(dst + 8)          = hiP.v[1];
        *(uint4*)(dst + C_)     = hiP.v[0]; *(uint4*)(dst + C_ + 8)     = hiP.v[1];
        *(uint4*)(dst + 2*C_)   = loP.v[0]; *(uint4*)(dst + 2*C_ + 8)   = loP.v[1];
    }
}

// ---------------------------------------------------------------------------
// HMMA GEMM mainloop: D[128m][128n] = sum_k A[m][k]*B[n][k], K=KEXT, BK=64.
// ---------------------------------------------------------------------------
#define SSTR 88
struct GemmSm {
    __nv_bfloat16 A[128 * SSTR];
    __nv_bfloat16 B[128 * SSTR];
};

__device__ __forceinline__ void gemm_mainloop(GemmSm* sm, float acc[4][4][4],
                                              const __nv_bfloat16* __restrict__ Abase,
                                              const __nv_bfloat16* __restrict__ Bbase) {
    int tid = threadIdx.x, wid = tid >> 5, lane = tid & 31;
    int wm = (wid >> 2) * 64;
    int wn = (wid & 3) * 32;

    uint32_t smA = smem_u32(sm->A), smB = smem_u32(sm->B);
    int aRow = wm + (lane & 15), aCol = (lane >> 4) * 8;
    int bRow = wn + (lane & 7),  bCol = ((lane >> 3) & 1) * 8;

    int ldRow = tid >> 3;
    int ldSeg = tid & 7;

    #pragma unroll 1
    for (int c = 0; c < KEXT / 64; c++) {
        int k0 = c * 64;
        __syncthreads();
        #pragma unroll
        for (int rr = 0; rr < 4; rr++) {
            int row = ldRow + rr * 32;
            *(uint4*)&sm->A[row * SSTR + ldSeg * 8] =
                *(const uint4*)(Abase + (size_t)row * KEXT + k0 + ldSeg * 8);
            *(uint4*)&sm->B[row * SSTR + ldSeg * 8] =
                *(const uint4*)(Bbase + (size_t)row * KEXT + k0 + ldSeg * 8);
        }
        __syncthreads();

        #pragma unroll
        for (int ks = 0; ks < 4; ks++) {
            uint32_t af[4][4], bf[4][2];
            #pragma unroll
            for (int mi = 0; mi < 4; mi++)
                ldsm_x4(af[mi], smA + ((aRow + mi*16) * SSTR + ks*16 + aCol) * 2);
            #pragma unroll
            for (int ni = 0; ni < 4; ni++)
                ldsm_x2(bf[ni], smB + ((bRow + ni*8) * SSTR + ks*16 + bCol) * 2);
            #pragma unroll
            for (int mi = 0; mi < 4; mi++)
                #pragma unroll
                for (int ni = 0; ni < 4; ni++)
                    mma_bf16(acc[mi][ni], af[mi], bf[ni]);
        }
    }
}

// ---------------------------------------------------------------------------
// 2) QKV GEMM -> Q,K: [b][h][n][d] fp32 ; V: [b][h][d][n] fp32
// ---------------------------------------------------------------------------
__global__ __launch_bounds__(256) void qkv_gemm(const float* __restrict__ bias) {
    __shared__ GemmSm sm;
    int n0 = blockIdx.x * 128, m0 = blockIdx.y * 128, b = blockIdx.z;

    float acc[4][4][4];
    #pragma unroll
    for (int i = 0; i < 4; i++)
        #pragma unroll
        for (int j = 0; j < 4; j++)
            { acc[i][j][0]=0.f; acc[i][j][1]=0.f; acc[i][j][2]=0.f; acc[i][j][3]=0.f; }

    gemm_mainloop(&sm, acc,
        g_wqkv_ext + (size_t)m0 * KEXT,
        g_hn_ext + ((size_t)b * N_ + n0) * KEXT);

    int wid = threadIdx.x >> 5, lane = threadIdx.x & 31;
    int wm = (wid >> 2) * 64, wn = (wid & 3) * 32;

    #pragma unroll
    for (int mi = 0; mi < 4; mi++) {
        #pragma unroll
        for (int half = 0; half < 2; half++) {
            int o = m0 + wm + mi*16 + (lane >> 2) + half*8;
            int s = o >> 9, rem = o & 511, h = rem >> 6, d = rem & 63;
            float bv = bias[o];
            if (s == 2) {   // V: [d][n] contiguous float2
                float* dst = g_v + (((size_t)b * NH + h) * HD + d) * N_;
                #pragma unroll
                for (int ni = 0; ni < 4; ni++) {
                    int n = n0 + wn + ni*8 + (lane & 3)*2;
                    float2 v;
                    v.x = acc[mi][ni][half*2 + 0] + bv;
                    v.y = acc[mi][ni][half*2 + 1] + bv;
                    *(float2*)&dst[n] = v;
                }
            } else {        // Q/K: [n][d], scattered 4B stores
                float* dst = (s == 0 ? g_q : g_k) + (((size_t)b * NH + h) * N_) * HD + d;
                #pragma unroll
                for (int ni = 0; ni < 4; ni++) {
                    int n = n0 + wn + ni*8 + (lane & 3)*2;
                    dst[(size_t)n * HD]       = acc[mi][ni][half*2 + 0] + bv;
                    dst[(size_t)(n+1) * HD]   = acc[mi][ni][half*2 + 1] + bv;
                }
            }
        }
    }
}

// ---------------------------------------------------------------------------
// 3) HMMA flash attention. CTA = 128 q rows of one (b,h); 8 warps x 16 rows.
//    n-chunks of 64. Split-bf16 on both S=QK^T (ext over d) and O=PV (ext n).
// ---------------------------------------------------------------------------
#define QSTR 136   // smem row stride (bf16): 64 hi + 64 lo + 8 pad; 272B
__device__ __forceinline__ void split4(float4 v, __nv_bfloat16* hi, __nv_bfloat16* lo) {
    __nv_bfloat16 hx = __float2bfloat16(v.x), hy = __float2bfloat16(v.y);
    __nv_bfloat16 hz = __float2bfloat16(v.z), hw = __float2bfloat16(v.w);
    __nv_bfloat162 h0; h0.x = hx; h0.y = hy;
    __nv_bfloat162 h1; h1.x = hz; h1.y = hw;
    *(__nv_bfloat162*)hi = h0; *(__nv_bfloat162*)(hi + 2) = h1;
    __nv_bfloat162 l0, l1;
    l0.x = __float2bfloat16(v.x - __bfloat162float(hx));
    l0.y = __float2bfloat16(v.y - __bfloat162float(hy));
    l1.x = __float2bfloat16(v.z - __bfloat162float(hz));
    l1.y = __float2bfloat16(v.w - __bfloat162float(hw));
    *(__nv_bfloat162*)lo = l0; *(__nv_bfloat162*)(lo + 2) = l1;
}

__global__ __launch_bounds__(256) void attn_kernel() {
    extern __shared__ __nv_bfloat16 sh[];
    __nv_bfloat16* Qh = sh;                    // [128][QSTR]
    __nv_bfloat16* Kx = sh + 128 * QSTR;       // [64][QSTR]
    __nv_bfloat16* Vx = Kx + 64 * QSTR;        // [64][QSTR]

    int q0 = blockIdx.x * 128;
    int bh = blockIdx.y;
    const float* qg = g_q + (size_t)bh * N_ * HD;
    const float* kg = g_k + (size_t)bh * N_ * HD;
    const float* vg = g_v + (size_t)bh * HD * N_;

    int tid = threadIdx.x, w = tid >> 5, lane = tid & 31;

    // ---- stage Q (scaled by 0.125, split hi/lo) ----
    #pragma unroll
    for (int i = 0; i < 8; i++) {
        int idx = tid + i * 256;
        int row = idx >> 4, d0 = (idx & 15) * 4;
        float4 v = *(const float4*)(qg + (size_t)(q0 + row) * HD + d0);
        v.x *= 0.125f; v.y *= 0.125f; v.z *= 0.125f; v.w *= 0.125f;
        split4(v, &Qh[row * QSTR + d0], &Qh[row * QSTR + 64 + d0]);
    }
    __syncthreads();

    // ---- load Q fragments (persistent) ----
    uint32_t qbase = smem_u32(Qh), kbase = smem_u32(Kx), vbase = smem_u32(Vx);
    int ar = w * 16 + (lane & 15);
    int ac = (lane >> 4) * 8;
    uint32_t qh[4][4], ql[4][4];
    #pragma unroll
    for (int ks = 0; ks < 4; ks++) {
        ldsm_x4(qh[ks], qbase + (ar * QSTR + ks * 16 + ac) * 2);
        ldsm_x4(ql[ks], qbase + (ar * QSTR + 64 + ks * 16 + ac) * 2);
    }

    float oacc[8][4];
    #pragma unroll
    for (int i = 0; i < 8; i++)
        { oacc[i][0]=0.f; oacc[i][1]=0.f; oacc[i][2]=0.f; oacc[i][3]=0.f; }
    float m0 = -1e30f, m1 = -1e30f, l0 = 0.f, l1 = 0.f;

    int br = lane & 7, bc8 = ((lane >> 3) & 1) * 8;

    #pragma unroll 1
    for (int ch = 0; ch < 16; ch++) {
        int n0 = ch * 64;
        __syncthreads();
        #pragma unroll
        for (int i = 0; i < 4; i++) {
            int idx = tid + i * 256;
            int row = idx >> 4, s4o = (idx & 15) * 4;
            float4 kv = *(const float4*)(kg + (size_t)(n0 + row) * HD + s4o);
            split4(kv, &Kx[row * QSTR + s4o], &Kx[row * QSTR + 64 + s4o]);
            float4 vv = *(const float4*)(vg + (size_t)row * N_ + n0 + s4o);
            split4(vv, &Vx[row * QSTR + s4o], &Vx[row * QSTR + 64 + s4o]);
        }
        __syncthreads();

        // ---- S = Q_ext . K_ext^T ----
        float sacc[8][4];
        #pragma unroll
        for (int i = 0; i < 8; i++)
            { sacc[i][0]=0.f; sacc[i][1]=0.f; sacc[i][2]=0.f; sacc[i][3]=0.f; }

        #pragma unroll
        for (int ks = 0; ks < 12; ks++) {
            const uint32_t* A = (ks < 4) ? qh[ks] : (ks < 8) ? qh[ks-4] : ql[ks-8];
            int col = ((ks < 4) ? ks*16 : (ks < 8) ? 64 + (ks-4)*16 : (ks-8)*16) + bc8;
            #pragma unroll
            for (int nf = 0; nf < 8; nf++) {
                uint32_t b2[2];
                ldsm_x2(b2, kbase + ((nf*8 + br) * QSTR + col) * 2);
                mma_bf16(sacc[nf], A, b2);
            }
        }

        // ---- online softmax (rows: r0 = lane>>2, r1 = r0+8 within warp tile) ----
        float mx0 = -1e30f, mx1 = -1e30f;
        #pragma unroll
        for (int nf = 0; nf < 8; nf++) {
            mx0 = fmaxf(mx0, fmaxf(sacc[nf][0], sacc[nf][1]));
            mx1 = fmaxf(mx1, fmaxf(sacc[nf][2], sacc[nf][3]));
        }
        mx0 = fmaxf(mx0, __shfl_xor_sync(0xffffffffu, mx0, 1));
        mx0 = fmaxf(mx0, __shfl_xor_sync(0xffffffffu, mx0, 2));
        mx1 = fmaxf(mx1, __shfl_xor_sync(0xffffffffu, mx1, 1));
        mx1 = fmaxf(mx1, __shfl_xor_sync(0xffffffffu, mx1, 2));
        float mn0 = fmaxf(m0, mx0), mn1 = fmaxf(m1, mx1);
        float f0 = ex2((m0 - mn0) * LOG2E), f1 = ex2((m1 - mn1) * LOG2E);

        float rs0 = 0.f, rs1 = 0.f;
        #pragma unroll
        for (int nf = 0; nf < 8; nf++) {
            sacc[nf][0] = ex2((sacc[nf][0] - mn0) * LOG2E);
            sacc[nf][1] = ex2((sacc[nf][1] - mn0) * LOG2E);
            sacc[nf][2] = ex2((sacc[nf][2] - mn1) * LOG2E);
            sacc[nf][3] = ex2((sacc[nf][3] - mn1) * LOG2E);
            rs0 += sacc[nf][0] + sacc[nf][1];
            rs1 += sacc[nf][2] + sacc[nf][3];
        }
        rs0 += __shfl_xor_sync(0xffffffffu, rs0, 1);
        rs0 += __shfl_xor_sync(0xffffffffu, rs0, 2);
        rs1 += __shfl_xor_sync(0xffffffffu, rs1, 1);
        rs1 += __shfl_xor_sync(0xffffffffu, rs1, 2);
        l0 = l0 * f0 + rs0; l1 = l1 * f1 + rs1;
        m0 = mn0; m1 = mn1;
        #pragma unroll
        for (int df = 0; df < 8; df++) {
            oacc[df][0] *= f0; oacc[df][1] *= f0;
            oacc[df][2] *= f1; oacc[df][3] *= f1;
        }

        // ---- P -> A fragments (hi & lo), pure register remap ----
        uint32_t phi[4][4], plo[4][4];
        #pragma unroll
        for (int ks = 0; ks < 4; ks++) {
            int j = 2 * ks;
            float p00 = sacc[j][0],   p01 = sacc[j][1];
            float p02 = sacc[j][2],   p03 = sacc[j][3];
            float p10 = sacc[j+1][0], p11 = sacc[j+1][1];
            float p12 = sacc[j+1][2], p13 = sacc[j+1][3];
            phi[ks][0] = packbf2(p00, p01);
            phi[ks][1] = packbf2(p02, p03);
            phi[ks][2] = packbf2(p10, p11);
            phi[ks][3] = packbf2(p12, p13);
            __nv_bfloat162* hp;
            hp = (__nv_bfloat162*)&phi[ks][0];
            plo[ks][0] = packbf2(p00 - __bfloat162float(hp->x), p01 - __bfloat162float(hp->y));
            hp = (__nv_bfloat162*)&phi[ks][1];
            plo[ks][1] = packbf2(p02 - __bfloat162float(hp->x), p03 - __bfloat162float(hp->y));
            hp = (__nv_bfloat162*)&phi[ks][2];
            plo[ks][2] = packbf2(p10 - __bfloat162float(hp->x), p11 - __bfloat162float(hp->y));
            hp = (__nv_bfloat162*)&phi[ks][3];
            plo[ks][3] = packbf2(p12 - __bfloat162float(hp->x), p13 - __bfloat162float(hp->y));
        }

        // ---- O += P_ext . V_ext ----
        #pragma unroll
        for (int ks = 0; ks < 12; ks++) {
            const uint32_t* A = (ks < 4) ? phi[ks] : (ks < 8) ? phi[ks-4] : plo[ks-8];
            int col = ((ks < 4) ? ks*16 : (ks < 8) ? 64 + (ks-4)*16 : (ks-8)*16) + bc8;
            #pragma unroll
            for (int df = 0; df < 8; df++) {
                uint32_t b2[2];
                ldsm_x2(b2, vbase + ((df*8 + br) * QSTR + col) * 2);
                mma_bf16(oacc[df], A, b2);
            }
        }
    }

    // ---- epilogue: normalize, split-bf16, write g_obuf_ext ----
    float inv0 = 1.f / l0, inv1 = 1.f / l1;
    int b = bh >> 3, h = bh & 7;
    int row0 = q0 + w * 16 + (lane >> 2);
    #pragma unroll
    for (int df = 0; df < 8; df++) {
        int chn = h * HD + df * 8 + (lane & 3) * 2;
        #pragma unroll
        for (int r = 0; r < 2; r++) {
            int row = row0 + r * 8;
            float v0 = oacc[df][r*2 + 0] * (r ? inv1 : inv0);
            float v1 = oacc[df][r*2 + 1] * (r ? inv1 : inv0);
            uint32_t hp = packbf2(v0, v1);
            __nv_bfloat162 hb = *(__nv_bfloat162*)&hp;
            uint32_t lp = packbf2(v0 - __bfloat162float(hb.x), v1 - __bfloat162float(hb.y));
            size_t eb = ((size_t)b * N_ + row) * KEXT + chn;
            *(uint32_t*)&g_obuf_ext[eb]          = hp;
            *(uint32_t*)&g_obuf_ext[eb + C_]     = hp;
            *(uint32_t*)&g_obuf_ext[eb + 2*C_]   = lp;
        }
    }
}

// ---------------------------------------------------------------------------
// 4) Proj GEMM + bias + residual -> out[b][c][n]
// ---------------------------------------------------------------------------
__global__ __launch_bounds__(256) void proj_gemm(const float* __restrict__ bias,
                                                 const float* __restrict__ x,
                                                 float* __restrict__ out) {
    __shared__ GemmSm sm;
    int n0 = blockIdx.x * 128, m0 = blockIdx.y * 128, b = blockIdx.z;

    float acc[4][4][4];
    #pragma unroll
    for (int i = 0; i < 4; i++)
        #pragma unroll
        for (int j = 0; j < 4; j++)
            { acc[i][j][0]=0.f; acc[i][j][1]=0.f; acc[i][j][2]=0.f; acc[i][j][3]=0.f; }

    gemm_mainloop(&sm, acc,
        g_wproj_ext + (size_t)m0 * KEXT,
        g_obuf_ext + ((size_t)b * N_ + n0) * KEXT);

    int wid = threadIdx.x >> 5, lane = threadIdx.x & 31;
    int wm = (wid >> 2) * 64, wn = (wid & 3) * 32;

    #pragma unroll
    for (int mi = 0; mi < 4; mi++) {
        #pragma unroll
        for (int half = 0; half < 2; half++) {
            int chn = m0 + wm + mi*16 + (lane >> 2) + half*8;
            float bv = bias[chn];
            size_t rowbase = ((size_t)b * C_ + chn) * N_;
            #pragma unroll
            for (int ni = 0; ni < 4; ni++) {
                int n = n0 + wn + ni*8 + (lane & 3)*2;
                float2 xv = *(const float2*)&x[rowbase + n];
                float2 v;
                v.x = acc[mi][ni][half*2 + 0] + bv + xv.x;
                v.y = acc[mi][ni][half*2 + 1] + bv + xv.y;
                *(float2*)&out[rowbase + n] = v;
            }
        }
    }
}

// ---------------------------------------------------------------------------
extern "C" void kernel_launch(void* const* d_in, const int* in_sizes, int n_in,
                              void* d_out, int out_size) {
    const float* x      = (const float*)d_in[0];
    const float* norm_w = (const float*)d_in[1];
    const float* norm_b = (const float*)d_in[2];
    const float* qkv_w  = (const float*)d_in[3];
    const float* qkv_b  = (const float*)d_in[4];
    const float* proj_w = (const float*)d_in[5];
    const float* proj_b = (const float*)d_in[6];
    float* out = (float*)d_out;

    cudaFuncSetAttribute(gn_kernel, cudaFuncAttributeMaxDynamicSharedMemorySize, 65536);
    int attn_smem = (128 + 64 + 64) * QSTR * 2;   // 69632 B
    cudaFuncSetAttribute(attn_kernel, cudaFuncAttributeMaxDynamicSharedMemorySize, attn_smem);

    __nv_bfloat16 *wq, *wp;
    cudaGetSymbolAddress((void**)&wq, g_wqkv_ext);
    cudaGetSymbolAddress((void**)&wp, g_wproj_ext);

    convw_kernel<<<3 * C_, 128>>>(qkv_w, wq);
    convw_kernel<<<C_, 128>>>(proj_w, wp);
    gn_kernel<<<B_ * G_, 256, 65536>>>(x, norm_w, norm_b);
    qkv_gemm<<<dim3(N_ / 128, (3 * C_) / 128, B_), 256>>>(qkv_b);
    attn_kernel<<<dim3(N_ / 128, B_ * NH), 256, attn_smem>>>();
    proj_gemm<<<dim3(N_ / 128, C_ / 128, B_), 256>>>(proj_b, x, out);
}

// round 5
// speedup vs baseline: 3.9383x; 1.0259x over previous
#include <cuda_runtime.h>
#include <cuda_bf16.h>
#include <cstdint>

#define B_   16
#define C_   512
#define NH   8
#define HD   64
#define N_   1024
#define G_   32
#define CPG  16
#define EPSV 1e-5f
#define KEXT 1536
#define LOG2E 1.4426950408889634f

// ---------------- scratch (device globals; no allocation allowed) -----------
__device__ float         g_q[(size_t)B_ * NH * N_ * HD];              // [b][h][n][d] fp32
__device__ float         g_k[(size_t)B_ * NH * N_ * HD];              // [b][h][n][d] fp32
__device__ __nv_bfloat16 g_vhi[(size_t)B_ * NH * HD * N_];            // [b][h][d][n] bf16 hi
__device__ __nv_bfloat16 g_vlo[(size_t)B_ * NH * HD * N_];            // [b][h][d][n] bf16 lo
__device__ __nv_bfloat16 g_hn_ext[(size_t)B_ * N_ * KEXT];
__device__ __nv_bfloat16 g_obuf_ext[(size_t)B_ * N_ * KEXT];
__device__ __nv_bfloat16 g_wqkv_ext[(size_t)(3*C_) * KEXT];
__device__ __nv_bfloat16 g_wproj_ext[(size_t)C_ * KEXT];

// ---------------- PTX helpers (baseline-safe for compute_103) ---------------
__device__ __forceinline__ uint32_t smem_u32(const void* p) {
    uint32_t a;
    asm("{ .reg .u64 t; cvta.to.shared.u64 t, %1; cvt.u32.u64 %0, t; }" : "=r"(a) : "l"(p));
    return a;
}
__device__ __forceinline__ void ldsm_x4(uint32_t* r, uint32_t addr) {
    asm volatile("ldmatrix.sync.aligned.m8n8.x4.shared.b16 {%0,%1,%2,%3}, [%4];"
                 : "=r"(r[0]), "=r"(r[1]), "=r"(r[2]), "=r"(r[3]) : "r"(addr));
}
__device__ __forceinline__ void ldsm_x2(uint32_t* r, uint32_t addr) {
    asm volatile("ldmatrix.sync.aligned.m8n8.x2.shared.b16 {%0,%1}, [%2];"
                 : "=r"(r[0]), "=r"(r[1]) : "r"(addr));
}
__device__ __forceinline__ void mma_bf16(float* c, const uint32_t* a, const uint32_t* b) {
    asm volatile("mma.sync.aligned.m16n8k16.row.col.f32.bf16.bf16.f32 "
                 "{%0,%1,%2,%3}, {%4,%5,%6,%7}, {%8,%9}, {%0,%1,%2,%3};"
                 : "+f"(c[0]), "+f"(c[1]), "+f"(c[2]), "+f"(c[3])
                 : "r"(a[0]), "r"(a[1]), "r"(a[2]), "r"(a[3]), "r"(b[0]), "r"(b[1]));
}
__device__ __forceinline__ float ex2(float x) {
    float r; asm("ex2.approx.f32 %0, %1;" : "=f"(r) : "f"(x)); return r;
}
__device__ __forceinline__ uint32_t packbf2(float a, float b) {
    __nv_bfloat162 t; t.x = __float2bfloat16(a); t.y = __float2bfloat16(b);
    return *(uint32_t*)&t;
}
#define CPA(dst, src) \
    asm volatile("cp.async.cg.shared.global [%0], [%1], 16;" :: "r"(dst), "l"(src))
#define CPCOMMIT() asm volatile("cp.async.commit_group;")
#define CPWAIT1()  asm volatile("cp.async.wait_group 1;")
#define CPWAIT0()  asm volatile("cp.async.wait_group 0;")

// ---------------------------------------------------------------------------
// 0) Weight split: w[o][c] fp32 -> ext[o][kext] bf16 (hi, lo, hi)
// ---------------------------------------------------------------------------
__global__ void convw_kernel(const float* __restrict__ w, __nv_bfloat16* __restrict__ ext) {
    int r = blockIdx.x;
    for (int c = threadIdx.x; c < C_; c += 128) {
        float v = w[(size_t)r * C_ + c];
        __nv_bfloat16 hi = __float2bfloat16(v);
        __nv_bfloat16 lo = __float2bfloat16(v - __bfloat162float(hi));
        size_t base = (size_t)r * KEXT;
        ext[base + c]          = hi;
        ext[base + C_ + c]     = lo;
        ext[base + 2 * C_ + c] = hi;
    }
}

// ---------------------------------------------------------------------------
// 1) GroupNorm + transpose + bf16 split: x[b][c][n] -> g_hn_ext[b][n][kext]
// ---------------------------------------------------------------------------
__global__ __launch_bounds__(256) void gn_kernel(const float* __restrict__ x,
                                                 const float* __restrict__ w,
                                                 const float* __restrict__ bb) {
    extern __shared__ float gsm[];
    int bg = blockIdx.x;
    int g = bg & (G_ - 1), b = bg >> 5;
    const float4* x4 = (const float4*)(x + (size_t)bg * CPG * N_);
    float4* s4 = (float4*)gsm;
    int tid = threadIdx.x;

    float s = 0.f, s2 = 0.f;
    #pragma unroll 4
    for (int i = tid; i < 4096; i += 256) {
        float4 v = x4[i];
        s4[i] = v;
        s  += v.x + v.y + v.z + v.w;
        s2 += v.x*v.x + v.y*v.y + v.z*v.z + v.w*v.w;
    }
    __shared__ float rs[256], rs2[256];
    rs[tid] = s; rs2[tid] = s2;
    __syncthreads();
    for (int off = 128; off > 0; off >>= 1) {
        if (tid < off) { rs[tid] += rs[tid+off]; rs2[tid] += rs2[tid+off]; }
        __syncthreads();
    }
    float mean = rs[0] * (1.f/16384.f);
    float var  = rs2[0] * (1.f/16384.f) - mean*mean;
    float rstd = rsqrtf(var + EPSV);

    float sc[CPG], sh[CPG];
    #pragma unroll
    for (int c16 = 0; c16 < CPG; c16++) {
        int c = g*CPG + c16;
        sc[c16] = rstd * w[c];
        sh[c16] = bb[c] - mean * sc[c16];
    }

    union Pack { __nv_bfloat16 h[CPG]; uint4 v[2]; };
    for (int n = tid; n < N_; n += 256) {
        Pack hiP, loP;
        #pragma unroll
        for (int c16 = 0; c16 < CPG; c16++) {
            float v = gsm[c16 * N_ + n] * sc[c16] + sh[c16];
            __nv_bfloat16 hv = __float2bfloat16(v);
            hiP.h[c16] = hv;
            loP.h[c16] = __float2bfloat16(v - __bfloat162float(hv));
        }
        __nv_bfloat16* dst = g_hn_ext + ((size_t)b * N_ + n) * KEXT + g * CPG;
        *(uint4*)(dst)          = hiP.v[0]; *(uint4*)(dst + 8)          = hiP.v[1];
        *(uint4*)(dst + C_)     = hiP.v[0]; *(uint4*)(dst + C_ + 8)     = hiP.v[1];
        *(uint4*)(dst + 2*C_)   = loP.v[0]; *(uint4*)(dst + 2*C_ + 8)   = loP.v[1];
    }
}

// ---------------------------------------------------------------------------
// HMMA GEMM mainloop, cp.async double-buffered. BK=64, K=KEXT (24 chunks).
// ---------------------------------------------------------------------------
#define SSTR 88
#define GEMM_SMEM (4 * 128 * SSTR * 2)   // 2 A bufs + 2 B bufs, bytes

__device__ __forceinline__ void gemm_mainloop(float acc[4][4][4],
                                              const __nv_bfloat16* __restrict__ Abase,
                                              const __nv_bfloat16* __restrict__ Bbase) {
    extern __shared__ __nv_bfloat16 dynsm[];
    __nv_bfloat16* As[2] = { dynsm,                dynsm + 128 * SSTR };
    __nv_bfloat16* Bs[2] = { dynsm + 2*128*SSTR,   dynsm + 3*128*SSTR };

    int tid = threadIdx.x, wid = tid >> 5, lane = tid & 31;
    int wm = (wid >> 2) * 64;
    int wn = (wid & 3) * 32;
    int aRow = wm + (lane & 15), aCol = (lane >> 4) * 8;
    int bRow = wn + (lane & 7),  bCol = ((lane >> 3) & 1) * 8;
    int ldRow = tid >> 3;
    int ldSeg = tid & 7;

    // issue chunk 0
    {
        int k0 = 0;
        #pragma unroll
        for (int rr = 0; rr < 4; rr++) {
            int row = ldRow + rr * 32;
            CPA(smem_u32(&As[0][row * SSTR + ldSeg * 8]),
                Abase + (size_t)row * KEXT + k0 + ldSeg * 8);
            CPA(smem_u32(&Bs[0][row * SSTR + ldSeg * 8]),
                Bbase + (size_t)row * KEXT + k0 + ldSeg * 8);
        }
        CPCOMMIT();
    }

    #pragma unroll 1
    for (int c = 0; c < KEXT / 64; c++) {
        if (c < KEXT / 64 - 1) {
            int k0 = (c + 1) * 64, s = (c + 1) & 1;
            #pragma unroll
            for (int rr = 0; rr < 4; rr++) {
                int row = ldRow + rr * 32;
                CPA(smem_u32(&As[s][row * SSTR + ldSeg * 8]),
                    Abase + (size_t)row * KEXT + k0 + ldSeg * 8);
                CPA(smem_u32(&Bs[s][row * SSTR + ldSeg * 8]),
                    Bbase + (size_t)row * KEXT + k0 + ldSeg * 8);
            }
            CPCOMMIT();
            CPWAIT1();
        } else {
            CPWAIT0();
        }
        __syncthreads();

        uint32_t smA = smem_u32(As[c & 1]), smB = smem_u32(Bs[c & 1]);
        #pragma unroll
        for (int ks = 0; ks < 4; ks++) {
            uint32_t af[4][4], bf[4][2];
            #pragma unroll
            for (int mi = 0; mi < 4; mi++)
                ldsm_x4(af[mi], smA + ((aRow + mi*16) * SSTR + ks*16 + aCol) * 2);
            #pragma unroll
            for (int ni = 0; ni < 4; ni++)
                ldsm_x2(bf[ni], smB + ((bRow + ni*8) * SSTR + ks*16 + bCol) * 2);
            #pragma unroll
            for (int mi = 0; mi < 4; mi++)
                #pragma unroll
                for (int ni = 0; ni < 4; ni++)
                    mma_bf16(acc[mi][ni], af[mi], bf[ni]);
        }
        __syncthreads();
    }
}

// ---------------------------------------------------------------------------
// 2) QKV GEMM -> Q,K fp32 [b][h][n][d]; V bf16 hi/lo planes [b][h][d][n]
// ---------------------------------------------------------------------------
__global__ __launch_bounds__(256) void qkv_gemm(const float* __restrict__ bias) {
    int n0 = blockIdx.x * 128, m0 = blockIdx.y * 128, b = blockIdx.z;

    float acc[4][4][4];
    #pragma unroll
    for (int i = 0; i < 4; i++)
        #pragma unroll
        for (int j = 0; j < 4; j++)
            { acc[i][j][0]=0.f; acc[i][j][1]=0.f; acc[i][j][2]=0.f; acc[i][j][3]=0.f; }

    gemm_mainloop(acc,
        g_wqkv_ext + (size_t)m0 * KEXT,
        g_hn_ext + ((size_t)b * N_ + n0) * KEXT);

    int wid = threadIdx.x >> 5, lane = threadIdx.x & 31;
    int wm = (wid >> 2) * 64, wn = (wid & 3) * 32;

    #pragma unroll
    for (int mi = 0; mi < 4; mi++) {
        #pragma unroll
        for (int half = 0; half < 2; half++) {
            int o = m0 + wm + mi*16 + (lane >> 2) + half*8;
            int s = o >> 9, rem = o & 511, h = rem >> 6, d = rem & 63;
            float bv = bias[o];
            if (s == 2) {   // V: bf16 hi/lo planes, packed 4B stores
                size_t vb = (((size_t)b * NH + h) * HD + d) * N_;
                #pragma unroll
                for (int ni = 0; ni < 4; ni++) {
                    int n = n0 + wn + ni*8 + (lane & 3)*2;
                    float v0 = acc[mi][ni][half*2 + 0] + bv;
                    float v1 = acc[mi][ni][half*2 + 1] + bv;
                    uint32_t hp = packbf2(v0, v1);
                    __nv_bfloat162 hb = *(__nv_bfloat162*)&hp;
                    uint32_t lp = packbf2(v0 - __bfloat162float(hb.x),
                                          v1 - __bfloat162float(hb.y));
                    *(uint32_t*)&g_vhi[vb + n] = hp;
                    *(uint32_t*)&g_vlo[vb + n] = lp;
                }
            } else {        // Q/K fp32 [n][d]
                float* dst = (s == 0 ? g_q : g_k) + (((size_t)b * NH + h) * N_) * HD + d;
                #pragma unroll
                for (int ni = 0; ni < 4; ni++) {
                    int n = n0 + wn + ni*8 + (lane & 3)*2;
                    dst[(size_t)n * HD]     = acc[mi][ni][half*2 + 0] + bv;
                    dst[(size_t)(n+1) * HD] = acc[mi][ni][half*2 + 1] + bv;
                }
            }
        }
    }
}

// ---------------------------------------------------------------------------
// 3) HMMA flash attention, cp.async pipelined K/V. CTA = 128 q rows of (b,h).
// ---------------------------------------------------------------------------
#define QSTR 136
// dynamic smem layout (bf16 units):
//   [0, 17408)         : Qh [128][QSTR]  -- aliased later by Fk[2] (fp32 64x64 each)
//   [17408, 26112)     : Kx [64][QSTR]
//   [26112, 43520)     : Vx[2] [64][QSTR] each
#define ATTN_SMEM (43520 * 2)

__device__ __forceinline__ void split4(float4 v, __nv_bfloat16* hi, __nv_bfloat16* lo) {
    __nv_bfloat16 hx = __float2bfloat16(v.x), hy = __float2bfloat16(v.y);
    __nv_bfloat16 hz = __float2bfloat16(v.z), hw = __float2bfloat16(v.w);
    __nv_bfloat162 h0; h0.x = hx; h0.y = hy;
    __nv_bfloat162 h1; h1.x = hz; h1.y = hw;
    *(__nv_bfloat162*)hi = h0; *(__nv_bfloat162*)(hi + 2) = h1;
    __nv_bfloat162 l0, l1;
    l0.x = __float2bfloat16(v.x - __bfloat162float(hx));
    l0.y = __float2bfloat16(v.y - __bfloat162float(hy));
    l1.x = __float2bfloat16(v.z - __bfloat162float(hz));
    l1.y = __float2bfloat16(v.w - __bfloat162float(hw));
    *(__nv_bfloat162*)lo = l0; *(__nv_bfloat162*)(lo + 2) = l1;
}

__global__ __launch_bounds__(256) void attn_kernel() {
    extern __shared__ __nv_bfloat16 dynsm[];
    __nv_bfloat16* Qh = dynsm;
    __nv_bfloat16* Kx = dynsm + 17408;
    __nv_bfloat16* Vx[2] = { dynsm + 26112, dynsm + 26112 + 8704 };
    float* Fk[2] = { (float*)dynsm, (float*)dynsm + 4096 };

    int q0 = blockIdx.x * 128;
    int bh = blockIdx.y;
    const float* qg = g_q + (size_t)bh * N_ * HD;
    const float* kg = g_k + (size_t)bh * N_ * HD;
    const __nv_bfloat16* vhi = g_vhi + (size_t)bh * HD * N_;
    const __nv_bfloat16* vlo = g_vlo + (size_t)bh * HD * N_;

    int tid = threadIdx.x, w = tid >> 5, lane = tid & 31;

    // ---- stage Q (scaled, split) into Qh ----
    #pragma unroll
    for (int i = 0; i < 8; i++) {
        int idx = tid + i * 256;
        int row = idx >> 4, d0 = (idx & 15) * 4;
        float4 v = *(const float4*)(qg + (size_t)(q0 + row) * HD + d0);
        v.x *= 0.125f; v.y *= 0.125f; v.z *= 0.125f; v.w *= 0.125f;
        split4(v, &Qh[row * QSTR + d0], &Qh[row * QSTR + 64 + d0]);
    }
    __syncthreads();

    // ---- Q fragments to registers ----
    uint32_t qbase = smem_u32(Qh), kbase = smem_u32(Kx);
    int ar = w * 16 + (lane & 15);
    int ac = (lane >> 4) * 8;
    uint32_t qh[4][4], ql[4][4];
    #pragma unroll
    for (int ks = 0; ks < 4; ks++) {
        ldsm_x4(qh[ks], qbase + (ar * QSTR + ks * 16 + ac) * 2);
        ldsm_x4(ql[ks], qbase + (ar * QSTR + 64 + ks * 16 + ac) * 2);
    }
    __syncthreads();    // Qh now dead; Fk may overwrite

    // ---- issue chunk 0 (K raw fp32 -> Fk[0], V ext bf16 -> Vx[0]) ----
    {
        #pragma unroll
        for (int i = 0; i < 4; i++) {
            int idx = tid + i * 256;
            int row = idx >> 4, seg = idx & 15;
            CPA(smem_u32(&Fk[0][row * 64 + seg * 4]),
                kg + (size_t)row * HD + seg * 4);
        }
        #pragma unroll
        for (int i = 0; i < 4; i++) {
            int idx = tid + i * 256;
            int d = idx >> 4, seg = idx & 15;
            const __nv_bfloat16* src = (seg < 8 ? vhi : vlo) + (size_t)d * N_ + (seg & 7) * 8;
            CPA(smem_u32(&Vx[0][d * QSTR + seg * 8]), src);
        }
        CPCOMMIT();
    }

    float oacc[8][4];
    #pragma unroll
    for (int i = 0; i < 8; i++)
        { oacc[i][0]=0.f; oacc[i][1]=0.f; oacc[i][2]=0.f; oacc[i][3]=0.f; }
    float m0 = -1e30f, m1 = -1e30f, l0 = 0.f, l1 = 0.f;

    int br = lane & 7, bc8 = ((lane >> 3) & 1) * 8;

    #pragma unroll 1
    for (int ch = 0; ch < 16; ch++) {
        // issue chunk ch+1
        if (ch < 15) {
            int n1 = (ch + 1) * 64, s = (ch + 1) & 1;
            #pragma unroll
            for (int i = 0; i < 4; i++) {
                int idx = tid + i * 256;
                int row = idx >> 4, seg = idx & 15;
                CPA(smem_u32(&Fk[s][row * 64 + seg * 4]),
                    kg + (size_t)(n1 + row) * HD + seg * 4);
            }
            #pragma unroll
            for (int i = 0; i < 4; i++) {
                int idx = tid + i * 256;
                int d = idx >> 4, seg = idx & 15;
                const __nv_bfloat16* src = (seg < 8 ? vhi : vlo) + (size_t)d * N_ + n1 + (seg & 7) * 8;
                CPA(smem_u32(&Vx[s][d * QSTR + seg * 8]), src);
            }
            CPCOMMIT();
            CPWAIT1();
        } else {
            CPWAIT0();
        }
        __syncthreads();

        // ---- split K chunk fp32 -> Kx ext ----
        {
            const float* fk = Fk[ch & 1];
            #pragma unroll
            for (int i = 0; i < 4; i++) {
                int idx = tid + i * 256;
                int row = idx >> 4, d0 = (idx & 15) * 4;
                float4 kv = *(const float4*)&fk[row * 64 + d0];
                split4(kv, &Kx[row * QSTR + d0], &Kx[row * QSTR + 64 + d0]);
            }
        }
        __syncthreads();

        uint32_t vbase = smem_u32(Vx[ch & 1]);

        // ---- S = Q_ext . K_ext^T ----
        float sacc[8][4];
        #pragma unroll
        for (int i = 0; i < 8; i++)
            { sacc[i][0]=0.f; sacc[i][1]=0.f; sacc[i][2]=0.f; sacc[i][3]=0.f; }

        #pragma unroll
        for (int ks = 0; ks < 12; ks++) {
            const uint32_t* A = (ks < 4) ? qh[ks] : (ks < 8) ? qh[ks-4] : ql[ks-8];
            int col = ((ks < 4) ? ks*16 : (ks < 8) ? 64 + (ks-4)*16 : (ks-8)*16) + bc8;
            #pragma unroll
            for (int nf = 0; nf < 8; nf++) {
                uint32_t b2[2];
                ldsm_x2(b2, kbase + ((nf*8 + br) * QSTR + col) * 2);
                mma_bf16(sacc[nf], A, b2);
            }
        }

        // ---- online softmax ----
        float mx0 = -1e30f, mx1 = -1e30f;
        #pragma unroll
        for (int nf = 0; nf < 8; nf++) {
            mx0 = fmaxf(mx0, fmaxf(sacc[nf][0], sacc[nf][1]));
            mx1 = fmaxf(mx1, fmaxf(sacc[nf][2], sacc[nf][3]));
        }
        mx0 = fmaxf(mx0, __shfl_xor_sync(0xffffffffu, mx0, 1));
        mx0 = fmaxf(mx0, __shfl_xor_sync(0xffffffffu, mx0, 2));
        mx1 = fmaxf(mx1, __shfl_xor_sync(0xffffffffu, mx1, 1));
        mx1 = fmaxf(mx1, __shfl_xor_sync(0xffffffffu, mx1, 2));
        float mn0 = fmaxf(m0, mx0), mn1 = fmaxf(m1, mx1);
        float f0 = ex2((m0 - mn0) * LOG2E), f1 = ex2((m1 - mn1) * LOG2E);

        float rs0 = 0.f, rs1 = 0.f;
        #pragma unroll
        for (int nf = 0; nf < 8; nf++) {
            sacc[nf][0] = ex2((sacc[nf][0] - mn0) * LOG2E);
            sacc[nf][1] = ex2((sacc[nf][1] - mn0) * LOG2E);
            sacc[nf][2] = ex2((sacc[nf][2] - mn1) * LOG2E);
            sacc[nf][3] = ex2((sacc[nf][3] - mn1) * LOG2E);
            rs0 += sacc[nf][0] + sacc[nf][1];
            rs1 += sacc[nf][2] + sacc[nf][3];
        }
        rs0 += __shfl_xor_sync(0xffffffffu, rs0, 1);
        rs0 += __shfl_xor_sync(0xffffffffu, rs0, 2);
        rs1 += __shfl_xor_sync(0xffffffffu, rs1, 1);
        rs1 += __shfl_xor_sync(0xffffffffu, rs1, 2);
        l0 = l0 * f0 + rs0; l1 = l1 * f1 + rs1;
        m0 = mn0; m1 = mn1;
        #pragma unroll
        for (int df = 0; df < 8; df++) {
            oacc[df][0] *= f0; oacc[df][1] *= f0;
            oacc[df][2] *= f1; oacc[df][3] *= f1;
        }

        // ---- P -> A fragments (hi & lo) ----
        uint32_t phi[4][4], plo[4][4];
        #pragma unroll
        for (int ks = 0; ks < 4; ks++) {
            int j = 2 * ks;
            float p00 = sacc[j][0],   p01 = sacc[j][1];
            float p02 = sacc[j][2],   p03 = sacc[j][3];
            float p10 = sacc[j+1][0], p11 = sacc[j+1][1];
            float p12 = sacc[j+1][2], p13 = sacc[j+1][3];
            phi[ks][0] = packbf2(p00, p01);
            phi[ks][1] = packbf2(p02, p03);
            phi[ks][2] = packbf2(p10, p11);
            phi[ks][3] = packbf2(p12, p13);
            __nv_bfloat162* hp;
            hp = (__nv_bfloat162*)&phi[ks][0];
            plo[ks][0] = packbf2(p00 - __bfloat162float(hp->x), p01 - __bfloat162float(hp->y));
            hp = (__nv_bfloat162*)&phi[ks][1];
            plo[ks][1] = packbf2(p02 - __bfloat162float(hp->x), p03 - __bfloat162float(hp->y));
            hp = (__nv_bfloat162*)&phi[ks][2];
            plo[ks][2] = packbf2(p10 - __bfloat162float(hp->x), p11 - __bfloat162float(hp->y));
            hp = (__nv_bfloat162*)&phi[ks][3];
            plo[ks][3] = packbf2(p12 - __bfloat162float(hp->x), p13 - __bfloat162float(hp->y));
        }

        // ---- O += P_ext . V_ext ----
        #pragma unroll
        for (int ks = 0; ks < 12; ks++) {
            const uint32_t* A = (ks < 4) ? phi[ks] : (ks < 8) ? phi[ks-4] : plo[ks-8];
            int col = ((ks < 4) ? ks*16 : (ks < 8) ? 64 + (ks-4)*16 : (ks-8)*16) + bc8;
            #pragma unroll
            for (int df = 0; df < 8; df++) {
                uint32_t b2[2];
                ldsm_x2(b2, vbase + ((df*8 + br) * QSTR + col) * 2);
                mma_bf16(oacc[df], A, b2);
            }
        }
        __syncthreads();
    }

    // ---- epilogue: normalize, split-bf16, write g_obuf_ext ----
    float inv0 = 1.f / l0, inv1 = 1.f / l1;
    int b = bh >> 3, h = bh & 7;
    int row0 = q0 + w * 16 + (lane >> 2);
    #pragma unroll
    for (int df = 0; df < 8; df++) {
        int chn = h * HD + df * 8 + (lane & 3) * 2;
        #pragma unroll
        for (int r = 0; r < 2; r++) {
            int row = row0 + r * 8;
            float v0 = oacc[df][r*2 + 0] * (r ? inv1 : inv0);
            float v1 = oacc[df][r*2 + 1] * (r ? inv1 : inv0);
            uint32_t hp = packbf2(v0, v1);
            __nv_bfloat162 hb = *(__nv_bfloat162*)&hp;
            uint32_t lp = packbf2(v0 - __bfloat162float(hb.x), v1 - __bfloat162float(hb.y));
            size_t eb = ((size_t)b * N_ + row) * KEXT + chn;
            *(uint32_t*)&g_obuf_ext[eb]          = hp;
            *(uint32_t*)&g_obuf_ext[eb + C_]     = hp;
            *(uint32_t*)&g_obuf_ext[eb + 2*C_]   = lp;
        }
    }
}

// ---------------------------------------------------------------------------
// 4) Proj GEMM + bias + residual -> out[b][c][n]
// ---------------------------------------------------------------------------
__global__ __launch_bounds__(256) void proj_gemm(const float* __restrict__ bias,
                                                 const float* __restrict__ x,
                                                 float* __restrict__ out) {
    int n0 = blockIdx.x * 128, m0 = blockIdx.y * 128, b = blockIdx.z;

    float acc[4][4][4];
    #pragma unroll
    for (int i = 0; i < 4; i++)
        #pragma unroll
        for (int j = 0; j < 4; j++)
            { acc[i][j][0]=0.f; acc[i][j][1]=0.f; acc[i][j][2]=0.f; acc[i][j][3]=0.f; }

    gemm_mainloop(acc,
        g_wproj_ext + (size_t)m0 * KEXT,
        g_obuf_ext + ((size_t)b * N_ + n0) * KEXT);

    int wid = threadIdx.x >> 5, lane = threadIdx.x & 31;
    int wm = (wid >> 2) * 64, wn = (wid & 3) * 32;

    #pragma unroll
    for (int mi = 0; mi < 4; mi++) {
        #pragma unroll
        for (int half = 0; half < 2; half++) {
            int chn = m0 + wm + mi*16 + (lane >> 2) + half*8;
            float bv = bias[chn];
            size_t rowbase = ((size_t)b * C_ + chn) * N_;
            #pragma unroll
            for (int ni = 0; ni < 4; ni++) {
                int n = n0 + wn + ni*8 + (lane & 3)*2;
                float2 xv = *(const float2*)&x[rowbase + n];
                float2 v;
                v.x = acc[mi][ni][half*2 + 0] + bv + xv.x;
                v.y = acc[mi][ni][half*2 + 1] + bv + xv.y;
                *(float2*)&out[rowbase + n] = v;
            }
        }
    }
}

// ---------------------------------------------------------------------------
extern "C" void kernel_launch(void* const* d_in, const int* in_sizes, int n_in,
                              void* d_out, int out_size) {
    const float* x      = (const float*)d_in[0];
    const float* norm_w = (const float*)d_in[1];
    const float* norm_b = (const float*)d_in[2];
    const float* qkv_w  = (const float*)d_in[3];
    const float* qkv_b  = (const float*)d_in[4];
    const float* proj_w = (const float*)d_in[5];
    const float* proj_b = (const float*)d_in[6];
    float* out = (float*)d_out;

    cudaFuncSetAttribute(gn_kernel, cudaFuncAttributeMaxDynamicSharedMemorySize, 65536);
    cudaFuncSetAttribute(qkv_gemm, cudaFuncAttributeMaxDynamicSharedMemorySize, GEMM_SMEM);
    cudaFuncSetAttribute(proj_gemm, cudaFuncAttributeMaxDynamicSharedMemorySize, GEMM_SMEM);
    cudaFuncSetAttribute(attn_kernel, cudaFuncAttributeMaxDynamicSharedMemorySize, ATTN_SMEM);

    __nv_bfloat16 *wq, *wp;
    cudaGetSymbolAddress((void**)&wq, g_wqkv_ext);
    cudaGetSymbolAddress((void**)&wp, g_wproj_ext);

    convw_kernel<<<3 * C_, 128>>>(qkv_w, wq);
    convw_kernel<<<C_, 128>>>(proj_w, wp);
    gn_kernel<<<B_ * G_, 256, 65536>>>(x, norm_w, norm_b);
    qkv_gemm<<<dim3(N_ / 128, (3 * C_) / 128, B_), 256, GEMM_SMEM>>>(qkv_b);
    attn_kernel<<<dim3(N_ / 128, B_ * NH), 256, ATTN_SMEM>>>();
    proj_gemm<<<dim3(N_ / 128, C_ / 128, B_), 256, GEMM_SMEM>>>(proj_b, x, out);
}

// round 6
// speedup vs baseline: 4.0286x; 1.0229x over previous
#include <cuda_runtime.h>
#include <cuda_bf16.h>
#include <cstdint>

#define B_   16
#define C_   512
#define NH   8
#define HD   64
#define N_   1024
#define G_   32
#define CPG  16
#define EPSV 1e-5f
#define KEXT 1536
#define LOG2E 1.4426950408889634f

// ---------------- scratch (device globals; no allocation allowed) -----------
__device__ __nv_bfloat16 g_qext[(size_t)B_ * NH * N_ * 128];   // [b][h][n][hi64|lo64], pre-scaled
__device__ __nv_bfloat16 g_kext[(size_t)B_ * NH * N_ * 128];   // [b][h][n][hi64|lo64]
__device__ __nv_bfloat16 g_vhi[(size_t)B_ * NH * HD * N_];     // [b][h][d][n]
__device__ __nv_bfloat16 g_vlo[(size_t)B_ * NH * HD * N_];
__device__ __nv_bfloat16 g_hn_ext[(size_t)B_ * N_ * KEXT];
__device__ __nv_bfloat16 g_obuf_ext[(size_t)B_ * N_ * KEXT];
__device__ __nv_bfloat16 g_wqkv_ext[(size_t)(3*C_) * KEXT];
__device__ __nv_bfloat16 g_wproj_ext[(size_t)C_ * KEXT];

// ---------------- PTX helpers (baseline-safe for compute_103) ---------------
__device__ __forceinline__ uint32_t smem_u32(const void* p) {
    uint32_t a;
    asm("{ .reg .u64 t; cvta.to.shared.u64 t, %1; cvt.u32.u64 %0, t; }" : "=r"(a) : "l"(p));
    return a;
}
__device__ __forceinline__ void ldsm_x4(uint32_t* r, uint32_t addr) {
    asm volatile("ldmatrix.sync.aligned.m8n8.x4.shared.b16 {%0,%1,%2,%3}, [%4];"
                 : "=r"(r[0]), "=r"(r[1]), "=r"(r[2]), "=r"(r[3]) : "r"(addr));
}
__device__ __forceinline__ void mma_bf16(float* c, const uint32_t* a, const uint32_t* b) {
    asm volatile("mma.sync.aligned.m16n8k16.row.col.f32.bf16.bf16.f32 "
                 "{%0,%1,%2,%3}, {%4,%5,%6,%7}, {%8,%9}, {%0,%1,%2,%3};"
                 : "+f"(c[0]), "+f"(c[1]), "+f"(c[2]), "+f"(c[3])
                 : "r"(a[0]), "r"(a[1]), "r"(a[2]), "r"(a[3]), "r"(b[0]), "r"(b[1]));
}
__device__ __forceinline__ float ex2(float x) {
    float r; asm("ex2.approx.f32 %0, %1;" : "=f"(r) : "f"(x)); return r;
}
__device__ __forceinline__ uint32_t packbf2(float a, float b) {
    __nv_bfloat162 t; t.x = __float2bfloat16(a); t.y = __float2bfloat16(b);
    return *(uint32_t*)&t;
}
#define CPA(dst, src) \
    asm volatile("cp.async.cg.shared.global [%0], [%1], 16;" :: "r"(dst), "l"(src))
#define CPCOMMIT() asm volatile("cp.async.commit_group;")
#define CPWAIT(n)  asm volatile("cp.async.wait_group %0;" :: "n"(n))

// ---------------------------------------------------------------------------
// 0) Weight split
// ---------------------------------------------------------------------------
__global__ void convw_kernel(const float* __restrict__ w, __nv_bfloat16* __restrict__ ext) {
    int r = blockIdx.x;
    for (int c = threadIdx.x; c < C_; c += 128) {
        float v = w[(size_t)r * C_ + c];
        __nv_bfloat16 hi = __float2bfloat16(v);
        __nv_bfloat16 lo = __float2bfloat16(v - __bfloat162float(hi));
        size_t base = (size_t)r * KEXT;
        ext[base + c]          = hi;
        ext[base + C_ + c]     = lo;
        ext[base + 2 * C_ + c] = hi;
    }
}

// ---------------------------------------------------------------------------
// 1) GroupNorm + transpose + bf16 split
// ---------------------------------------------------------------------------
__global__ __launch_bounds__(256) void gn_kernel(const float* __restrict__ x,
                                                 const float* __restrict__ w,
                                                 const float* __restrict__ bb) {
    extern __shared__ float gsm[];
    int bg = blockIdx.x;
    int g = bg & (G_ - 1), b = bg >> 5;
    const float4* x4 = (const float4*)(x + (size_t)bg * CPG * N_);
    float4* s4 = (float4*)gsm;
    int tid = threadIdx.x;

    float s = 0.f, s2 = 0.f;
    #pragma unroll 4
    for (int i = tid; i < 4096; i += 256) {
        float4 v = x4[i];
        s4[i] = v;
        s  += v.x + v.y + v.z + v.w;
        s2 += v.x*v.x + v.y*v.y + v.z*v.z + v.w*v.w;
    }
    __shared__ float rs[256], rs2[256];
    rs[tid] = s; rs2[tid] = s2;
    __syncthreads();
    for (int off = 128; off > 0; off >>= 1) {
        if (tid < off) { rs[tid] += rs[tid+off]; rs2[tid] += rs2[tid+off]; }
        __syncthreads();
    }
    float mean = rs[0] * (1.f/16384.f);
    float var  = rs2[0] * (1.f/16384.f) - mean*mean;
    float rstd = rsqrtf(var + EPSV);

    float sc[CPG], sh[CPG];
    #pragma unroll
    for (int c16 = 0; c16 < CPG; c16++) {
        int c = g*CPG + c16;
        sc[c16] = rstd * w[c];
        sh[c16] = bb[c] - mean * sc[c16];
    }

    union Pack { __nv_bfloat16 h[CPG]; uint4 v[2]; };
    for (int n = tid; n < N_; n += 256) {
        Pack hiP, loP;
        #pragma unroll
        for (int c16 = 0; c16 < CPG; c16++) {
            float v = gsm[c16 * N_ + n] * sc[c16] + sh[c16];
            __nv_bfloat16 hv = __float2bfloat16(v);
            hiP.h[c16] = hv;
            loP.h[c16] = __float2bfloat16(v - __bfloat162float(hv));
        }
        __nv_bfloat16* dst = g_hn_ext + ((size_t)b * N_ + n) * KEXT + g * CPG;
        *(uint4*)(dst)          = hiP.v[0]; *(uint4*)(dst + 8)          = hiP.v[1];
        *(uint4*)(dst + C_)     = hiP.v[0]; *(uint4*)(dst + C_ + 8)     = hiP.v[1];
        *(uint4*)(dst + 2*C_)   = loP.v[0]; *(uint4*)(dst + 2*C_ + 8)   = loP.v[1];
    }
}

// ---------------------------------------------------------------------------
// HMMA GEMM mainloop: 3-stage cp.async ring, one sync per chunk. BK=64.
// ---------------------------------------------------------------------------
#define SSTR 72
#define STAGE_U (2 * 128 * SSTR)           // bf16 units per stage (A + B)
#define GEMM_SMEM (3 * STAGE_U * 2)        // bytes = 110592

__device__ __forceinline__ void gemm_issue(__nv_bfloat16* As, __nv_bfloat16* Bs,
                                           const __nv_bfloat16* Abase,
                                           const __nv_bfloat16* Bbase,
                                           int k0, int ldRow, int ldSeg) {
    #pragma unroll
    for (int rr = 0; rr < 4; rr++) {
        int row = ldRow + rr * 32;
        CPA(smem_u32(&As[row * SSTR + ldSeg * 8]),
            Abase + (size_t)row * KEXT + k0 + ldSeg * 8);
        CPA(smem_u32(&Bs[row * SSTR + ldSeg * 8]),
            Bbase + (size_t)row * KEXT + k0 + ldSeg * 8);
    }
    CPCOMMIT();
}

__device__ __forceinline__ void gemm_mainloop(float acc[4][4][4],
                                              const __nv_bfloat16* __restrict__ Abase,
                                              const __nv_bfloat16* __restrict__ Bbase) {
    extern __shared__ __nv_bfloat16 dynsm[];
    __nv_bfloat16* As[3] = { dynsm, dynsm + STAGE_U, dynsm + 2*STAGE_U };
    __nv_bfloat16* Bs[3] = { dynsm + 128*SSTR, dynsm + STAGE_U + 128*SSTR,
                             dynsm + 2*STAGE_U + 128*SSTR };

    int tid = threadIdx.x, wid = tid >> 5, lane = tid & 31;
    int wm = (wid >> 2) * 64;
    int wn = (wid & 3) * 32;
    int aRow = wm + (lane & 15), aCol = (lane >> 4) * 8;
    int bRowP = (lane & 7) + ((lane >> 4) * 8);       // x4 B pair row component
    int bColP = ((lane >> 3) & 1) * 8;
    int ldRow = tid >> 3;
    int ldSeg = tid & 7;

    gemm_issue(As[0], Bs[0], Abase, Bbase, 0, ldRow, ldSeg);
    gemm_issue(As[1], Bs[1], Abase, Bbase, 64, ldRow, ldSeg);

    #pragma unroll 1
    for (int c = 0; c < KEXT / 64; c++) {
        if (c < KEXT / 64 - 2) CPWAIT(1); else CPWAIT(0);
        __syncthreads();
        if (c + 2 < KEXT / 64)
            gemm_issue(As[(c+2)%3], Bs[(c+2)%3], Abase, Bbase, (c+2)*64, ldRow, ldSeg);

        uint32_t smA = smem_u32(As[c%3]), smB = smem_u32(Bs[c%3]);
        #pragma unroll
        for (int ks = 0; ks < 4; ks++) {
            uint32_t af[4][4], bf[2][4];
            #pragma unroll
            for (int mi = 0; mi < 4; mi++)
                ldsm_x4(af[mi], smA + ((aRow + mi*16) * SSTR + ks*16 + aCol) * 2);
            #pragma unroll
            for (int n2 = 0; n2 < 2; n2++)
                ldsm_x4(bf[n2], smB + ((wn + n2*16 + bRowP) * SSTR + ks*16 + bColP) * 2);
            #pragma unroll
            for (int mi = 0; mi < 4; mi++)
                #pragma unroll
                for (int n2 = 0; n2 < 2; n2++) {
                    mma_bf16(acc[mi][2*n2],   af[mi], &bf[n2][0]);
                    mma_bf16(acc[mi][2*n2+1], af[mi], &bf[n2][2]);
                }
        }
    }
}

// ---------------------------------------------------------------------------
// 2) QKV GEMM -> Q,K ext bf16 [b][h][n][128]; V hi/lo planes [b][h][d][n]
// ---------------------------------------------------------------------------
__global__ __launch_bounds__(256) void qkv_gemm(const float* __restrict__ bias) {
    int n0 = blockIdx.x * 128, m0 = blockIdx.y * 128, b = blockIdx.z;

    float acc[4][4][4];
    #pragma unroll
    for (int i = 0; i < 4; i++)
        #pragma unroll
        for (int j = 0; j < 4; j++)
            { acc[i][j][0]=0.f; acc[i][j][1]=0.f; acc[i][j][2]=0.f; acc[i][j][3]=0.f; }

    gemm_mainloop(acc,
        g_wqkv_ext + (size_t)m0 * KEXT,
        g_hn_ext + ((size_t)b * N_ + n0) * KEXT);

    int wid = threadIdx.x >> 5, lane = threadIdx.x & 31;
    int wm = (wid >> 2) * 64, wn = (wid & 3) * 32;

    #pragma unroll
    for (int mi = 0; mi < 4; mi++) {
        #pragma unroll
        for (int half = 0; half < 2; half++) {
            int o = m0 + wm + mi*16 + (lane >> 2) + half*8;
            int s = o >> 9, rem = o & 511, h = rem >> 6, d = rem & 63;
            float bv = bias[o];
            if (s == 2) {   // V: bf16 hi/lo planes
                size_t vb = (((size_t)b * NH + h) * HD + d) * N_;
                #pragma unroll
                for (int ni = 0; ni < 4; ni++) {
                    int n = n0 + wn + ni*8 + (lane & 3)*2;
                    float v0 = acc[mi][ni][half*2 + 0] + bv;
                    float v1 = acc[mi][ni][half*2 + 1] + bv;
                    uint32_t hp = packbf2(v0, v1);
                    __nv_bfloat162 hb = *(__nv_bfloat162*)&hp;
                    uint32_t lp = packbf2(v0 - __bfloat162float(hb.x),
                                          v1 - __bfloat162float(hb.y));
                    *(uint32_t*)&g_vhi[vb + n] = hp;
                    *(uint32_t*)&g_vlo[vb + n] = lp;
                }
            } else {        // Q/K: ext bf16 [n][hi64|lo64]; Q pre-scaled
                float scl = (s == 0) ? 0.125f : 1.0f;
                __nv_bfloat16* dst = (s == 0 ? g_qext : g_kext)
                                     + (((size_t)b * NH + h) * N_) * 128 + d;
                #pragma unroll
                for (int ni = 0; ni < 4; ni++) {
                    int n = n0 + wn + ni*8 + (lane & 3)*2;
                    float v0 = (acc[mi][ni][half*2 + 0] + bv) * scl;
                    float v1 = (acc[mi][ni][half*2 + 1] + bv) * scl;
                    __nv_bfloat16 h0 = __float2bfloat16(v0);
                    __nv_bfloat16 h1 = __float2bfloat16(v1);
                    dst[(size_t)n * 128]            = h0;
                    dst[(size_t)n * 128 + 64]       = __float2bfloat16(v0 - __bfloat162float(h0));
                    dst[(size_t)(n+1) * 128]        = h1;
                    dst[(size_t)(n+1) * 128 + 64]   = __float2bfloat16(v1 - __bfloat162float(h1));
                }
            }
        }
    }
}

// ---------------------------------------------------------------------------
// 3) HMMA flash attention: pre-split Q/K/V, 3-buffer cp.async ring.
// ---------------------------------------------------------------------------
#define QSTR 136
// smem (bf16 units): Qh [0,17408) — aliased by ring stage 2 after Q frags load
//   stage0: K @17408, V @26112 ; stage1: K @34816, V @43520 ; stage2: K @0, V @8704
#define ATTN_SMEM (52224 * 2)

__global__ __launch_bounds__(256) void attn_kernel() {
    extern __shared__ __nv_bfloat16 dynsm[];
    __nv_bfloat16* Qh = dynsm;
    __nv_bfloat16* Kx[3] = { dynsm + 17408, dynsm + 34816, dynsm };
    __nv_bfloat16* Vx[3] = { dynsm + 26112, dynsm + 43520, dynsm + 8704 };

    int q0 = blockIdx.x * 128;
    int bh = blockIdx.y;
    const __nv_bfloat16* qg = g_qext + (size_t)bh * N_ * 128;
    const __nv_bfloat16* kg = g_kext + (size_t)bh * N_ * 128;
    const __nv_bfloat16* vhi = g_vhi + (size_t)bh * HD * N_;
    const __nv_bfloat16* vlo = g_vlo + (size_t)bh * HD * N_;

    int tid = threadIdx.x, w = tid >> 5, lane = tid & 31;

    // ---- issue Q stage (group 0) ----
    #pragma unroll
    for (int i = 0; i < 8; i++) {
        int idx = tid + i * 256;
        int row = idx >> 4, seg = idx & 15;
        CPA(smem_u32(&Qh[row * QSTR + seg * 8]), qg + (size_t)(q0 + row) * 128 + seg * 8);
    }
    CPCOMMIT();

    // ---- issue KV chunk 0 and 1 (groups 1, 2) ----
    #pragma unroll
    for (int st = 0; st < 2; st++) {
        int nb = st * 64;
        #pragma unroll
        for (int i = 0; i < 4; i++) {
            int idx = tid + i * 256;
            int row = idx >> 4, seg = idx & 15;
            CPA(smem_u32(&Kx[st][row * QSTR + seg * 8]),
                kg + (size_t)(nb + row) * 128 + seg * 8);
        }
        #pragma unroll
        for (int i = 0; i < 4; i++) {
            int idx = tid + i * 256;
            int d = idx >> 4, seg = idx & 15;
            const __nv_bfloat16* src = (seg < 8 ? vhi : vlo) + (size_t)d * N_ + nb + (seg & 7) * 8;
            CPA(smem_u32(&Vx[st][d * QSTR + seg * 8]), src);
        }
        CPCOMMIT();
    }

    // ---- Q fragments ----
    CPWAIT(2);
    __syncthreads();
    uint32_t qbase = smem_u32(Qh);
    int ar = w * 16 + (lane & 15);
    int ac = (lane >> 4) * 8;
    uint32_t qh[4][4], ql[4][4];
    #pragma unroll
    for (int ks = 0; ks < 4; ks++) {
        ldsm_x4(qh[ks], qbase + (ar * QSTR + ks * 16 + ac) * 2);
        ldsm_x4(ql[ks], qbase + (ar * QSTR + 64 + ks * 16 + ac) * 2);
    }
    __syncthreads();   // Qh dead -> stage 2 may reuse

    float oacc[8][4];
    #pragma unroll
    for (int i = 0; i < 8; i++)
        { oacc[i][0]=0.f; oacc[i][1]=0.f; oacc[i][2]=0.f; oacc[i][3]=0.f; }
    float m0 = -1e30f, m1 = -1e30f, l0 = 0.f, l1 = 0.f;

    int bRowP = (lane & 7) + ((lane >> 4) * 8);
    int bColP = ((lane >> 3) & 1) * 8;

    #pragma unroll 1
    for (int ch = 0; ch < 16; ch++) {
        if (ch < 14) CPWAIT(1); else CPWAIT(0);
        __syncthreads();

        // issue chunk ch+2 into ring (after barrier: no warp still reads it)
        if (ch + 2 < 16) {
            int st = (ch + 2) % 3, nb = (ch + 2) * 64;
            #pragma unroll
            for (int i = 0; i < 4; i++) {
                int idx = tid + i * 256;
                int row = idx >> 4, seg = idx & 15;
                CPA(smem_u32(&Kx[st][row * QSTR + seg * 8]),
                    kg + (size_t)(nb + row) * 128 + seg * 8);
            }
            #pragma unroll
            for (int i = 0; i < 4; i++) {
                int idx = tid + i * 256;
                int d = idx >> 4, seg = idx & 15;
                const __nv_bfloat16* src = (seg < 8 ? vhi : vlo) + (size_t)d * N_ + nb + (seg & 7) * 8;
                CPA(smem_u32(&Vx[st][d * QSTR + seg * 8]), src);
            }
            CPCOMMIT();
        }

        uint32_t kbase = smem_u32(Kx[ch % 3]);
        uint32_t vbase = smem_u32(Vx[ch % 3]);

        // ---- S = Q_ext . K_ext^T ----
        float sacc[8][4];
        #pragma unroll
        for (int i = 0; i < 8; i++)
            { sacc[i][0]=0.f; sacc[i][1]=0.f; sacc[i][2]=0.f; sacc[i][3]=0.f; }

        #pragma unroll
        for (int ks = 0; ks < 12; ks++) {
            const uint32_t* A = (ks < 4) ? qh[ks] : (ks < 8) ? qh[ks-4] : ql[ks-8];
            int col = ((ks < 4) ? ks*16 : (ks < 8) ? 64 + (ks-4)*16 : (ks-8)*16) + bColP;
            #pragma unroll
            for (int n2 = 0; n2 < 4; n2++) {
                uint32_t b4[4];
                ldsm_x4(b4, kbase + ((n2*16 + bRowP) * QSTR + col) * 2);
                mma_bf16(sacc[2*n2],   A, &b4[0]);
                mma_bf16(sacc[2*n2+1], A, &b4[2]);
            }
        }

        // ---- online softmax ----
        float mx0 = -1e30f, mx1 = -1e30f;
        #pragma unroll
        for (int nf = 0; nf < 8; nf++) {
            mx0 = fmaxf(mx0, fmaxf(sacc[nf][0], sacc[nf][1]));
            mx1 = fmaxf(mx1, fmaxf(sacc[nf][2], sacc[nf][3]));
        }
        mx0 = fmaxf(mx0, __shfl_xor_sync(0xffffffffu, mx0, 1));
        mx0 = fmaxf(mx0, __shfl_xor_sync(0xffffffffu, mx0, 2));
        mx1 = fmaxf(mx1, __shfl_xor_sync(0xffffffffu, mx1, 1));
        mx1 = fmaxf(mx1, __shfl_xor_sync(0xffffffffu, mx1, 2));
        float mn0 = fmaxf(m0, mx0), mn1 = fmaxf(m1, mx1);
        float f0 = ex2((m0 - mn0) * LOG2E), f1 = ex2((m1 - mn1) * LOG2E);

        float rs0 = 0.f, rs1 = 0.f;
        #pragma unroll
        for (int nf = 0; nf < 8; nf++) {
            sacc[nf][0] = ex2((sacc[nf][0] - mn0) * LOG2E);
            sacc[nf][1] = ex2((sacc[nf][1] - mn0) * LOG2E);
            sacc[nf][2] = ex2((sacc[nf][2] - mn1) * LOG2E);
            sacc[nf][3] = ex2((sacc[nf][3] - mn1) * LOG2E);
            rs0 += sacc[nf][0] + sacc[nf][1];
            rs1 += sacc[nf][2] + sacc[nf][3];
        }
        rs0 += __shfl_xor_sync(0xffffffffu, rs0, 1);
        rs0 += __shfl_xor_sync(0xffffffffu, rs0, 2);
        rs1 += __shfl_xor_sync(0xffffffffu, rs1, 1);
        rs1 += __shfl_xor_sync(0xffffffffu, rs1, 2);
        l0 = l0 * f0 + rs0; l1 = l1 * f1 + rs1;
        m0 = mn0; m1 = mn1;
        #pragma unroll
        for (int df = 0; df < 8; df++) {
            oacc[df][0] *= f0; oacc[df][1] *= f0;
            oacc[df][2] *= f1; oacc[df][3] *= f1;
        }

        // ---- P -> A fragments (hi & lo) ----
        uint32_t phi[4][4], plo[4][4];
        #pragma unroll
        for (int ks = 0; ks < 4; ks++) {
            int j = 2 * ks;
            float p00 = sacc[j][0],   p01 = sacc[j][1];
            float p02 = sacc[j][2],   p03 = sacc[j][3];
            float p10 = sacc[j+1][0], p11 = sacc[j+1][1];
            float p12 = sacc[j+1][2], p13 = sacc[j+1][3];
            phi[ks][0] = packbf2(p00, p01);
            phi[ks][1] = packbf2(p02, p03);
            phi[ks][2] = packbf2(p10, p11);
            phi[ks][3] = packbf2(p12, p13);
            __nv_bfloat162* hp;
            hp = (__nv_bfloat162*)&phi[ks][0];
            plo[ks][0] = packbf2(p00 - __bfloat162float(hp->x), p01 - __bfloat162float(hp->y));
            hp = (__nv_bfloat162*)&phi[ks][1];
            plo[ks][1] = packbf2(p02 - __bfloat162float(hp->x), p03 - __bfloat162float(hp->y));
            hp = (__nv_bfloat162*)&phi[ks][2];
            plo[ks][2] = packbf2(p10 - __bfloat162float(hp->x), p11 - __bfloat162float(hp->y));
            hp = (__nv_bfloat162*)&phi[ks][3];
            plo[ks][3] = packbf2(p12 - __bfloat162float(hp->x), p13 - __bfloat162float(hp->y));
        }

        // ---- O += P_ext . V_ext ----
        #pragma unroll
        for (int ks = 0; ks < 12; ks++) {
            const uint32_t* A = (ks < 4) ? phi[ks] : (ks < 8) ? phi[ks-4] : plo[ks-8];
            int col = ((ks < 4) ? ks*16 : (ks < 8) ? 64 + (ks-4)*16 : (ks-8)*16) + bColP;
            #pragma unroll
            for (int d2 = 0; d2 < 4; d2++) {
                uint32_t b4[4];
                ldsm_x4(b4, vbase + ((d2*16 + bRowP) * QSTR + col) * 2);
                mma_bf16(oacc[2*d2],   A, &b4[0]);
                mma_bf16(oacc[2*d2+1], A, &b4[2]);
            }
        }
    }

    // ---- epilogue ----
    float inv0 = 1.f / l0, inv1 = 1.f / l1;
    int b = bh >> 3, h = bh & 7;
    int row0 = q0 + w * 16 + (lane >> 2);
    #pragma unroll
    for (int df = 0; df < 8; df++) {
        int chn = h * HD + df * 8 + (lane & 3) * 2;
        #pragma unroll
        for (int r = 0; r < 2; r++) {
            int row = row0 + r * 8;
            float v0 = oacc[df][r*2 + 0] * (r ? inv1 : inv0);
            float v1 = oacc[df][r*2 + 1] * (r ? inv1 : inv0);
            uint32_t hp = packbf2(v0, v1);
            __nv_bfloat162 hb = *(__nv_bfloat162*)&hp;
            uint32_t lp = packbf2(v0 - __bfloat162float(hb.x), v1 - __bfloat162float(hb.y));
            size_t eb = ((size_t)b * N_ + row) * KEXT + chn;
            *(uint32_t*)&g_obuf_ext[eb]          = hp;
            *(uint32_t*)&g_obuf_ext[eb + C_]     = hp;
            *(uint32_t*)&g_obuf_ext[eb + 2*C_]   = lp;
        }
    }
}

// ---------------------------------------------------------------------------
// 4) Proj GEMM + bias + residual -> out[b][c][n]
// ---------------------------------------------------------------------------
__global__ __launch_bounds__(256) void proj_gemm(const float* __restrict__ bias,
                                                 const float* __restrict__ x,
                                                 float* __restrict__ out) {
    int n0 = blockIdx.x * 128, m0 = blockIdx.y * 128, b = blockIdx.z;

    float acc[4][4][4];
    #pragma unroll
    for (int i = 0; i < 4; i++)
        #pragma unroll
        for (int j = 0; j < 4; j++)
            { acc[i][j][0]=0.f; acc[i][j][1]=0.f; acc[i][j][2]=0.f; acc[i][j][3]=0.f; }

    gemm_mainloop(acc,
        g_wproj_ext + (size_t)m0 * KEXT,
        g_obuf_ext + ((size_t)b * N_ + n0) * KEXT);

    int wid = threadIdx.x >> 5, lane = threadIdx.x & 31;
    int wm = (wid >> 2) * 64, wn = (wid & 3) * 32;

    #pragma unroll
    for (int mi = 0; mi < 4; mi++) {
        #pragma unroll
        for (int half = 0; half < 2; half++) {
            int chn = m0 + wm + mi*16 + (lane >> 2) + half*8;
            float bv = bias[chn];
            size_t rowbase = ((size_t)b * C_ + chn) * N_;
            #pragma unroll
            for (int ni = 0; ni < 4; ni++) {
                int n = n0 + wn + ni*8 + (lane & 3)*2;
                float2 xv = *(const float2*)&x[rowbase + n];
                float2 v;
                v.x = acc[mi][ni][half*2 + 0] + bv + xv.x;
                v.y = acc[mi][ni][half*2 + 1] + bv + xv.y;
                *(float2*)&out[rowbase + n] = v;
            }
        }
    }
}

// ---------------------------------------------------------------------------
extern "C" void kernel_launch(void* const* d_in, const int* in_sizes, int n_in,
                              void* d_out, int out_size) {
    const float* x      = (const float*)d_in[0];
    const float* norm_w = (const float*)d_in[1];
    const float* norm_b = (const float*)d_in[2];
    const float* qkv_w  = (const float*)d_in[3];
    const float* qkv_b  = (const float*)d_in[4];
    const float* proj_w = (const float*)d_in[5];
    const float* proj_b = (const float*)d_in[6];
    float* out = (float*)d_out;

    cudaFuncSetAttribute(gn_kernel, cudaFuncAttributeMaxDynamicSharedMemorySize, 65536);
    cudaFuncSetAttribute(qkv_gemm, cudaFuncAttributeMaxDynamicSharedMemorySize, GEMM_SMEM);
    cudaFuncSetAttribute(proj_gemm, cudaFuncAttributeMaxDynamicSharedMemorySize, GEMM_SMEM);
    cudaFuncSetAttribute(attn_kernel, cudaFuncAttributeMaxDynamicSharedMemorySize, ATTN_SMEM);

    __nv_bfloat16 *wq, *wp;
    cudaGetSymbolAddress((void**)&wq, g_wqkv_ext);
    cudaGetSymbolAddress((void**)&wp, g_wproj_ext);

    convw_kernel<<<3 * C_, 128>>>(qkv_w, wq);
    convw_kernel<<<C_, 128>>>(proj_w, wp);
    gn_kernel<<<B_ * G_, 256, 65536>>>(x, norm_w, norm_b);
    qkv_gemm<<<dim3(N_ / 128, (3 * C_) / 128, B_), 256, GEMM_SMEM>>>(qkv_b);
    attn_kernel<<<dim3(N_ / 128, B_ * NH), 256, ATTN_SMEM>>>();
    proj_gemm<<<dim3(N_ / 128, C_ / 128, B_), 256, GEMM_SMEM>>>(proj_b, x, out);
}

// round 7
// speedup vs baseline: 4.4177x; 1.0966x over previous
#include <cuda_runtime.h>
#include <cuda_bf16.h>
#include <cstdint>

#define B_   16
#define C_   512
#define NH   8
#define HD   64
#define N_   1024
#define G_   32
#define CPG  16
#define EPSV 1e-5f
#define KEXT 1536
#define LOG2E 1.4426950408889634f

// ---------------- scratch (device globals; no allocation allowed) -----------
__device__ __nv_bfloat16 g_qext[(size_t)B_ * NH * N_ * 128];   // [b][h][n][hi64|lo64], pre-scaled
__device__ __nv_bfloat16 g_kext[(size_t)B_ * NH * N_ * 128];   // [b][h][n][hi64|lo64]
__device__ __nv_bfloat16 g_vhi[(size_t)B_ * NH * HD * N_];     // [b][h][d][n]
__device__ __nv_bfloat16 g_vlo[(size_t)B_ * NH * HD * N_];
__device__ __nv_bfloat16 g_hn_ext[(size_t)B_ * N_ * KEXT];
__device__ __nv_bfloat16 g_obuf_ext[(size_t)B_ * N_ * KEXT];
__device__ __nv_bfloat16 g_wqkv_ext[(size_t)(3*C_) * KEXT];
__device__ __nv_bfloat16 g_wproj_ext[(size_t)C_ * KEXT];

// ---------------- PTX helpers (baseline-safe for compute_103) ---------------
__device__ __forceinline__ uint32_t smem_u32(const void* p) {
    uint32_t a;
    asm("{ .reg .u64 t; cvta.to.shared.u64 t, %1; cvt.u32.u64 %0, t; }" : "=r"(a) : "l"(p));
    return a;
}
__device__ __forceinline__ void ldsm_x4(uint32_t* r, uint32_t addr) {
    asm volatile("ldmatrix.sync.aligned.m8n8.x4.shared.b16 {%0,%1,%2,%3}, [%4];"
                 : "=r"(r[0]), "=r"(r[1]), "=r"(r[2]), "=r"(r[3]) : "r"(addr));
}
__device__ __forceinline__ void mma_bf16(float* c, const uint32_t* a, const uint32_t* b) {
    asm volatile("mma.sync.aligned.m16n8k16.row.col.f32.bf16.bf16.f32 "
                 "{%0,%1,%2,%3}, {%4,%5,%6,%7}, {%8,%9}, {%0,%1,%2,%3};"
                 : "+f"(c[0]), "+f"(c[1]), "+f"(c[2]), "+f"(c[3])
                 : "r"(a[0]), "r"(a[1]), "r"(a[2]), "r"(a[3]), "r"(b[0]), "r"(b[1]));
}
__device__ __forceinline__ float ex2(float x) {
    float r; asm("ex2.approx.f32 %0, %1;" : "=f"(r) : "f"(x)); return r;
}
__device__ __forceinline__ uint32_t packbf2(float a, float b) {
    __nv_bfloat162 t; t.x = __float2bfloat16(a); t.y = __float2bfloat16(b);
    return *(uint32_t*)&t;
}
#define CPA(dst, src) \
    asm volatile("cp.async.cg.shared.global [%0], [%1], 16;" :: "r"(dst), "l"(src))
#define CPCOMMIT() asm volatile("cp.async.commit_group;")
#define CPWAIT(n)  asm volatile("cp.async.wait_group %0;" :: "n"(n))

// ---------------------------------------------------------------------------
// 0) Weight split
// ---------------------------------------------------------------------------
__global__ void convw_kernel(const float* __restrict__ w, __nv_bfloat16* __restrict__ ext) {
    int r = blockIdx.x;
    for (int c = threadIdx.x; c < C_; c += 128) {
        float v = w[(size_t)r * C_ + c];
        __nv_bfloat16 hi = __float2bfloat16(v);
        __nv_bfloat16 lo = __float2bfloat16(v - __bfloat162float(hi));
        size_t base = (size_t)r * KEXT;
        ext[base + c]          = hi;
        ext[base + C_ + c]     = lo;
        ext[base + 2 * C_ + c] = hi;
    }
}

// ---------------------------------------------------------------------------
// 1) GroupNorm + transpose + bf16 split
// ---------------------------------------------------------------------------
__global__ __launch_bounds__(256) void gn_kernel(const float* __restrict__ x,
                                                 const float* __restrict__ w,
                                                 const float* __restrict__ bb) {
    extern __shared__ float gsm[];
    int bg = blockIdx.x;
    int g = bg & (G_ - 1), b = bg >> 5;
    const float4* x4 = (const float4*)(x + (size_t)bg * CPG * N_);
    float4* s4 = (float4*)gsm;
    int tid = threadIdx.x;

    float s = 0.f, s2 = 0.f;
    #pragma unroll 4
    for (int i = tid; i < 4096; i += 256) {
        float4 v = x4[i];
        s4[i] = v;
        s  += v.x + v.y + v.z + v.w;
        s2 += v.x*v.x + v.y*v.y + v.z*v.z + v.w*v.w;
    }
    __shared__ float rs[256], rs2[256];
    rs[tid] = s; rs2[tid] = s2;
    __syncthreads();
    for (int off = 128; off > 0; off >>= 1) {
        if (tid < off) { rs[tid] += rs[tid+off]; rs2[tid] += rs2[tid+off]; }
        __syncthreads();
    }
    float mean = rs[0] * (1.f/16384.f);
    float var  = rs2[0] * (1.f/16384.f) - mean*mean;
    float rstd = rsqrtf(var + EPSV);

    float sc[CPG], sh[CPG];
    #pragma unroll
    for (int c16 = 0; c16 < CPG; c16++) {
        int c = g*CPG + c16;
        sc[c16] = rstd * w[c];
        sh[c16] = bb[c] - mean * sc[c16];
    }

    union Pack { __nv_bfloat16 h[CPG]; uint4 v[2]; };
    for (int n = tid; n < N_; n += 256) {
        Pack hiP, loP;
        #pragma unroll
        for (int c16 = 0; c16 < CPG; c16++) {
            float v = gsm[c16 * N_ + n] * sc[c16] + sh[c16];
            __nv_bfloat16 hv = __float2bfloat16(v);
            hiP.h[c16] = hv;
            loP.h[c16] = __float2bfloat16(v - __bfloat162float(hv));
        }
        __nv_bfloat16* dst = g_hn_ext + ((size_t)b * N_ + n) * KEXT + g * CPG;
        *(uint4*)(dst)          = hiP.v[0]; *(uint4*)(dst + 8)          = hiP.v[1];
        *(uint4*)(dst + C_)     = hiP.v[0]; *(uint4*)(dst + C_ + 8)     = hiP.v[1];
        *(uint4*)(dst + 2*C_)   = loP.v[0]; *(uint4*)(dst + 2*C_ + 8)   = loP.v[1];
    }
}

// ---------------------------------------------------------------------------
// HMMA GEMM mainloop: 2-stage cp.async (R4 skeleton) + fragment double-buffer.
// ---------------------------------------------------------------------------
#define SSTR 88
#define STAGE_U (2 * 128 * SSTR)
#define GEMM_SMEM (2 * STAGE_U * 2)        // 90112 B

__device__ __forceinline__ void gemm_issue(__nv_bfloat16* As, __nv_bfloat16* Bs,
                                           const __nv_bfloat16* Abase,
                                           const __nv_bfloat16* Bbase,
                                           int k0, int ldRow, int ldSeg) {
    #pragma unroll
    for (int rr = 0; rr < 4; rr++) {
        int row = ldRow + rr * 32;
        CPA(smem_u32(&As[row * SSTR + ldSeg * 8]),
            Abase + (size_t)row * KEXT + k0 + ldSeg * 8);
        CPA(smem_u32(&Bs[row * SSTR + ldSeg * 8]),
            Bbase + (size_t)row * KEXT + k0 + ldSeg * 8);
    }
    CPCOMMIT();
}

__device__ __forceinline__ void gemm_mainloop(float acc[4][4][4],
                                              const __nv_bfloat16* __restrict__ Abase,
                                              const __nv_bfloat16* __restrict__ Bbase) {
    extern __shared__ __nv_bfloat16 dynsm[];
    __nv_bfloat16* As[2] = { dynsm, dynsm + STAGE_U };
    __nv_bfloat16* Bs[2] = { dynsm + 128*SSTR, dynsm + STAGE_U + 128*SSTR };

    int tid = threadIdx.x, wid = tid >> 5, lane = tid & 31;
    int wm = (wid >> 2) * 64;
    int wn = (wid & 3) * 32;
    int aRow = wm + (lane & 15), aCol = (lane >> 4) * 8;
    int bRowP = (lane & 7) + ((lane >> 4) * 8);
    int bColP = ((lane >> 3) & 1) * 8;
    int ldRow = tid >> 3;
    int ldSeg = tid & 7;

    gemm_issue(As[0], Bs[0], Abase, Bbase, 0, ldRow, ldSeg);

    #pragma unroll 1
    for (int c = 0; c < KEXT / 64; c++) {
        if (c + 1 < KEXT / 64) {
            gemm_issue(As[(c+1)&1], Bs[(c+1)&1], Abase, Bbase, (c+1)*64, ldRow, ldSeg);
            CPWAIT(1);
        } else {
            CPWAIT(0);
        }
        __syncthreads();

        uint32_t smA = smem_u32(As[c&1]), smB = smem_u32(Bs[c&1]);
        uint32_t af[2][4][4], bf[2][2][4];
        // preload ks=0 fragments
        #pragma unroll
        for (int mi = 0; mi < 4; mi++)
            ldsm_x4(af[0][mi], smA + ((aRow + mi*16) * SSTR + aCol) * 2);
        #pragma unroll
        for (int n2 = 0; n2 < 2; n2++)
            ldsm_x4(bf[0][n2], smB + ((wn + n2*16 + bRowP) * SSTR + bColP) * 2);

        #pragma unroll
        for (int ks = 0; ks < 4; ks++) {
            int cur = ks & 1, nxt = cur ^ 1;
            if (ks < 3) {
                #pragma unroll
                for (int mi = 0; mi < 4; mi++)
                    ldsm_x4(af[nxt][mi], smA + ((aRow + mi*16) * SSTR + (ks+1)*16 + aCol) * 2);
                #pragma unroll
                for (int n2 = 0; n2 < 2; n2++)
                    ldsm_x4(bf[nxt][n2], smB + ((wn + n2*16 + bRowP) * SSTR + (ks+1)*16 + bColP) * 2);
            }
            #pragma unroll
            for (int mi = 0; mi < 4; mi++)
                #pragma unroll
                for (int n2 = 0; n2 < 2; n2++) {
                    mma_bf16(acc[mi][2*n2],   af[cur][mi], &bf[cur][n2][0]);
                    mma_bf16(acc[mi][2*n2+1], af[cur][mi], &bf[cur][n2][2]);
                }
        }
        __syncthreads();
    }
}

// ---------------------------------------------------------------------------
// 2) QKV GEMM -> Q,K ext bf16 [b][h][n][128] (smem-staged coalesced stores);
//    V hi/lo planes [b][h][d][n]
// ---------------------------------------------------------------------------
#define ESTR 136   // staging row stride (bf16): conflict-free quads, 16B-aligned rows

__global__ __launch_bounds__(256, 2) void qkv_gemm(const float* __restrict__ bias) {
    int n0 = blockIdx.x * 128, m0 = blockIdx.y * 128, b = blockIdx.z;

    float acc[4][4][4];
    #pragma unroll
    for (int i = 0; i < 4; i++)
        #pragma unroll
        for (int j = 0; j < 4; j++)
            { acc[i][j][0]=0.f; acc[i][j][1]=0.f; acc[i][j][2]=0.f; acc[i][j][3]=0.f; }

    gemm_mainloop(acc,
        g_wqkv_ext + (size_t)m0 * KEXT,
        g_hn_ext + ((size_t)b * N_ + n0) * KEXT);

    extern __shared__ __nv_bfloat16 dynsm[];
    int tid = threadIdx.x, wid = tid >> 5, lane = tid & 31;
    int wm = (wid >> 2) * 64, wn = (wid & 3) * 32;
    int s = m0 >> 9;                      // uniform per CTA

    if (s == 2) {                         // V path
        #pragma unroll
        for (int mi = 0; mi < 4; mi++) {
            #pragma unroll
            for (int half = 0; half < 2; half++) {
                int o = m0 + wm + mi*16 + (lane >> 2) + half*8;
                int rem = o & 511, h = rem >> 6, d = rem & 63;
                float bv = bias[o];
                size_t vb = (((size_t)b * NH + h) * HD + d) * N_;
                #pragma unroll
                for (int ni = 0; ni < 4; ni++) {
                    int n = n0 + wn + ni*8 + (lane & 3)*2;
                    float v0 = acc[mi][ni][half*2 + 0] + bv;
                    float v1 = acc[mi][ni][half*2 + 1] + bv;
                    uint32_t hp = packbf2(v0, v1);
                    __nv_bfloat162 hb = *(__nv_bfloat162*)&hp;
                    uint32_t lp = packbf2(v0 - __bfloat162float(hb.x),
                                          v1 - __bfloat162float(hb.y));
                    *(uint32_t*)&g_vhi[vb + n] = hp;
                    *(uint32_t*)&g_vlo[vb + n] = lp;
                }
            }
        }
    } else {                              // Q/K: stage in smem, coalesced copy-out
        float scl = (s == 0) ? 0.125f : 1.0f;
        #pragma unroll
        for (int mi = 0; mi < 4; mi++) {
            #pragma unroll
            for (int half = 0; half < 2; half++) {
                int o = m0 + wm + mi*16 + (lane >> 2) + half*8;
                int hp = (o >> 6) & 1, d = o & 63;
                float bv = bias[o];
                __nv_bfloat16* Eb = dynsm + hp * (128 * ESTR);
                #pragma unroll
                for (int ni = 0; ni < 4; ni++) {
                    int nloc = wn + ni*8 + (lane & 3)*2;
                    float v0 = (acc[mi][ni][half*2 + 0] + bv) * scl;
                    float v1 = (acc[mi][ni][half*2 + 1] + bv) * scl;
                    __nv_bfloat16 h0 = __float2bfloat16(v0);
                    __nv_bfloat16 h1 = __float2bfloat16(v1);
                    Eb[nloc * ESTR + d]            = h0;
                    Eb[nloc * ESTR + 64 + d]       = __float2bfloat16(v0 - __bfloat162float(h0));
                    Eb[(nloc+1) * ESTR + d]        = h1;
                    Eb[(nloc+1) * ESTR + 64 + d]   = __float2bfloat16(v1 - __bfloat162float(h1));
                }
            }
        }
        __syncthreads();
        int h0g = (m0 & 511) >> 6;
        __nv_bfloat16* outp = (s == 0 ? g_qext : g_kext);
        #pragma unroll
        for (int i = 0; i < 16; i++) {
            int f = tid + i * 256;
            int hp = f >> 11, r = f & 2047, nloc = r >> 4, seg = r & 15;
            *(uint4*)(outp + (((size_t)b * NH + h0g + hp) * N_ + n0 + nloc) * 128 + seg * 8)
                = *(uint4*)(dynsm + hp * (128 * ESTR) + nloc * ESTR + seg * 8);
        }
    }
}

// ---------------------------------------------------------------------------
// 3) HMMA flash attention: pre-split Q/K/V, 3-ring; khi/vhi fragments reused.
// ---------------------------------------------------------------------------
#define QSTR 136
#define ATTN_SMEM (52224 * 2)

__global__ __launch_bounds__(256) void attn_kernel() {
    extern __shared__ __nv_bfloat16 dynsm[];
    __nv_bfloat16* Qh = dynsm;
    __nv_bfloat16* Kx[3] = { dynsm + 17408, dynsm + 34816, dynsm };
    __nv_bfloat16* Vx[3] = { dynsm + 26112, dynsm + 43520, dynsm + 8704 };

    int q0 = blockIdx.x * 128;
    int bh = blockIdx.y;
    const __nv_bfloat16* qg = g_qext + (size_t)bh * N_ * 128;
    const __nv_bfloat16* kg = g_kext + (size_t)bh * N_ * 128;
    const __nv_bfloat16* vhi = g_vhi + (size_t)bh * HD * N_;
    const __nv_bfloat16* vlo = g_vlo + (size_t)bh * HD * N_;

    int tid = threadIdx.x, w = tid >> 5, lane = tid & 31;

    #pragma unroll
    for (int i = 0; i < 8; i++) {
        int idx = tid + i * 256;
        int row = idx >> 4, seg = idx & 15;
        CPA(smem_u32(&Qh[row * QSTR + seg * 8]), qg + (size_t)(q0 + row) * 128 + seg * 8);
    }
    CPCOMMIT();

    #pragma unroll
    for (int st = 0; st < 2; st++) {
        int nb = st * 64;
        #pragma unroll
        for (int i = 0; i < 4; i++) {
            int idx = tid + i * 256;
            int row = idx >> 4, seg = idx & 15;
            CPA(smem_u32(&Kx[st][row * QSTR + seg * 8]),
                kg + (size_t)(nb + row) * 128 + seg * 8);
        }
        #pragma unroll
        for (int i = 0; i < 4; i++) {
            int idx = tid + i * 256;
            int d = idx >> 4, seg = idx & 15;
            const __nv_bfloat16* src = (seg < 8 ? vhi : vlo) + (size_t)d * N_ + nb + (seg & 7) * 8;
            CPA(smem_u32(&Vx[st][d * QSTR + seg * 8]), src);
        }
        CPCOMMIT();
    }

    CPWAIT(2);
    __syncthreads();
    uint32_t qbase = smem_u32(Qh);
    int ar = w * 16 + (lane & 15);
    int ac = (lane >> 4) * 8;
    uint32_t qh[4][4], ql[4][4];
    #pragma unroll
    for (int ks = 0; ks < 4; ks++) {
        ldsm_x4(qh[ks], qbase + (ar * QSTR + ks * 16 + ac) * 2);
        ldsm_x4(ql[ks], qbase + (ar * QSTR + 64 + ks * 16 + ac) * 2);
    }
    __syncthreads();

    float oacc[8][4];
    #pragma unroll
    for (int i = 0; i < 8; i++)
        { oacc[i][0]=0.f; oacc[i][1]=0.f; oacc[i][2]=0.f; oacc[i][3]=0.f; }
    float m0 = -1e30f, m1 = -1e30f, l0 = 0.f, l1 = 0.f;

    int bRowP = (lane & 7) + ((lane >> 4) * 8);
    int bColP = ((lane >> 3) & 1) * 8;

    #pragma unroll 1
    for (int ch = 0; ch < 16; ch++) {
        if (ch < 14) CPWAIT(1); else CPWAIT(0);
        __syncthreads();

        if (ch + 2 < 16) {
            int st = (ch + 2) % 3, nb = (ch + 2) * 64;
            #pragma unroll
            for (int i = 0; i < 4; i++) {
                int idx = tid + i * 256;
                int row = idx >> 4, seg = idx & 15;
                CPA(smem_u32(&Kx[st][row * QSTR + seg * 8]),
                    kg + (size_t)(nb + row) * 128 + seg * 8);
            }
            #pragma unroll
            for (int i = 0; i < 4; i++) {
                int idx = tid + i * 256;
                int d = idx >> 4, seg = idx & 15;
                const __nv_bfloat16* src = (seg < 8 ? vhi : vlo) + (size_t)d * N_ + nb + (seg & 7) * 8;
                CPA(smem_u32(&Vx[st][d * QSTR + seg * 8]), src);
            }
            CPCOMMIT();
        }

        uint32_t kbase = smem_u32(Kx[ch % 3]);
        uint32_t vbase = smem_u32(Vx[ch % 3]);

        // ---- S = Q_ext . K_ext^T (khi fragments reused for qh and ql) ----
        float sacc[8][4];
        #pragma unroll
        for (int i = 0; i < 8; i++)
            { sacc[i][0]=0.f; sacc[i][1]=0.f; sacc[i][2]=0.f; sacc[i][3]=0.f; }

        #pragma unroll
        for (int n2 = 0; n2 < 4; n2++) {
            uint32_t kb[4][4];
            #pragma unroll
            for (int ks = 0; ks < 4; ks++)
                ldsm_x4(kb[ks], kbase + ((n2*16 + bRowP) * QSTR + ks*16 + bColP) * 2);
            #pragma unroll
            for (int ks = 0; ks < 4; ks++) {
                mma_bf16(sacc[2*n2],   qh[ks], &kb[ks][0]);
                mma_bf16(sacc[2*n2+1], qh[ks], &kb[ks][2]);
            }
            #pragma unroll
            for (int ks = 0; ks < 4; ks++) {
                mma_bf16(sacc[2*n2],   ql[ks], &kb[ks][0]);
                mma_bf16(sacc[2*n2+1], ql[ks], &kb[ks][2]);
            }
            #pragma unroll
            for (int ks = 0; ks < 4; ks++)
                ldsm_x4(kb[ks], kbase + ((n2*16 + bRowP) * QSTR + 64 + ks*16 + bColP) * 2);
            #pragma unroll
            for (int ks = 0; ks < 4; ks++) {
                mma_bf16(sacc[2*n2],   qh[ks], &kb[ks][0]);
                mma_bf16(sacc[2*n2+1], qh[ks], &kb[ks][2]);
            }
        }

        // ---- online softmax ----
        float mx0 = -1e30f, mx1 = -1e30f;
        #pragma unroll
        for (int nf = 0; nf < 8; nf++) {
            mx0 = fmaxf(mx0, fmaxf(sacc[nf][0], sacc[nf][1]));
            mx1 = fmaxf(mx1, fmaxf(sacc[nf][2], sacc[nf][3]));
        }
        mx0 = fmaxf(mx0, __shfl_xor_sync(0xffffffffu, mx0, 1));
        mx0 = fmaxf(mx0, __shfl_xor_sync(0xffffffffu, mx0, 2));
        mx1 = fmaxf(mx1, __shfl_xor_sync(0xffffffffu, mx1, 1));
        mx1 = fmaxf(mx1, __shfl_xor_sync(0xffffffffu, mx1, 2));
        float mn0 = fmaxf(m0, mx0), mn1 = fmaxf(m1, mx1);
        float f0 = ex2((m0 - mn0) * LOG2E), f1 = ex2((m1 - mn1) * LOG2E);

        float rs0 = 0.f, rs1 = 0.f;
        #pragma unroll
        for (int nf = 0; nf < 8; nf++) {
            sacc[nf][0] = ex2((sacc[nf][0] - mn0) * LOG2E);
            sacc[nf][1] = ex2((sacc[nf][1] - mn0) * LOG2E);
            sacc[nf][2] = ex2((sacc[nf][2] - mn1) * LOG2E);
            sacc[nf][3] = ex2((sacc[nf][3] - mn1) * LOG2E);
            rs0 += sacc[nf][0] + sacc[nf][1];
            rs1 += sacc[nf][2] + sacc[nf][3];
        }
        rs0 += __shfl_xor_sync(0xffffffffu, rs0, 1);
        rs0 += __shfl_xor_sync(0xffffffffu, rs0, 2);
        rs1 += __shfl_xor_sync(0xffffffffu, rs1, 1);
        rs1 += __shfl_xor_sync(0xffffffffu, rs1, 2);
        l0 = l0 * f0 + rs0; l1 = l1 * f1 + rs1;
        m0 = mn0; m1 = mn1;
        #pragma unroll
        for (int df = 0; df < 8; df++) {
            oacc[df][0] *= f0; oacc[df][1] *= f0;
            oacc[df][2] *= f1; oacc[df][3] *= f1;
        }

        // ---- P -> A fragments (hi & lo) ----
        uint32_t phi[4][4], plo[4][4];
        #pragma unroll
        for (int ks = 0; ks < 4; ks++) {
            int j = 2 * ks;
            float p00 = sacc[j][0],   p01 = sacc[j][1];
            float p02 = sacc[j][2],   p03 = sacc[j][3];
            float p10 = sacc[j+1][0], p11 = sacc[j+1][1];
            float p12 = sacc[j+1][2], p13 = sacc[j+1][3];
            phi[ks][0] = packbf2(p00, p01);
            phi[ks][1] = packbf2(p02, p03);
            phi[ks][2] = packbf2(p10, p11);
            phi[ks][3] = packbf2(p12, p13);
            __nv_bfloat162* hp;
            hp = (__nv_bfloat162*)&phi[ks][0];
            plo[ks][0] = packbf2(p00 - __bfloat162float(hp->x), p01 - __bfloat162float(hp->y));
            hp = (__nv_bfloat162*)&phi[ks][1];
            plo[ks][1] = packbf2(p02 - __bfloat162float(hp->x), p03 - __bfloat162float(hp->y));
            hp = (__nv_bfloat162*)&phi[ks][2];
            plo[ks][2] = packbf2(p10 - __bfloat162float(hp->x), p11 - __bfloat162float(hp->y));
            hp = (__nv_bfloat162*)&phi[ks][3];
            plo[ks][3] = packbf2(p12 - __bfloat162float(hp->x), p13 - __bfloat162float(hp->y));
        }

        // ---- O += P_ext . V_ext (vhi fragments reused for phi and plo) ----
        #pragma unroll
        for (int d2 = 0; d2 < 4; d2++) {
            uint32_t vb4[4][4];
            #pragma unroll
            for (int ks = 0; ks < 4; ks++)
                ldsm_x4(vb4[ks], vbase + ((d2*16 + bRowP) * QSTR + ks*16 + bColP) * 2);
            #pragma unroll
            for (int ks = 0; ks < 4; ks++) {
                mma_bf16(oacc[2*d2],   phi[ks], &vb4[ks][0]);
                mma_bf16(oacc[2*d2+1], phi[ks], &vb4[ks][2]);
            }
            #pragma unroll
            for (int ks = 0; ks < 4; ks++) {
                mma_bf16(oacc[2*d2],   plo[ks], &vb4[ks][0]);
                mma_bf16(oacc[2*d2+1], plo[ks], &vb4[ks][2]);
            }
            #pragma unroll
            for (int ks = 0; ks < 4; ks++)
                ldsm_x4(vb4[ks], vbase + ((d2*16 + bRowP) * QSTR + 64 + ks*16 + bColP) * 2);
            #pragma unroll
            for (int ks = 0; ks < 4; ks++) {
                mma_bf16(oacc[2*d2],   phi[ks], &vb4[ks][0]);
                mma_bf16(oacc[2*d2+1], phi[ks], &vb4[ks][2]);
            }
        }
    }

    // ---- epilogue ----
    float inv0 = 1.f / l0, inv1 = 1.f / l1;
    int b = bh >> 3, h = bh & 7;
    int row0 = q0 + w * 16 + (lane >> 2);
    #pragma unroll
    for (int df = 0; df < 8; df++) {
        int chn = h * HD + df * 8 + (lane & 3) * 2;
        #pragma unroll
        for (int r = 0; r < 2; r++) {
            int row = row0 + r * 8;
            float v0 = oacc[df][r*2 + 0] * (r ? inv1 : inv0);
            float v1 = oacc[df][r*2 + 1] * (r ? inv1 : inv0);
            uint32_t hp = packbf2(v0, v1);
            __nv_bfloat162 hb = *(__nv_bfloat162*)&hp;
            uint32_t lp = packbf2(v0 - __bfloat162float(hb.x), v1 - __bfloat162float(hb.y));
            size_t eb = ((size_t)b * N_ + row) * KEXT + chn;
            *(uint32_t*)&g_obuf_ext[eb]          = hp;
            *(uint32_t*)&g_obuf_ext[eb + C_]     = hp;
            *(uint32_t*)&g_obuf_ext[eb + 2*C_]   = lp;
        }
    }
}

// ---------------------------------------------------------------------------
// 4) Proj GEMM + bias + residual -> out[b][c][n]
// ---------------------------------------------------------------------------
__global__ __launch_bounds__(256, 2) void proj_gemm(const float* __restrict__ bias,
                                                    const float* __restrict__ x,
                                                    float* __restrict__ out) {
    int n0 = blockIdx.x * 128, m0 = blockIdx.y * 128, b = blockIdx.z;

    float acc[4][4][4];
    #pragma unroll
    for (int i = 0; i < 4; i++)
        #pragma unroll
        for (int j = 0; j < 4; j++)
            { acc[i][j][0]=0.f; acc[i][j][1]=0.f; acc[i][j][2]=0.f; acc[i][j][3]=0.f; }

    gemm_mainloop(acc,
        g_wproj_ext + (size_t)m0 * KEXT,
        g_obuf_ext + ((size_t)b * N_ + n0) * KEXT);

    int wid = threadIdx.x >> 5, lane = threadIdx.x & 31;
    int wm = (wid >> 2) * 64, wn = (wid & 3) * 32;

    #pragma unroll
    for (int mi = 0; mi < 4; mi++) {
        #pragma unroll
        for (int half = 0; half < 2; half++) {
            int chn = m0 + wm + mi*16 + (lane >> 2) + half*8;
            float bv = bias[chn];
            size_t rowbase = ((size_t)b * C_ + chn) * N_;
            #pragma unroll
            for (int ni = 0; ni < 4; ni++) {
                int n = n0 + wn + ni*8 + (lane & 3)*2;
                float2 xv = *(const float2*)&x[rowbase + n];
                float2 v;
                v.x = acc[mi][ni][half*2 + 0] + bv + xv.x;
                v.y = acc[mi][ni][half*2 + 1] + bv + xv.y;
                *(float2*)&out[rowbase + n] = v;
            }
        }
    }
}

// ---------------------------------------------------------------------------
extern "C" void kernel_launch(void* const* d_in, const int* in_sizes, int n_in,
                              void* d_out, int out_size) {
    const float* x      = (const float*)d_in[0];
    const float* norm_w = (const float*)d_in[1];
    const float* norm_b = (const float*)d_in[2];
    const float* qkv_w  = (const float*)d_in[3];
    const float* qkv_b  = (const float*)d_in[4];
    const float* proj_w = (const float*)d_in[5];
    const float* proj_b = (const float*)d_in[6];
    float* out = (float*)d_out;

    cudaFuncSetAttribute(gn_kernel, cudaFuncAttributeMaxDynamicSharedMemorySize, 65536);
    cudaFuncSetAttribute(qkv_gemm, cudaFuncAttributeMaxDynamicSharedMemorySize, GEMM_SMEM);
    cudaFuncSetAttribute(proj_gemm, cudaFuncAttributeMaxDynamicSharedMemorySize, GEMM_SMEM);
    cudaFuncSetAttribute(attn_kernel, cudaFuncAttributeMaxDynamicSharedMemorySize, ATTN_SMEM);

    __nv_bfloat16 *wq, *wp;
    cudaGetSymbolAddress((void**)&wq, g_wqkv_ext);
    cudaGetSymbolAddress((void**)&wp, g_wproj_ext);

    convw_kernel<<<3 * C_, 128>>>(qkv_w, wq);
    convw_kernel<<<C_, 128>>>(proj_w, wp);
    gn_kernel<<<B_ * G_, 256, 65536>>>(x, norm_w, norm_b);
    qkv_gemm<<<dim3(N_ / 128, (3 * C_) / 128, B_), 256, GEMM_SMEM>>>(qkv_b);
    attn_kernel<<<dim3(N_ / 128, B_ * NH), 256, ATTN_SMEM>>>();
    proj_gemm<<<dim3(N_ / 128, C_ / 128, B_), 256, GEMM_SMEM>>>(proj_b, x, out);
}

// round 8
// speedup vs baseline: 4.6681x; 1.0567x over previous
#include <cuda_runtime.h>
#include <cuda_bf16.h>
#include <cstdint>

#define B_   16
#define C_   512
#define NH   8
#define HD   64
#define N_   1024
#define G_   32
#define CPG  16
#define EPSV 1e-5f
#define KEXT 1536
#define LOG2E 1.4426950408889634f

// ---------------- scratch (device globals; no allocation allowed) -----------
__device__ __nv_bfloat16 g_qext[(size_t)B_ * NH * N_ * 128];   // [b][h][n][hi64|lo64], pre-scaled
__device__ __nv_bfloat16 g_kext[(size_t)B_ * NH * N_ * 128];   // [b][h][n][hi64|lo64]
__device__ __nv_bfloat16 g_vhi[(size_t)B_ * NH * HD * N_];     // [b][h][d][n]
__device__ __nv_bfloat16 g_vlo[(size_t)B_ * NH * HD * N_];
__device__ __nv_bfloat16 g_hn_ext[(size_t)B_ * N_ * KEXT];
__device__ __nv_bfloat16 g_obuf_ext[(size_t)B_ * N_ * KEXT];
__device__ __nv_bfloat16 g_wqkv_ext[(size_t)(3*C_) * KEXT];
__device__ __nv_bfloat16 g_wproj_ext[(size_t)C_ * KEXT];

// ---------------- PTX helpers (baseline-safe for compute_103) ---------------
__device__ __forceinline__ uint32_t smem_u32(const void* p) {
    uint32_t a;
    asm("{ .reg .u64 t; cvta.to.shared.u64 t, %1; cvt.u32.u64 %0, t; }" : "=r"(a) : "l"(p));
    return a;
}
__device__ __forceinline__ void ldsm_x4(uint32_t* r, uint32_t addr) {
    asm volatile("ldmatrix.sync.aligned.m8n8.x4.shared.b16 {%0,%1,%2,%3}, [%4];"
                 : "=r"(r[0]), "=r"(r[1]), "=r"(r[2]), "=r"(r[3]) : "r"(addr));
}
__device__ __forceinline__ void mma_bf16(float* c, const uint32_t* a, const uint32_t* b) {
    asm volatile("mma.sync.aligned.m16n8k16.row.col.f32.bf16.bf16.f32 "
                 "{%0,%1,%2,%3}, {%4,%5,%6,%7}, {%8,%9}, {%0,%1,%2,%3};"
                 : "+f"(c[0]), "+f"(c[1]), "+f"(c[2]), "+f"(c[3])
                 : "r"(a[0]), "r"(a[1]), "r"(a[2]), "r"(a[3]), "r"(b[0]), "r"(b[1]));
}
__device__ __forceinline__ float ex2(float x) {
    float r; asm("ex2.approx.f32 %0, %1;" : "=f"(r) : "f"(x)); return r;
}
__device__ __forceinline__ uint32_t packbf2(float a, float b) {
    __nv_bfloat162 t; t.x = __float2bfloat16(a); t.y = __float2bfloat16(b);
    return *(uint32_t*)&t;
}
#define CPA(dst, src) \
    asm volatile("cp.async.cg.shared.global [%0], [%1], 16;" :: "r"(dst), "l"(src))
#define CPCOMMIT() asm volatile("cp.async.commit_group;")
#define CPWAIT(n)  asm volatile("cp.async.wait_group %0;" :: "n"(n))

// ---------------------------------------------------------------------------
// 0) Weight split
// ---------------------------------------------------------------------------
__global__ void convw_kernel(const float* __restrict__ w, __nv_bfloat16* __restrict__ ext) {
    int r = blockIdx.x;
    for (int c = threadIdx.x; c < C_; c += 128) {
        float v = w[(size_t)r * C_ + c];
        __nv_bfloat16 hi = __float2bfloat16(v);
        __nv_bfloat16 lo = __float2bfloat16(v - __bfloat162float(hi));
        size_t base = (size_t)r * KEXT;
        ext[base + c]          = hi;
        ext[base + C_ + c]     = lo;
        ext[base + 2 * C_ + c] = hi;
    }
}

// ---------------------------------------------------------------------------
// 1) GroupNorm + transpose + bf16 split
// ---------------------------------------------------------------------------
__global__ __launch_bounds__(256) void gn_kernel(const float* __restrict__ x,
                                                 const float* __restrict__ w,
                                                 const float* __restrict__ bb) {
    extern __shared__ float gsm[];
    int bg = blockIdx.x;
    int g = bg & (G_ - 1), b = bg >> 5;
    const float4* x4 = (const float4*)(x + (size_t)bg * CPG * N_);
    float4* s4 = (float4*)gsm;
    int tid = threadIdx.x;

    float s = 0.f, s2 = 0.f;
    #pragma unroll 4
    for (int i = tid; i < 4096; i += 256) {
        float4 v = x4[i];
        s4[i] = v;
        s  += v.x + v.y + v.z + v.w;
        s2 += v.x*v.x + v.y*v.y + v.z*v.z + v.w*v.w;
    }
    __shared__ float rs[256], rs2[256];
    rs[tid] = s; rs2[tid] = s2;
    __syncthreads();
    for (int off = 128; off > 0; off >>= 1) {
        if (tid < off) { rs[tid] += rs[tid+off]; rs2[tid] += rs2[tid+off]; }
        __syncthreads();
    }
    float mean = rs[0] * (1.f/16384.f);
    float var  = rs2[0] * (1.f/16384.f) - mean*mean;
    float rstd = rsqrtf(var + EPSV);

    float sc[CPG], sh[CPG];
    #pragma unroll
    for (int c16 = 0; c16 < CPG; c16++) {
        int c = g*CPG + c16;
        sc[c16] = rstd * w[c];
        sh[c16] = bb[c] - mean * sc[c16];
    }

    union Pack { __nv_bfloat16 h[CPG]; uint4 v[2]; };
    for (int n = tid; n < N_; n += 256) {
        Pack hiP, loP;
        #pragma unroll
        for (int c16 = 0; c16 < CPG; c16++) {
            float v = gsm[c16 * N_ + n] * sc[c16] + sh[c16];
            __nv_bfloat16 hv = __float2bfloat16(v);
            hiP.h[c16] = hv;
            loP.h[c16] = __float2bfloat16(v - __bfloat162float(hv));
        }
        __nv_bfloat16* dst = g_hn_ext + ((size_t)b * N_ + n) * KEXT + g * CPG;
        *(uint4*)(dst)          = hiP.v[0]; *(uint4*)(dst + 8)          = hiP.v[1];
        *(uint4*)(dst + C_)     = hiP.v[0]; *(uint4*)(dst + C_ + 8)     = hiP.v[1];
        *(uint4*)(dst + 2*C_)   = loP.v[0]; *(uint4*)(dst + 2*C_ + 8)   = loP.v[1];
    }
}

// ---------------------------------------------------------------------------
// HMMA GEMM mainloop: 2-stage cp.async + fragment double-buffer (unchanged).
// ---------------------------------------------------------------------------
#define SSTR 88
#define STAGE_U (2 * 128 * SSTR)
#define GEMM_SMEM (2 * STAGE_U * 2)        // 90112 B

__device__ __forceinline__ void gemm_issue(__nv_bfloat16* As, __nv_bfloat16* Bs,
                                           const __nv_bfloat16* Abase,
                                           const __nv_bfloat16* Bbase,
                                           int k0, int ldRow, int ldSeg) {
    #pragma unroll
    for (int rr = 0; rr < 4; rr++) {
        int row = ldRow + rr * 32;
        CPA(smem_u32(&As[row * SSTR + ldSeg * 8]),
            Abase + (size_t)row * KEXT + k0 + ldSeg * 8);
        CPA(smem_u32(&Bs[row * SSTR + ldSeg * 8]),
            Bbase + (size_t)row * KEXT + k0 + ldSeg * 8);
    }
    CPCOMMIT();
}

__device__ __forceinline__ void gemm_mainloop(float acc[4][4][4],
                                              const __nv_bfloat16* __restrict__ Abase,
                                              const __nv_bfloat16* __restrict__ Bbase) {
    extern __shared__ __nv_bfloat16 dynsm[];
    __nv_bfloat16* As[2] = { dynsm, dynsm + STAGE_U };
    __nv_bfloat16* Bs[2] = { dynsm + 128*SSTR, dynsm + STAGE_U + 128*SSTR };

    int tid = threadIdx.x, wid = tid >> 5, lane = tid & 31;
    int wm = (wid >> 2) * 64;
    int wn = (wid & 3) * 32;
    int aRow = wm + (lane & 15), aCol = (lane >> 4) * 8;
    int bRowP = (lane & 7) + ((lane >> 4) * 8);
    int bColP = ((lane >> 3) & 1) * 8;
    int ldRow = tid >> 3;
    int ldSeg = tid & 7;

    gemm_issue(As[0], Bs[0], Abase, Bbase, 0, ldRow, ldSeg);

    #pragma unroll 1
    for (int c = 0; c < KEXT / 64; c++) {
        if (c + 1 < KEXT / 64) {
            gemm_issue(As[(c+1)&1], Bs[(c+1)&1], Abase, Bbase, (c+1)*64, ldRow, ldSeg);
            CPWAIT(1);
        } else {
            CPWAIT(0);
        }
        __syncthreads();

        uint32_t smA = smem_u32(As[c&1]), smB = smem_u32(Bs[c&1]);
        uint32_t af[2][4][4], bf[2][2][4];
        #pragma unroll
        for (int mi = 0; mi < 4; mi++)
            ldsm_x4(af[0][mi], smA + ((aRow + mi*16) * SSTR + aCol) * 2);
        #pragma unroll
        for (int n2 = 0; n2 < 2; n2++)
            ldsm_x4(bf[0][n2], smB + ((wn + n2*16 + bRowP) * SSTR + bColP) * 2);

        #pragma unroll
        for (int ks = 0; ks < 4; ks++) {
            int cur = ks & 1, nxt = cur ^ 1;
            if (ks < 3) {
                #pragma unroll
                for (int mi = 0; mi < 4; mi++)
                    ldsm_x4(af[nxt][mi], smA + ((aRow + mi*16) * SSTR + (ks+1)*16 + aCol) * 2);
                #pragma unroll
                for (int n2 = 0; n2 < 2; n2++)
                    ldsm_x4(bf[nxt][n2], smB + ((wn + n2*16 + bRowP) * SSTR + (ks+1)*16 + bColP) * 2);
            }
            #pragma unroll
            for (int mi = 0; mi < 4; mi++)
                #pragma unroll
                for (int n2 = 0; n2 < 2; n2++) {
                    mma_bf16(acc[mi][2*n2],   af[cur][mi], &bf[cur][n2][0]);
                    mma_bf16(acc[mi][2*n2+1], af[cur][mi], &bf[cur][n2][2]);
                }
        }
        __syncthreads();
    }
}

// ---------------------------------------------------------------------------
// 2) QKV GEMM -> Q,K ext bf16 [b][h][n][128] (smem-staged coalesced stores);
//    V hi/lo planes [b][h][d][n]
// ---------------------------------------------------------------------------
#define ESTR 136

__global__ __launch_bounds__(256, 2) void qkv_gemm(const float* __restrict__ bias) {
    int n0 = blockIdx.x * 128, m0 = blockIdx.y * 128, b = blockIdx.z;

    float acc[4][4][4];
    #pragma unroll
    for (int i = 0; i < 4; i++)
        #pragma unroll
        for (int j = 0; j < 4; j++)
            { acc[i][j][0]=0.f; acc[i][j][1]=0.f; acc[i][j][2]=0.f; acc[i][j][3]=0.f; }

    gemm_mainloop(acc,
        g_wqkv_ext + (size_t)m0 * KEXT,
        g_hn_ext + ((size_t)b * N_ + n0) * KEXT);

    extern __shared__ __nv_bfloat16 dynsm[];
    int tid = threadIdx.x, wid = tid >> 5, lane = tid & 31;
    int wm = (wid >> 2) * 64, wn = (wid & 3) * 32;
    int s = m0 >> 9;

    if (s == 2) {
        #pragma unroll
        for (int mi = 0; mi < 4; mi++) {
            #pragma unroll
            for (int half = 0; half < 2; half++) {
                int o = m0 + wm + mi*16 + (lane >> 2) + half*8;
                int rem = o & 511, h = rem >> 6, d = rem & 63;
                float bv = bias[o];
                size_t vb = (((size_t)b * NH + h) * HD + d) * N_;
                #pragma unroll
                for (int ni = 0; ni < 4; ni++) {
                    int n = n0 + wn + ni*8 + (lane & 3)*2;
                    float v0 = acc[mi][ni][half*2 + 0] + bv;
                    float v1 = acc[mi][ni][half*2 + 1] + bv;
                    uint32_t hp = packbf2(v0, v1);
                    __nv_bfloat162 hb = *(__nv_bfloat162*)&hp;
                    uint32_t lp = packbf2(v0 - __bfloat162float(hb.x),
                                          v1 - __bfloat162float(hb.y));
                    *(uint32_t*)&g_vhi[vb + n] = hp;
                    *(uint32_t*)&g_vlo[vb + n] = lp;
                }
            }
        }
    } else {
        float scl = (s == 0) ? 0.125f : 1.0f;
        #pragma unroll
        for (int mi = 0; mi < 4; mi++) {
            #pragma unroll
            for (int half = 0; half < 2; half++) {
                int o = m0 + wm + mi*16 + (lane >> 2) + half*8;
                int hp = (o >> 6) & 1, d = o & 63;
                float bv = bias[o];
                __nv_bfloat16* Eb = dynsm + hp * (128 * ESTR);
                #pragma unroll
                for (int ni = 0; ni < 4; ni++) {
                    int nloc = wn + ni*8 + (lane & 3)*2;
                    float v0 = (acc[mi][ni][half*2 + 0] + bv) * scl;
                    float v1 = (acc[mi][ni][half*2 + 1] + bv) * scl;
                    __nv_bfloat16 h0 = __float2bfloat16(v0);
                    __nv_bfloat16 h1 = __float2bfloat16(v1);
                    Eb[nloc * ESTR + d]            = h0;
                    Eb[nloc * ESTR + 64 + d]       = __float2bfloat16(v0 - __bfloat162float(h0));
                    Eb[(nloc+1) * ESTR + d]        = h1;
                    Eb[(nloc+1) * ESTR + 64 + d]   = __float2bfloat16(v1 - __bfloat162float(h1));
                }
            }
        }
        __syncthreads();
        int h0g = (m0 & 511) >> 6;
        __nv_bfloat16* outp = (s == 0 ? g_qext : g_kext);
        #pragma unroll
        for (int i = 0; i < 16; i++) {
            int f = tid + i * 256;
            int hp = f >> 11, r = f & 2047, nloc = r >> 4, seg = r & 15;
            *(uint4*)(outp + (((size_t)b * NH + h0g + hp) * N_ + n0 + nloc) * 128 + seg * 8)
                = *(uint4*)(dynsm + hp * (128 * ESTR) + nloc * ESTR + seg * 8);
        }
    }
}

// ---------------------------------------------------------------------------
// 3) HMMA flash attention: 3-ring, streamed B fragments, 2 CTA/SM.
// ---------------------------------------------------------------------------
#define QSTR 136
#define ATTN_SMEM (52224 * 2)

__global__ __launch_bounds__(256, 2) void attn_kernel() {
    extern __shared__ __nv_bfloat16 dynsm[];
    __nv_bfloat16* Qh = dynsm;
    __nv_bfloat16* Kx[3] = { dynsm + 17408, dynsm + 34816, dynsm };
    __nv_bfloat16* Vx[3] = { dynsm + 26112, dynsm + 43520, dynsm + 8704 };

    int q0 = blockIdx.x * 128;
    int bh = blockIdx.y;
    const __nv_bfloat16* qg = g_qext + (size_t)bh * N_ * 128;
    const __nv_bfloat16* kg = g_kext + (size_t)bh * N_ * 128;
    const __nv_bfloat16* vhi = g_vhi + (size_t)bh * HD * N_;
    const __nv_bfloat16* vlo = g_vlo + (size_t)bh * HD * N_;

    int tid = threadIdx.x, w = tid >> 5, lane = tid & 31;

    #pragma unroll
    for (int i = 0; i < 8; i++) {
        int idx = tid + i * 256;
        int row = idx >> 4, seg = idx & 15;
        CPA(smem_u32(&Qh[row * QSTR + seg * 8]), qg + (size_t)(q0 + row) * 128 + seg * 8);
    }
    CPCOMMIT();

    #pragma unroll
    for (int st = 0; st < 2; st++) {
        int nb = st * 64;
        #pragma unroll
        for (int i = 0; i < 4; i++) {
            int idx = tid + i * 256;
            int row = idx >> 4, seg = idx & 15;
            CPA(smem_u32(&Kx[st][row * QSTR + seg * 8]),
                kg + (size_t)(nb + row) * 128 + seg * 8);
        }
        #pragma unroll
        for (int i = 0; i < 4; i++) {
            int idx = tid + i * 256;
            int d = idx >> 4, seg = idx & 15;
            const __nv_bfloat16* src = (seg < 8 ? vhi : vlo) + (size_t)d * N_ + nb + (seg & 7) * 8;
            CPA(smem_u32(&Vx[st][d * QSTR + seg * 8]), src);
        }
        CPCOMMIT();
    }

    CPWAIT(2);
    __syncthreads();
    uint32_t qbase = smem_u32(Qh);
    int ar = w * 16 + (lane & 15);
    int ac = (lane >> 4) * 8;
    uint32_t qh[4][4], ql[4][4];
    #pragma unroll
    for (int ks = 0; ks < 4; ks++) {
        ldsm_x4(qh[ks], qbase + (ar * QSTR + ks * 16 + ac) * 2);
        ldsm_x4(ql[ks], qbase + (ar * QSTR + 64 + ks * 16 + ac) * 2);
    }
    __syncthreads();

    float oacc[8][4];
    #pragma unroll
    for (int i = 0; i < 8; i++)
        { oacc[i][0]=0.f; oacc[i][1]=0.f; oacc[i][2]=0.f; oacc[i][3]=0.f; }
    float m0 = -1e30f, m1 = -1e30f, l0 = 0.f, l1 = 0.f;

    int bRowP = (lane & 7) + ((lane >> 4) * 8);
    int bColP = ((lane >> 3) & 1) * 8;

    #pragma unroll 1
    for (int ch = 0; ch < 16; ch++) {
        if (ch < 14) CPWAIT(1); else CPWAIT(0);
        __syncthreads();

        if (ch + 2 < 16) {
            int st = (ch + 2) % 3, nb = (ch + 2) * 64;
            #pragma unroll
            for (int i = 0; i < 4; i++) {
                int idx = tid + i * 256;
                int row = idx >> 4, seg = idx & 15;
                CPA(smem_u32(&Kx[st][row * QSTR + seg * 8]),
                    kg + (size_t)(nb + row) * 128 + seg * 8);
            }
            #pragma unroll
            for (int i = 0; i < 4; i++) {
                int idx = tid + i * 256;
                int d = idx >> 4, seg = idx & 15;
                const __nv_bfloat16* src = (seg < 8 ? vhi : vlo) + (size_t)d * N_ + nb + (seg & 7) * 8;
                CPA(smem_u32(&Vx[st][d * QSTR + seg * 8]), src);
            }
            CPCOMMIT();
        }

        uint32_t kbase = smem_u32(Kx[ch % 3]);
        uint32_t vbase = smem_u32(Vx[ch % 3]);

        // ---- S = Q_ext . K_ext^T (streamed kb; khi applied to qh AND ql) ----
        float sacc[8][4];
        #pragma unroll
        for (int i = 0; i < 8; i++)
            { sacc[i][0]=0.f; sacc[i][1]=0.f; sacc[i][2]=0.f; sacc[i][3]=0.f; }

        #pragma unroll
        for (int n2 = 0; n2 < 4; n2++) {
            #pragma unroll
            for (int ks = 0; ks < 4; ks++) {
                uint32_t kb[4];
                ldsm_x4(kb, kbase + ((n2*16 + bRowP) * QSTR + ks*16 + bColP) * 2);
                mma_bf16(sacc[2*n2],   qh[ks], &kb[0]);
                mma_bf16(sacc[2*n2+1], qh[ks], &kb[2]);
                mma_bf16(sacc[2*n2],   ql[ks], &kb[0]);
                mma_bf16(sacc[2*n2+1], ql[ks], &kb[2]);
            }
            #pragma unroll
            for (int ks = 0; ks < 4; ks++) {
                uint32_t kb[4];
                ldsm_x4(kb, kbase + ((n2*16 + bRowP) * QSTR + 64 + ks*16 + bColP) * 2);
                mma_bf16(sacc[2*n2],   qh[ks], &kb[0]);
                mma_bf16(sacc[2*n2+1], qh[ks], &kb[2]);
            }
        }

        // ---- online softmax ----
        float mx0 = -1e30f, mx1 = -1e30f;
        #pragma unroll
        for (int nf = 0; nf < 8; nf++) {
            mx0 = fmaxf(mx0, fmaxf(sacc[nf][0], sacc[nf][1]));
            mx1 = fmaxf(mx1, fmaxf(sacc[nf][2], sacc[nf][3]));
        }
        mx0 = fmaxf(mx0, __shfl_xor_sync(0xffffffffu, mx0, 1));
        mx0 = fmaxf(mx0, __shfl_xor_sync(0xffffffffu, mx0, 2));
        mx1 = fmaxf(mx1, __shfl_xor_sync(0xffffffffu, mx1, 1));
        mx1 = fmaxf(mx1, __shfl_xor_sync(0xffffffffu, mx1, 2));
        float mn0 = fmaxf(m0, mx0), mn1 = fmaxf(m1, mx1);
        float f0 = ex2((m0 - mn0) * LOG2E), f1 = ex2((m1 - mn1) * LOG2E);

        float rs0 = 0.f, rs1 = 0.f;
        #pragma unroll
        for (int nf = 0; nf < 8; nf++) {
            sacc[nf][0] = ex2((sacc[nf][0] - mn0) * LOG2E);
            sacc[nf][1] = ex2((sacc[nf][1] - mn0) * LOG2E);
            sacc[nf][2] = ex2((sacc[nf][2] - mn1) * LOG2E);
            sacc[nf][3] = ex2((sacc[nf][3] - mn1) * LOG2E);
            rs0 += sacc[nf][0] + sacc[nf][1];
            rs1 += sacc[nf][2] + sacc[nf][3];
        }
        rs0 += __shfl_xor_sync(0xffffffffu, rs0, 1);
        rs0 += __shfl_xor_sync(0xffffffffu, rs0, 2);
        rs1 += __shfl_xor_sync(0xffffffffu, rs1, 1);
        rs1 += __shfl_xor_sync(0xffffffffu, rs1, 2);
        l0 = l0 * f0 + rs0; l1 = l1 * f1 + rs1;
        m0 = mn0; m1 = mn1;
        #pragma unroll
        for (int df = 0; df < 8; df++) {
            oacc[df][0] *= f0; oacc[df][1] *= f0;
            oacc[df][2] *= f1; oacc[df][3] *= f1;
        }

        // ---- P -> A fragments (hi & lo) ----
        uint32_t phi[4][4], plo[4][4];
        #pragma unroll
        for (int ks = 0; ks < 4; ks++) {
            int j = 2 * ks;
            float p00 = sacc[j][0],   p01 = sacc[j][1];
            float p02 = sacc[j][2],   p03 = sacc[j][3];
            float p10 = sacc[j+1][0], p11 = sacc[j+1][1];
            float p12 = sacc[j+1][2], p13 = sacc[j+1][3];
            phi[ks][0] = packbf2(p00, p01);
            phi[ks][1] = packbf2(p02, p03);
            phi[ks][2] = packbf2(p10, p11);
            phi[ks][3] = packbf2(p12, p13);
            __nv_bfloat162* hp;
            hp = (__nv_bfloat162*)&phi[ks][0];
            plo[ks][0] = packbf2(p00 - __bfloat162float(hp->x), p01 - __bfloat162float(hp->y));
            hp = (__nv_bfloat162*)&phi[ks][1];
            plo[ks][1] = packbf2(p02 - __bfloat162float(hp->x), p03 - __bfloat162float(hp->y));
            hp = (__nv_bfloat162*)&phi[ks][2];
            plo[ks][2] = packbf2(p10 - __bfloat162float(hp->x), p11 - __bfloat162float(hp->y));
            hp = (__nv_bfloat162*)&phi[ks][3];
            plo[ks][3] = packbf2(p12 - __bfloat162float(hp->x), p13 - __bfloat162float(hp->y));
        }

        // ---- O += P_ext . V_ext (streamed vb; vhi applied to phi AND plo) ----
        #pragma unroll
        for (int d2 = 0; d2 < 4; d2++) {
            #pragma unroll
            for (int ks = 0; ks < 4; ks++) {
                uint32_t vb[4];
                ldsm_x4(vb, vbase + ((d2*16 + bRowP) * QSTR + ks*16 + bColP) * 2);
                mma_bf16(oacc[2*d2],   phi[ks], &vb[0]);
                mma_bf16(oacc[2*d2+1], phi[ks], &vb[2]);
                mma_bf16(oacc[2*d2],   plo[ks], &vb[0]);
                mma_bf16(oacc[2*d2+1], plo[ks], &vb[2]);
            }
            #pragma unroll
            for (int ks = 0; ks < 4; ks++) {
                uint32_t vb[4];
                ldsm_x4(vb, vbase + ((d2*16 + bRowP) * QSTR + 64 + ks*16 + bColP) * 2);
                mma_bf16(oacc[2*d2],   phi[ks], &vb[0]);
                mma_bf16(oacc[2*d2+1], phi[ks], &vb[2]);
            }
        }
    }

    // ---- epilogue ----
    float inv0 = 1.f / l0, inv1 = 1.f / l1;
    int b = bh >> 3, h = bh & 7;
    int row0 = q0 + w * 16 + (lane >> 2);
    #pragma unroll
    for (int df = 0; df < 8; df++) {
        int chn = h * HD + df * 8 + (lane & 3) * 2;
        #pragma unroll
        for (int r = 0; r < 2; r++) {
            int row = row0 + r * 8;
            float v0 = oacc[df][r*2 + 0] * (r ? inv1 : inv0);
            float v1 = oacc[df][r*2 + 1] * (r ? inv1 : inv0);
            uint32_t hp = packbf2(v0, v1);
            __nv_bfloat162 hb = *(__nv_bfloat162*)&hp;
            uint32_t lp = packbf2(v0 - __bfloat162float(hb.x), v1 - __bfloat162float(hb.y));
            size_t eb = ((size_t)b * N_ + row) * KEXT + chn;
            *(uint32_t*)&g_obuf_ext[eb]          = hp;
            *(uint32_t*)&g_obuf_ext[eb + C_]     = hp;
            *(uint32_t*)&g_obuf_ext[eb + 2*C_]   = lp;
        }
    }
}

// ---------------------------------------------------------------------------
// 4) Proj GEMM + bias + residual -> out[b][c][n]
// ---------------------------------------------------------------------------
__global__ __launch_bounds__(256, 2) void proj_gemm(const float* __restrict__ bias,
                                                    const float* __restrict__ x,
                                                    float* __restrict__ out) {
    int n0 = blockIdx.x * 128, m0 = blockIdx.y * 128, b = blockIdx.z;

    float acc[4][4][4];
    #pragma unroll
    for (int i = 0; i < 4; i++)
        #pragma unroll
        for (int j = 0; j < 4; j++)
            { acc[i][j][0]=0.f; acc[i][j][1]=0.f; acc[i][j][2]=0.f; acc[i][j][3]=0.f; }

    gemm_mainloop(acc,
        g_wproj_ext + (size_t)m0 * KEXT,
        g_obuf_ext + ((size_t)b * N_ + n0) * KEXT);

    int wid = threadIdx.x >> 5, lane = threadIdx.x & 31;
    int wm = (wid >> 2) * 64, wn = (wid & 3) * 32;

    #pragma unroll
    for (int mi = 0; mi < 4; mi++) {
        #pragma unroll
        for (int half = 0; half < 2; half++) {
            int chn = m0 + wm + mi*16 + (lane >> 2) + half*8;
            float bv = bias[chn];
            size_t rowbase = ((size_t)b * C_ + chn) * N_;
            #pragma unroll
            for (int ni = 0; ni < 4; ni++) {
                int n = n0 + wn + ni*8 + (lane & 3)*2;
                float2 xv = *(const float2*)&x[rowbase + n];
                float2 v;
                v.x = acc[mi][ni][half*2 + 0] + bv + xv.x;
                v.y = acc[mi][ni][half*2 + 1] + bv + xv.y;
                *(float2*)&out[rowbase + n] = v;
            }
        }
    }
}

// ---------------------------------------------------------------------------
extern "C" void kernel_launch(void* const* d_in, const int* in_sizes, int n_in,
                              void* d_out, int out_size) {
    const float* x      = (const float*)d_in[0];
    const float* norm_w = (const float*)d_in[1];
    const float* norm_b = (const float*)d_in[2];
    const float* qkv_w  = (const float*)d_in[3];
    const float* qkv_b  = (const float*)d_in[4];
    const float* proj_w = (const float*)d_in[5];
    const float* proj_b = (const float*)d_in[6];
    float* out = (float*)d_out;

    cudaFuncSetAttribute(gn_kernel, cudaFuncAttributeMaxDynamicSharedMemorySize, 65536);
    cudaFuncSetAttribute(qkv_gemm, cudaFuncAttributeMaxDynamicSharedMemorySize, GEMM_SMEM);
    cudaFuncSetAttribute(proj_gemm, cudaFuncAttributeMaxDynamicSharedMemorySize, GEMM_SMEM);
    cudaFuncSetAttribute(attn_kernel, cudaFuncAttributeMaxDynamicSharedMemorySize, ATTN_SMEM);

    __nv_bfloat16 *wq, *wp;
    cudaGetSymbolAddress((void**)&wq, g_wqkv_ext);
    cudaGetSymbolAddress((void**)&wp, g_wproj_ext);

    convw_kernel<<<3 * C_, 128>>>(qkv_w, wq);
    convw_kernel<<<C_, 128>>>(proj_w, wp);
    gn_kernel<<<B_ * G_, 256, 65536>>>(x, norm_w, norm_b);
    qkv_gemm<<<dim3(N_ / 128, (3 * C_) / 128, B_), 256, GEMM_SMEM>>>(qkv_b);
    attn_kernel<<<dim3(N_ / 128, B_ * NH), 256, ATTN_SMEM>>>();
    proj_gemm<<<dim3(N_ / 128, C_ / 128, B_), 256, GEMM_SMEM>>>(proj_b, x, out);
}

// round 9
// speedup vs baseline: 4.8525x; 1.0395x over previous
#include <cuda_runtime.h>
#include <cuda_bf16.h>
#include <cstdint>

#define B_   16
#define C_   512
#define NH   8
#define HD   64
#define N_   1024
#define G_   32
#define CPG  16
#define EPSV 1e-5f
#define LOG2E 1.4426950408889634f

// ---------------- scratch (device globals; no allocation allowed) -----------
__device__ __nv_bfloat16 g_qext[(size_t)B_ * NH * N_ * 128];   // [b][h][n][hi64|lo64], pre-scaled
__device__ __nv_bfloat16 g_kext[(size_t)B_ * NH * N_ * 128];   // [b][h][n][hi64|lo64]
__device__ __nv_bfloat16 g_vhi[(size_t)B_ * NH * HD * N_];     // [b][h][d][n]
__device__ __nv_bfloat16 g_vlo[(size_t)B_ * NH * HD * N_];
__device__ __nv_bfloat16 g_hn[(size_t)B_ * N_ * 1024];         // [b][n][hi512|lo512]
__device__ __nv_bfloat16 g_obuf[(size_t)B_ * N_ * 1024];       // [b][n][hi512|lo512]
__device__ __nv_bfloat16 g_wqkv[(size_t)(3*C_) * 1024];        // [o][hi512|lo512]
__device__ __nv_bfloat16 g_wproj[(size_t)C_ * 1024];           // [o][hi512|lo512]

// ---------------- PTX helpers (baseline-safe for compute_103) ---------------
__device__ __forceinline__ uint32_t smem_u32(const void* p) {
    uint32_t a;
    asm("{ .reg .u64 t; cvta.to.shared.u64 t, %1; cvt.u32.u64 %0, t; }" : "=r"(a) : "l"(p));
    return a;
}
__device__ __forceinline__ void ldsm_x4(uint32_t* r, uint32_t addr) {
    asm volatile("ldmatrix.sync.aligned.m8n8.x4.shared.b16 {%0,%1,%2,%3}, [%4];"
                 : "=r"(r[0]), "=r"(r[1]), "=r"(r[2]), "=r"(r[3]) : "r"(addr));
}
__device__ __forceinline__ void mma_bf16(float* c, const uint32_t* a, const uint32_t* b) {
    asm volatile("mma.sync.aligned.m16n8k16.row.col.f32.bf16.bf16.f32 "
                 "{%0,%1,%2,%3}, {%4,%5,%6,%7}, {%8,%9}, {%0,%1,%2,%3};"
                 : "+f"(c[0]), "+f"(c[1]), "+f"(c[2]), "+f"(c[3])
                 : "r"(a[0]), "r"(a[1]), "r"(a[2]), "r"(a[3]), "r"(b[0]), "r"(b[1]));
}
__device__ __forceinline__ float ex2(float x) {
    float r; asm("ex2.approx.f32 %0, %1;" : "=f"(r) : "f"(x)); return r;
}
__device__ __forceinline__ uint32_t packbf2(float a, float b) {
    __nv_bfloat162 t; t.x = __float2bfloat16(a); t.y = __float2bfloat16(b);
    return *(uint32_t*)&t;
}
#define CPA(dst, src) \
    asm volatile("cp.async.cg.shared.global [%0], [%1], 16;" :: "r"(dst), "l"(src))
#define CPCOMMIT() asm volatile("cp.async.commit_group;")
#define CPWAIT(n)  asm volatile("cp.async.wait_group %0;" :: "n"(n))

// ---------------------------------------------------------------------------
// 0) Weight split: w[o][c] fp32 -> 2-plane [o][hi512|lo512]
// ---------------------------------------------------------------------------
__global__ void convw_kernel(const float* __restrict__ wq, const float* __restrict__ wp) {
    int r = blockIdx.x;
    const float* src = (r < 3*C_) ? wq + (size_t)r * C_ : wp + (size_t)(r - 3*C_) * C_;
    __nv_bfloat16* dst = (r < 3*C_) ? g_wqkv + (size_t)r * 1024
                                    : g_wproj + (size_t)(r - 3*C_) * 1024;
    for (int c = threadIdx.x; c < C_; c += 128) {
        float v = src[c];
        __nv_bfloat16 hi = __float2bfloat16(v);
        dst[c]       = hi;
        dst[512 + c] = __float2bfloat16(v - __bfloat162float(hi));
    }
}

// ---------------------------------------------------------------------------
// 1) GroupNorm + transpose + bf16 split -> g_hn [b][n][hi512|lo512]
//    No data staging: phase 2 re-reads x from L2. Thread handles 4 consecutive n.
// ---------------------------------------------------------------------------
__global__ __launch_bounds__(256) void gn_kernel(const float* __restrict__ x,
                                                 const float* __restrict__ w,
                                                 const float* __restrict__ bb) {
    int bg = blockIdx.x;
    int g = bg & (G_ - 1), b = bg >> 5;
    const float4* x4 = (const float4*)(x + (size_t)bg * CPG * N_);
    int tid = threadIdx.x;

    float s = 0.f, s2 = 0.f;
    #pragma unroll
    for (int i = 0; i < 16; i++) {
        float4 v = x4[tid + i * 256];
        s  += v.x + v.y + v.z + v.w;
        s2 += v.x*v.x + v.y*v.y + v.z*v.z + v.w*v.w;
    }
    __shared__ float rs[256], rs2[256];
    rs[tid] = s; rs2[tid] = s2;
    __syncthreads();
    for (int off = 128; off > 0; off >>= 1) {
        if (tid < off) { rs[tid] += rs[tid+off]; rs2[tid] += rs2[tid+off]; }
        __syncthreads();
    }
    float mean = rs[0] * (1.f/16384.f);
    float var  = rs2[0] * (1.f/16384.f) - mean*mean;
    float rstd = rsqrtf(var + EPSV);

    float sc[CPG], sh[CPG];
    #pragma unroll
    for (int c16 = 0; c16 < CPG; c16++) {
        int c = g*CPG + c16;
        sc[c16] = rstd * w[c];
        sh[c16] = bb[c] - mean * sc[c16];
    }

    // phase 2: thread -> 4 consecutive n (float4 per channel row, L2 hit)
    float4 vals[CPG];
    #pragma unroll
    for (int c16 = 0; c16 < CPG; c16++) {
        float4 v = x4[c16 * 256 + tid];
        vals[c16].x = v.x*sc[c16]+sh[c16]; vals[c16].y = v.y*sc[c16]+sh[c16];
        vals[c16].z = v.z*sc[c16]+sh[c16]; vals[c16].w = v.w*sc[c16]+sh[c16];
    }
    union Pack { __nv_bfloat16 h[CPG]; uint4 v[2]; };
    #pragma unroll
    for (int j = 0; j < 4; j++) {
        Pack hiP, loP;
        #pragma unroll
        for (int c16 = 0; c16 < CPG; c16++) {
            float v = j == 0 ? vals[c16].x : j == 1 ? vals[c16].y
                    : j == 2 ? vals[c16].z : vals[c16].w;
            __nv_bfloat16 hv = __float2bfloat16(v);
            hiP.h[c16] = hv;
            loP.h[c16] = __float2bfloat16(v - __bfloat162float(hv));
        }
        __nv_bfloat16* dst = g_hn + ((size_t)b * N_ + tid*4 + j) * 1024 + g * CPG;
        *(uint4*)(dst)         = hiP.v[0]; *(uint4*)(dst + 8)         = hiP.v[1];
        *(uint4*)(dst + 512)   = loP.v[0]; *(uint4*)(dst + 512 + 8)   = loP.v[1];
    }
}

// ---------------------------------------------------------------------------
// HMMA GEMM mainloop: 2-stage cp.async + fragment double-buffer.
// 24 virtual chunks of 64 over 2-plane storage:
//   A (weights, hi|lo): chunks 0-7 hi, 8-15 lo, 16-23 hi
//   B (acts,   hi|lo): chunks 0-7 hi, 8-15 hi (re-read), 16-23 lo
// ---------------------------------------------------------------------------
#define SSTR 88
#define STAGE_U (2 * 128 * SSTR)
#define GEMM_SMEM (2 * STAGE_U * 2)        // 90112 B
#define NCHUNK 24

__device__ __forceinline__ int kmapA(int c) {
    return (c < 8) ? c*64 : (c < 16) ? 512 + (c-8)*64 : (c-16)*64;
}
__device__ __forceinline__ int kmapB(int c) {
    return (c < 8) ? c*64 : (c < 16) ? (c-8)*64 : 512 + (c-16)*64;
}

__device__ __forceinline__ void gemm_issue(__nv_bfloat16* As, __nv_bfloat16* Bs,
                                           const __nv_bfloat16* Abase,
                                           const __nv_bfloat16* Bbase,
                                           int c, int ldRow, int ldSeg) {
    int kA = kmapA(c), kB = kmapB(c);
    #pragma unroll
    for (int rr = 0; rr < 4; rr++) {
        int row = ldRow + rr * 32;
        CPA(smem_u32(&As[row * SSTR + ldSeg * 8]),
            Abase + (size_t)row * 1024 + kA + ldSeg * 8);
        CPA(smem_u32(&Bs[row * SSTR + ldSeg * 8]),
            Bbase + (size_t)row * 1024 + kB + ldSeg * 8);
    }
    CPCOMMIT();
}

__device__ __forceinline__ void gemm_mainloop(float acc[4][4][4],
                                              const __nv_bfloat16* __restrict__ Abase,
                                              const __nv_bfloat16* __restrict__ Bbase) {
    extern __shared__ __nv_bfloat16 dynsm[];
    __nv_bfloat16* As[2] = { dynsm, dynsm + STAGE_U };
    __nv_bfloat16* Bs[2] = { dynsm + 128*SSTR, dynsm + STAGE_U + 128*SSTR };

    int tid = threadIdx.x, wid = tid >> 5, lane = tid & 31;
    int wm = (wid >> 2) * 64;
    int wn = (wid & 3) * 32;
    int aRow = wm + (lane & 15), aCol = (lane >> 4) * 8;
    int bRowP = (lane & 7) + ((lane >> 4) * 8);
    int bColP = ((lane >> 3) & 1) * 8;
    int ldRow = tid >> 3;
    int ldSeg = tid & 7;

    gemm_issue(As[0], Bs[0], Abase, Bbase, 0, ldRow, ldSeg);

    #pragma unroll 1
    for (int c = 0; c < NCHUNK; c++) {
        if (c + 1 < NCHUNK) {
            gemm_issue(As[(c+1)&1], Bs[(c+1)&1], Abase, Bbase, c+1, ldRow, ldSeg);
            CPWAIT(1);
        } else {
            CPWAIT(0);
        }
        __syncthreads();

        uint32_t smA = smem_u32(As[c&1]), smB = smem_u32(Bs[c&1]);
        uint32_t af[2][4][4], bf[2][2][4];
        #pragma unroll
        for (int mi = 0; mi < 4; mi++)
            ldsm_x4(af[0][mi], smA + ((aRow + mi*16) * SSTR + aCol) * 2);
        #pragma unroll
        for (int n2 = 0; n2 < 2; n2++)
            ldsm_x4(bf[0][n2], smB + ((wn + n2*16 + bRowP) * SSTR + bColP) * 2);

        #pragma unroll
        for (int ks = 0; ks < 4; ks++) {
            int cur = ks & 1, nxt = cur ^ 1;
            if (ks < 3) {
                #pragma unroll
                for (int mi = 0; mi < 4; mi++)
                    ldsm_x4(af[nxt][mi], smA + ((aRow + mi*16) * SSTR + (ks+1)*16 + aCol) * 2);
                #pragma unroll
                for (int n2 = 0; n2 < 2; n2++)
                    ldsm_x4(bf[nxt][n2], smB + ((wn + n2*16 + bRowP) * SSTR + (ks+1)*16 + bColP) * 2);
            }
            #pragma unroll
            for (int mi = 0; mi < 4; mi++)
                #pragma unroll
                for (int n2 = 0; n2 < 2; n2++) {
                    mma_bf16(acc[mi][2*n2],   af[cur][mi], &bf[cur][n2][0]);
                    mma_bf16(acc[mi][2*n2+1], af[cur][mi], &bf[cur][n2][2]);
                }
        }
        __syncthreads();
    }
}

// ---------------------------------------------------------------------------
// 2) QKV GEMM -> Q,K ext bf16 [b][h][n][128] (smem-staged coalesced stores);
//    V hi/lo planes [b][h][d][n]
// ---------------------------------------------------------------------------
#define ESTR 136

__global__ __launch_bounds__(256, 2) void qkv_gemm(const float* __restrict__ bias) {
    int n0 = blockIdx.x * 128, m0 = blockIdx.y * 128, b = blockIdx.z;

    float acc[4][4][4];
    #pragma unroll
    for (int i = 0; i < 4; i++)
        #pragma unroll
        for (int j = 0; j < 4; j++)
            { acc[i][j][0]=0.f; acc[i][j][1]=0.f; acc[i][j][2]=0.f; acc[i][j][3]=0.f; }

    gemm_mainloop(acc,
        g_wqkv + (size_t)m0 * 1024,
        g_hn + ((size_t)b * N_ + n0) * 1024);

    extern __shared__ __nv_bfloat16 dynsm[];
    int tid = threadIdx.x, wid = tid >> 5, lane = tid & 31;
    int wm = (wid >> 2) * 64, wn = (wid & 3) * 32;
    int s = m0 >> 9;

    if (s == 2) {
        #pragma unroll
        for (int mi = 0; mi < 4; mi++) {
            #pragma unroll
            for (int half = 0; half < 2; half++) {
                int o = m0 + wm + mi*16 + (lane >> 2) + half*8;
                int rem = o & 511, h = rem >> 6, d = rem & 63;
                float bv = bias[o];
                size_t vb = (((size_t)b * NH + h) * HD + d) * N_;
                #pragma unroll
                for (int ni = 0; ni < 4; ni++) {
                    int n = n0 + wn + ni*8 + (lane & 3)*2;
                    float v0 = acc[mi][ni][half*2 + 0] + bv;
                    float v1 = acc[mi][ni][half*2 + 1] + bv;
                    uint32_t hp = packbf2(v0, v1);
                    __nv_bfloat162 hb = *(__nv_bfloat162*)&hp;
                    uint32_t lp = packbf2(v0 - __bfloat162float(hb.x),
                                          v1 - __bfloat162float(hb.y));
                    *(uint32_t*)&g_vhi[vb + n] = hp;
                    *(uint32_t*)&g_vlo[vb + n] = lp;
                }
            }
        }
    } else {
        float scl = (s == 0) ? 0.125f : 1.0f;
        #pragma unroll
        for (int mi = 0; mi < 4; mi++) {
            #pragma unroll
            for (int half = 0; half < 2; half++) {
                int o = m0 + wm + mi*16 + (lane >> 2) + half*8;
                int hp = (o >> 6) & 1, d = o & 63;
                float bv = bias[o];
                __nv_bfloat16* Eb = dynsm + hp * (128 * ESTR);
                #pragma unroll
                for (int ni = 0; ni < 4; ni++) {
                    int nloc = wn + ni*8 + (lane & 3)*2;
                    float v0 = (acc[mi][ni][half*2 + 0] + bv) * scl;
                    float v1 = (acc[mi][ni][half*2 + 1] + bv) * scl;
                    __nv_bfloat16 h0 = __float2bfloat16(v0);
                    __nv_bfloat16 h1 = __float2bfloat16(v1);
                    Eb[nloc * ESTR + d]            = h0;
                    Eb[nloc * ESTR + 64 + d]       = __float2bfloat16(v0 - __bfloat162float(h0));
                    Eb[(nloc+1) * ESTR + d]        = h1;
                    Eb[(nloc+1) * ESTR + 64 + d]   = __float2bfloat16(v1 - __bfloat162float(h1));
                }
            }
        }
        __syncthreads();
        int h0g = (m0 & 511) >> 6;
        __nv_bfloat16* outp = (s == 0 ? g_qext : g_kext);
        #pragma unroll
        for (int i = 0; i < 16; i++) {
            int f = tid + i * 256;
            int hp = f >> 11, r = f & 2047, nloc = r >> 4, seg = r & 15;
            *(uint4*)(outp + (((size_t)b * NH + h0g + hp) * N_ + n0 + nloc) * 128 + seg * 8)
                = *(uint4*)(dynsm + hp * (128 * ESTR) + nloc * ESTR + seg * 8);
        }
    }
}

// ---------------------------------------------------------------------------
// 3) HMMA flash attention: 3-ring, streamed B fragments, 2 CTA/SM.
// ---------------------------------------------------------------------------
#define QSTR 136
#define ATTN_SMEM (52224 * 2)

__global__ __launch_bounds__(256, 2) void attn_kernel() {
    extern __shared__ __nv_bfloat16 dynsm[];
    __nv_bfloat16* Qh = dynsm;
    __nv_bfloat16* Kx[3] = { dynsm + 17408, dynsm + 34816, dynsm };
    __nv_bfloat16* Vx[3] = { dynsm + 26112, dynsm + 43520, dynsm + 8704 };

    int q0 = blockIdx.x * 128;
    int bh = blockIdx.y;
    const __nv_bfloat16* qg = g_qext + (size_t)bh * N_ * 128;
    const __nv_bfloat16* kg = g_kext + (size_t)bh * N_ * 128;
    const __nv_bfloat16* vhi = g_vhi + (size_t)bh * HD * N_;
    const __nv_bfloat16* vlo = g_vlo + (size_t)bh * HD * N_;

    int tid = threadIdx.x, w = tid >> 5, lane = tid & 31;

    #pragma unroll
    for (int i = 0; i < 8; i++) {
        int idx = tid + i * 256;
        int row = idx >> 4, seg = idx & 15;
        CPA(smem_u32(&Qh[row * QSTR + seg * 8]), qg + (size_t)(q0 + row) * 128 + seg * 8);
    }
    CPCOMMIT();

    #pragma unroll
    for (int st = 0; st < 2; st++) {
        int nb = st * 64;
        #pragma unroll
        for (int i = 0; i < 4; i++) {
            int idx = tid + i * 256;
            int row = idx >> 4, seg = idx & 15;
            CPA(smem_u32(&Kx[st][row * QSTR + seg * 8]),
                kg + (size_t)(nb + row) * 128 + seg * 8);
        }
        #pragma unroll
        for (int i = 0; i < 4; i++) {
            int idx = tid + i * 256;
            int d = idx >> 4, seg = idx & 15;
            const __nv_bfloat16* src = (seg < 8 ? vhi : vlo) + (size_t)d * N_ + nb + (seg & 7) * 8;
            CPA(smem_u32(&Vx[st][d * QSTR + seg * 8]), src);
        }
        CPCOMMIT();
    }

    CPWAIT(2);
    __syncthreads();
    uint32_t qbase = smem_u32(Qh);
    int ar = w * 16 + (lane & 15);
    int ac = (lane >> 4) * 8;
    uint32_t qh[4][4], ql[4][4];
    #pragma unroll
    for (int ks = 0; ks < 4; ks++) {
        ldsm_x4(qh[ks], qbase + (ar * QSTR + ks * 16 + ac) * 2);
        ldsm_x4(ql[ks], qbase + (ar * QSTR + 64 + ks * 16 + ac) * 2);
    }
    __syncthreads();

    float oacc[8][4];
    #pragma unroll
    for (int i = 0; i < 8; i++)
        { oacc[i][0]=0.f; oacc[i][1]=0.f; oacc[i][2]=0.f; oacc[i][3]=0.f; }
    float m0 = -1e30f, m1 = -1e30f, l0 = 0.f, l1 = 0.f;

    int bRowP = (lane & 7) + ((lane >> 4) * 8);
    int bColP = ((lane >> 3) & 1) * 8;

    #pragma unroll 1
    for (int ch = 0; ch < 16; ch++) {
        if (ch < 14) CPWAIT(1); else CPWAIT(0);
        __syncthreads();

        if (ch + 2 < 16) {
            int st = (ch + 2) % 3, nb = (ch + 2) * 64;
            #pragma unroll
            for (int i = 0; i < 4; i++) {
                int idx = tid + i * 256;
                int row = idx >> 4, seg = idx & 15;
                CPA(smem_u32(&Kx[st][row * QSTR + seg * 8]),
                    kg + (size_t)(nb + row) * 128 + seg * 8);
            }
            #pragma unroll
            for (int i = 0; i < 4; i++) {
                int idx = tid + i * 256;
                int d = idx >> 4, seg = idx & 15;
                const __nv_bfloat16* src = (seg < 8 ? vhi : vlo) + (size_t)d * N_ + nb + (seg & 7) * 8;
                CPA(smem_u32(&Vx[st][d * QSTR + seg * 8]), src);
            }
            CPCOMMIT();
        }

        uint32_t kbase = smem_u32(Kx[ch % 3]);
        uint32_t vbase = smem_u32(Vx[ch % 3]);

        float sacc[8][4];
        #pragma unroll
        for (int i = 0; i < 8; i++)
            { sacc[i][0]=0.f; sacc[i][1]=0.f; sacc[i][2]=0.f; sacc[i][3]=0.f; }

        #pragma unroll
        for (int n2 = 0; n2 < 4; n2++) {
            #pragma unroll
            for (int ks = 0; ks < 4; ks++) {
                uint32_t kb[4];
                ldsm_x4(kb, kbase + ((n2*16 + bRowP) * QSTR + ks*16 + bColP) * 2);
                mma_bf16(sacc[2*n2],   qh[ks], &kb[0]);
                mma_bf16(sacc[2*n2+1], qh[ks], &kb[2]);
                mma_bf16(sacc[2*n2],   ql[ks], &kb[0]);
                mma_bf16(sacc[2*n2+1], ql[ks], &kb[2]);
            }
            #pragma unroll
            for (int ks = 0; ks < 4; ks++) {
                uint32_t kb[4];
                ldsm_x4(kb, kbase + ((n2*16 + bRowP) * QSTR + 64 + ks*16 + bColP) * 2);
                mma_bf16(sacc[2*n2],   qh[ks], &kb[0]);
                mma_bf16(sacc[2*n2+1], qh[ks], &kb[2]);
            }
        }

        float mx0 = -1e30f, mx1 = -1e30f;
        #pragma unroll
        for (int nf = 0; nf < 8; nf++) {
            mx0 = fmaxf(mx0, fmaxf(sacc[nf][0], sacc[nf][1]));
            mx1 = fmaxf(mx1, fmaxf(sacc[nf][2], sacc[nf][3]));
        }
        mx0 = fmaxf(mx0, __shfl_xor_sync(0xffffffffu, mx0, 1));
        mx0 = fmaxf(mx0, __shfl_xor_sync(0xffffffffu, mx0, 2));
        mx1 = fmaxf(mx1, __shfl_xor_sync(0xffffffffu, mx1, 1));
        mx1 = fmaxf(mx1, __shfl_xor_sync(0xffffffffu, mx1, 2));
        float mn0 = fmaxf(m0, mx0), mn1 = fmaxf(m1, mx1);
        float f0 = ex2((m0 - mn0) * LOG2E), f1 = ex2((m1 - mn1) * LOG2E);

        float rs0 = 0.f, rs1 = 0.f;
        #pragma unroll
        for (int nf = 0; nf < 8; nf++) {
            sacc[nf][0] = ex2((sacc[nf][0] - mn0) * LOG2E);
            sacc[nf][1] = ex2((sacc[nf][1] - mn0) * LOG2E);
            sacc[nf][2] = ex2((sacc[nf][2] - mn1) * LOG2E);
            sacc[nf][3] = ex2((sacc[nf][3] - mn1) * LOG2E);
            rs0 += sacc[nf][0] + sacc[nf][1];
            rs1 += sacc[nf][2] + sacc[nf][3];
        }
        rs0 += __shfl_xor_sync(0xffffffffu, rs0, 1);
        rs0 += __shfl_xor_sync(0xffffffffu, rs0, 2);
        rs1 += __shfl_xor_sync(0xffffffffu, rs1, 1);
        rs1 += __shfl_xor_sync(0xffffffffu, rs1, 2);
        l0 = l0 * f0 + rs0; l1 = l1 * f1 + rs1;
        m0 = mn0; m1 = mn1;
        #pragma unroll
        for (int df = 0; df < 8; df++) {
            oacc[df][0] *= f0; oacc[df][1] *= f0;
            oacc[df][2] *= f1; oacc[df][3] *= f1;
        }

        uint32_t phi[4][4], plo[4][4];
        #pragma unroll
        for (int ks = 0; ks < 4; ks++) {
            int j = 2 * ks;
            float p00 = sacc[j][0],   p01 = sacc[j][1];
            float p02 = sacc[j][2],   p03 = sacc[j][3];
            float p10 = sacc[j+1][0], p11 = sacc[j+1][1];
            float p12 = sacc[j+1][2], p13 = sacc[j+1][3];
            phi[ks][0] = packbf2(p00, p01);
            phi[ks][1] = packbf2(p02, p03);
            phi[ks][2] = packbf2(p10, p11);
            phi[ks][3] = packbf2(p12, p13);
            __nv_bfloat162* hp;
            hp = (__nv_bfloat162*)&phi[ks][0];
            plo[ks][0] = packbf2(p00 - __bfloat162float(hp->x), p01 - __bfloat162float(hp->y));
            hp = (__nv_bfloat162*)&phi[ks][1];
            plo[ks][1] = packbf2(p02 - __bfloat162float(hp->x), p03 - __bfloat162float(hp->y));
            hp = (__nv_bfloat162*)&phi[ks][2];
            plo[ks][2] = packbf2(p10 - __bfloat162float(hp->x), p11 - __bfloat162float(hp->y));
            hp = (__nv_bfloat162*)&phi[ks][3];
            plo[ks][3] = packbf2(p12 - __bfloat162float(hp->x), p13 - __bfloat162float(hp->y));
        }

        #pragma unroll
        for (int d2 = 0; d2 < 4; d2++) {
            #pragma unroll
            for (int ks = 0; ks < 4; ks++) {
                uint32_t vb[4];
                ldsm_x4(vb, vbase + ((d2*16 + bRowP) * QSTR + ks*16 + bColP) * 2);
                mma_bf16(oacc[2*d2],   phi[ks], &vb[0]);
                mma_bf16(oacc[2*d2+1], phi[ks], &vb[2]);
                mma_bf16(oacc[2*d2],   plo[ks], &vb[0]);
                mma_bf16(oacc[2*d2+1], plo[ks], &vb[2]);
            }
            #pragma unroll
            for (int ks = 0; ks < 4; ks++) {
                uint32_t vb[4];
                ldsm_x4(vb, vbase + ((d2*16 + bRowP) * QSTR + 64 + ks*16 + bColP) * 2);
                mma_bf16(oacc[2*d2],   phi[ks], &vb[0]);
                mma_bf16(oacc[2*d2+1], phi[ks], &vb[2]);
            }
        }
    }

    // ---- epilogue: 2-plane obuf [b][n][hi512|lo512] ----
    float inv0 = 1.f / l0, inv1 = 1.f / l1;
    int b = bh >> 3, h = bh & 7;
    int row0 = q0 + w * 16 + (lane >> 2);
    #pragma unroll
    for (int df = 0; df < 8; df++) {
        int chn = h * HD + df * 8 + (lane & 3) * 2;
        #pragma unroll
        for (int r = 0; r < 2; r++) {
            int row = row0 + r * 8;
            float v0 = oacc[df][r*2 + 0] * (r ? inv1 : inv0);
            float v1 = oacc[df][r*2 + 1] * (r ? inv1 : inv0);
            uint32_t hp = packbf2(v0, v1);
            __nv_bfloat162 hb = *(__nv_bfloat162*)&hp;
            uint32_t lp = packbf2(v0 - __bfloat162float(hb.x), v1 - __bfloat162float(hb.y));
            size_t eb = ((size_t)b * N_ + row) * 1024 + chn;
            *(uint32_t*)&g_obuf[eb]       = hp;
            *(uint32_t*)&g_obuf[eb + 512] = lp;
        }
    }
}

// ---------------------------------------------------------------------------
// 4) Proj GEMM + bias + residual -> out[b][c][n]
// ---------------------------------------------------------------------------
__global__ __launch_bounds__(256, 2) void proj_gemm(const float* __restrict__ bias,
                                                    const float* __restrict__ x,
                                                    float* __restrict__ out) {
    int n0 = blockIdx.x * 128, m0 = blockIdx.y * 128, b = blockIdx.z;

    float acc[4][4][4];
    #pragma unroll
    for (int i = 0; i < 4; i++)
        #pragma unroll
        for (int j = 0; j < 4; j++)
            { acc[i][j][0]=0.f; acc[i][j][1]=0.f; acc[i][j][2]=0.f; acc[i][j][3]=0.f; }

    gemm_mainloop(acc,
        g_wproj + (size_t)m0 * 1024,
        g_obuf + ((size_t)b * N_ + n0) * 1024);

    int wid = threadIdx.x >> 5, lane = threadIdx.x & 31;
    int wm = (wid >> 2) * 64, wn = (wid & 3) * 32;

    #pragma unroll
    for (int mi = 0; mi < 4; mi++) {
        #pragma unroll
        for (int half = 0; half < 2; half++) {
            int chn = m0 + wm + mi*16 + (lane >> 2) + half*8;
            float bv = bias[chn];
            size_t rowbase = ((size_t)b * C_ + chn) * N_;
            #pragma unroll
            for (int ni = 0; ni < 4; ni++) {
                int n = n0 + wn + ni*8 + (lane & 3)*2;
                float2 xv = *(const float2*)&x[rowbase + n];
                float2 v;
                v.x = acc[mi][ni][half*2 + 0] + bv + xv.x;
                v.y = acc[mi][ni][half*2 + 1] + bv + xv.y;
                *(float2*)&out[rowbase + n] = v;
            }
        }
    }
}

// ---------------------------------------------------------------------------
extern "C" void kernel_launch(void* const* d_in, const int* in_sizes, int n_in,
                              void* d_out, int out_size) {
    const float* x      = (const float*)d_in[0];
    const float* norm_w = (const float*)d_in[1];
    const float* norm_b = (const float*)d_in[2];
    const float* qkv_w  = (const float*)d_in[3];
    const float* qkv_b  = (const float*)d_in[4];
    const float* proj_w = (const float*)d_in[5];
    const float* proj_b = (const float*)d_in[6];
    float* out = (float*)d_out;

    cudaFuncSetAttribute(qkv_gemm, cudaFuncAttributeMaxDynamicSharedMemorySize, GEMM_SMEM);
    cudaFuncSetAttribute(proj_gemm, cudaFuncAttributeMaxDynamicSharedMemorySize, GEMM_SMEM);
    cudaFuncSetAttribute(attn_kernel, cudaFuncAttributeMaxDynamicSharedMemorySize, ATTN_SMEM);

    convw_kernel<<<4 * C_, 128>>>(qkv_w, proj_w);
    gn_kernel<<<B_ * G_, 256>>>(x, norm_w, norm_b);
    qkv_gemm<<<dim3(N_ / 128, (3 * C_) / 128, B_), 256, GEMM_SMEM>>>(qkv_b);
    attn_kernel<<<dim3(N_ / 128, B_ * NH), 256, ATTN_SMEM>>>();
    proj_gemm<<<dim3(N_ / 128, C_ / 128, B_), 256, GEMM_SMEM>>>(proj_b, x, out);
}

// round 10
// speedup vs baseline: 5.0180x; 1.0341x over previous
#include <cuda_runtime.h>
#include <cuda_bf16.h>
#include <cstdint>

#define B_   16
#define C_   512
#define NH   8
#define HD   64
#define N_   1024
#define G_   32
#define CPG  16
#define EPSV 1e-5f
#define LOG2E 1.4426950408889634f

// ---------------- scratch (device globals; no allocation allowed) -----------
__device__ __nv_bfloat16 g_qext[(size_t)B_ * NH * N_ * 128];   // [b][h][n][hi64|lo64], pre-scaled
__device__ __nv_bfloat16 g_kext[(size_t)B_ * NH * N_ * 128];   // [b][h][n][hi64|lo64]
__device__ __nv_bfloat16 g_vhi[(size_t)B_ * NH * HD * N_];     // [b][h][d][n]
__device__ __nv_bfloat16 g_vlo[(size_t)B_ * NH * HD * N_];
__device__ __nv_bfloat16 g_hn[(size_t)B_ * N_ * 1024];         // [b][n][hi512|lo512]
__device__ __nv_bfloat16 g_obuf[(size_t)B_ * N_ * 1024];       // [b][n][hi512|lo512]
__device__ __nv_bfloat16 g_wqkv[(size_t)(3*C_) * 1024];        // [o][hi512|lo512]
__device__ __nv_bfloat16 g_wproj[(size_t)C_ * 1024];           // [o][hi512|lo512]

// ---------------- PTX helpers (baseline-safe for compute_103) ---------------
__device__ __forceinline__ uint32_t smem_u32(const void* p) {
    uint32_t a;
    asm("{ .reg .u64 t; cvta.to.shared.u64 t, %1; cvt.u32.u64 %0, t; }" : "=r"(a) : "l"(p));
    return a;
}
__device__ __forceinline__ void ldsm_x4(uint32_t* r, uint32_t addr) {
    asm volatile("ldmatrix.sync.aligned.m8n8.x4.shared.b16 {%0,%1,%2,%3}, [%4];"
                 : "=r"(r[0]), "=r"(r[1]), "=r"(r[2]), "=r"(r[3]) : "r"(addr));
}
__device__ __forceinline__ void mma_bf16(float* c, const uint32_t* a, const uint32_t* b) {
    asm volatile("mma.sync.aligned.m16n8k16.row.col.f32.bf16.bf16.f32 "
                 "{%0,%1,%2,%3}, {%4,%5,%6,%7}, {%8,%9}, {%0,%1,%2,%3};"
                 : "+f"(c[0]), "+f"(c[1]), "+f"(c[2]), "+f"(c[3])
                 : "r"(a[0]), "r"(a[1]), "r"(a[2]), "r"(a[3]), "r"(b[0]), "r"(b[1]));
}
__device__ __forceinline__ float ex2(float x) {
    float r; asm("ex2.approx.f32 %0, %1;" : "=f"(r) : "f"(x)); return r;
}
__device__ __forceinline__ uint32_t packbf2(float a, float b) {
    __nv_bfloat162 t; t.x = __float2bfloat16(a); t.y = __float2bfloat16(b);
    return *(uint32_t*)&t;
}
#define CPA(dst, src) \
    asm volatile("cp.async.cg.shared.global [%0], [%1], 16;" :: "r"(dst), "l"(src))
#define CPCOMMIT() asm volatile("cp.async.commit_group;")
#define CPWAIT(n)  asm volatile("cp.async.wait_group %0;" :: "n"(n))

// ---------------------------------------------------------------------------
// 0) Weight split: w[o][c] fp32 -> 2-plane [o][hi512|lo512]
// ---------------------------------------------------------------------------
__global__ void convw_kernel(const float* __restrict__ wq, const float* __restrict__ wp) {
    int r = blockIdx.x;
    const float* src = (r < 3*C_) ? wq + (size_t)r * C_ : wp + (size_t)(r - 3*C_) * C_;
    __nv_bfloat16* dst = (r < 3*C_) ? g_wqkv + (size_t)r * 1024
                                    : g_wproj + (size_t)(r - 3*C_) * 1024;
    for (int c = threadIdx.x; c < C_; c += 128) {
        float v = src[c];
        __nv_bfloat16 hi = __float2bfloat16(v);
        dst[c]       = hi;
        dst[512 + c] = __float2bfloat16(v - __bfloat162float(hi));
    }
}

// ---------------------------------------------------------------------------
// 1) GroupNorm + transpose + bf16 split -> g_hn [b][n][hi512|lo512]
// ---------------------------------------------------------------------------
__global__ __launch_bounds__(256) void gn_kernel(const float* __restrict__ x,
                                                 const float* __restrict__ w,
                                                 const float* __restrict__ bb) {
    int bg = blockIdx.x;
    int g = bg & (G_ - 1), b = bg >> 5;
    const float4* x4 = (const float4*)(x + (size_t)bg * CPG * N_);
    int tid = threadIdx.x;

    float s = 0.f, s2 = 0.f;
    #pragma unroll
    for (int i = 0; i < 16; i++) {
        float4 v = x4[tid + i * 256];
        s  += v.x + v.y + v.z + v.w;
        s2 += v.x*v.x + v.y*v.y + v.z*v.z + v.w*v.w;
    }
    __shared__ float rs[256], rs2[256];
    rs[tid] = s; rs2[tid] = s2;
    __syncthreads();
    for (int off = 128; off > 0; off >>= 1) {
        if (tid < off) { rs[tid] += rs[tid+off]; rs2[tid] += rs2[tid+off]; }
        __syncthreads();
    }
    float mean = rs[0] * (1.f/16384.f);
    float var  = rs2[0] * (1.f/16384.f) - mean*mean;
    float rstd = rsqrtf(var + EPSV);

    float sc[CPG], sh[CPG];
    #pragma unroll
    for (int c16 = 0; c16 < CPG; c16++) {
        int c = g*CPG + c16;
        sc[c16] = rstd * w[c];
        sh[c16] = bb[c] - mean * sc[c16];
    }

    float4 vals[CPG];
    #pragma unroll
    for (int c16 = 0; c16 < CPG; c16++) {
        float4 v = x4[c16 * 256 + tid];
        vals[c16].x = v.x*sc[c16]+sh[c16]; vals[c16].y = v.y*sc[c16]+sh[c16];
        vals[c16].z = v.z*sc[c16]+sh[c16]; vals[c16].w = v.w*sc[c16]+sh[c16];
    }
    union Pack { __nv_bfloat16 h[CPG]; uint4 v[2]; };
    #pragma unroll
    for (int j = 0; j < 4; j++) {
        Pack hiP, loP;
        #pragma unroll
        for (int c16 = 0; c16 < CPG; c16++) {
            float v = j == 0 ? vals[c16].x : j == 1 ? vals[c16].y
                    : j == 2 ? vals[c16].z : vals[c16].w;
            __nv_bfloat16 hv = __float2bfloat16(v);
            hiP.h[c16] = hv;
            loP.h[c16] = __float2bfloat16(v - __bfloat162float(hv));
        }
        __nv_bfloat16* dst = g_hn + ((size_t)b * N_ + tid*4 + j) * 1024 + g * CPG;
        *(uint4*)(dst)         = hiP.v[0]; *(uint4*)(dst + 8)         = hiP.v[1];
        *(uint4*)(dst + 512)   = loP.v[0]; *(uint4*)(dst + 512 + 8)   = loP.v[1];
    }
}

// ---------------------------------------------------------------------------
// HMMA GEMM mainloop: 2-stage cp.async + fragment double-buffer.
// 24 virtual chunks over 2-plane storage (A: hi,lo,hi ; B: hi,hi,lo).
// ---------------------------------------------------------------------------
#define SSTR 88
#define STAGE_U (2 * 128 * SSTR)
#define GEMM_SMEM (2 * STAGE_U * 2)        // 90112 B
#define NCHUNK 24

__device__ __forceinline__ int kmapA(int c) {
    return (c < 8) ? c*64 : (c < 16) ? 512 + (c-8)*64 : (c-16)*64;
}
__device__ __forceinline__ int kmapB(int c) {
    return (c < 8) ? c*64 : (c < 16) ? (c-8)*64 : 512 + (c-16)*64;
}

__device__ __forceinline__ void gemm_issue(__nv_bfloat16* As, __nv_bfloat16* Bs,
                                           const __nv_bfloat16* Abase,
                                           const __nv_bfloat16* Bbase,
                                           int c, int ldRow, int ldSeg) {
    int kA = kmapA(c), kB = kmapB(c);
    #pragma unroll
    for (int rr = 0; rr < 4; rr++) {
        int row = ldRow + rr * 32;
        CPA(smem_u32(&As[row * SSTR + ldSeg * 8]),
            Abase + (size_t)row * 1024 + kA + ldSeg * 8);
        CPA(smem_u32(&Bs[row * SSTR + ldSeg * 8]),
            Bbase + (size_t)row * 1024 + kB + ldSeg * 8);
    }
    CPCOMMIT();
}

__device__ __forceinline__ void gemm_mainloop(float acc[4][4][4],
                                              const __nv_bfloat16* __restrict__ Abase,
                                              const __nv_bfloat16* __restrict__ Bbase) {
    extern __shared__ __nv_bfloat16 dynsm[];
    __nv_bfloat16* As[2] = { dynsm, dynsm + STAGE_U };
    __nv_bfloat16* Bs[2] = { dynsm + 128*SSTR, dynsm + STAGE_U + 128*SSTR };

    int tid = threadIdx.x, wid = tid >> 5, lane = tid & 31;
    int wm = (wid >> 2) * 64;
    int wn = (wid & 3) * 32;
    int aRow = wm + (lane & 15), aCol = (lane >> 4) * 8;
    int bRowP = (lane & 7) + ((lane >> 4) * 8);
    int bColP = ((lane >> 3) & 1) * 8;
    int ldRow = tid >> 3;
    int ldSeg = tid & 7;

    gemm_issue(As[0], Bs[0], Abase, Bbase, 0, ldRow, ldSeg);

    #pragma unroll 1
    for (int c = 0; c < NCHUNK; c++) {
        if (c + 1 < NCHUNK) {
            gemm_issue(As[(c+1)&1], Bs[(c+1)&1], Abase, Bbase, c+1, ldRow, ldSeg);
            CPWAIT(1);
        } else {
            CPWAIT(0);
        }
        __syncthreads();

        uint32_t smA = smem_u32(As[c&1]), smB = smem_u32(Bs[c&1]);
        uint32_t af[2][4][4], bf[2][2][4];
        #pragma unroll
        for (int mi = 0; mi < 4; mi++)
            ldsm_x4(af[0][mi], smA + ((aRow + mi*16) * SSTR + aCol) * 2);
        #pragma unroll
        for (int n2 = 0; n2 < 2; n2++)
            ldsm_x4(bf[0][n2], smB + ((wn + n2*16 + bRowP) * SSTR + bColP) * 2);

        #pragma unroll
        for (int ks = 0; ks < 4; ks++) {
            int cur = ks & 1, nxt = cur ^ 1;
            if (ks < 3) {
                #pragma unroll
                for (int mi = 0; mi < 4; mi++)
                    ldsm_x4(af[nxt][mi], smA + ((aRow + mi*16) * SSTR + (ks+1)*16 + aCol) * 2);
                #pragma unroll
                for (int n2 = 0; n2 < 2; n2++)
                    ldsm_x4(bf[nxt][n2], smB + ((wn + n2*16 + bRowP) * SSTR + (ks+1)*16 + bColP) * 2);
            }
            #pragma unroll
            for (int mi = 0; mi < 4; mi++)
                #pragma unroll
                for (int n2 = 0; n2 < 2; n2++) {
                    mma_bf16(acc[mi][2*n2],   af[cur][mi], &bf[cur][n2][0]);
                    mma_bf16(acc[mi][2*n2+1], af[cur][mi], &bf[cur][n2][2]);
                }
        }
        __syncthreads();
    }
}

// ---------------------------------------------------------------------------
// 2) QKV GEMM -> Q,K ext bf16 [b][h][n][128] (smem-staged coalesced stores);
//    V hi/lo planes [b][h][d][n]
// ---------------------------------------------------------------------------
#define ESTR 136

__global__ __launch_bounds__(256, 2) void qkv_gemm(const float* __restrict__ bias) {
    int n0 = blockIdx.x * 128, m0 = blockIdx.y * 128, b = blockIdx.z;

    float acc[4][4][4];
    #pragma unroll
    for (int i = 0; i < 4; i++)
        #pragma unroll
        for (int j = 0; j < 4; j++)
            { acc[i][j][0]=0.f; acc[i][j][1]=0.f; acc[i][j][2]=0.f; acc[i][j][3]=0.f; }

    gemm_mainloop(acc,
        g_wqkv + (size_t)m0 * 1024,
        g_hn + ((size_t)b * N_ + n0) * 1024);

    extern __shared__ __nv_bfloat16 dynsm[];
    int tid = threadIdx.x, wid = tid >> 5, lane = tid & 31;
    int wm = (wid >> 2) * 64, wn = (wid & 3) * 32;
    int s = m0 >> 9;

    if (s == 2) {
        #pragma unroll
        for (int mi = 0; mi < 4; mi++) {
            #pragma unroll
            for (int half = 0; half < 2; half++) {
                int o = m0 + wm + mi*16 + (lane >> 2) + half*8;
                int rem = o & 511, h = rem >> 6, d = rem & 63;
                float bv = bias[o];
                size_t vb = (((size_t)b * NH + h) * HD + d) * N_;
                #pragma unroll
                for (int ni = 0; ni < 4; ni++) {
                    int n = n0 + wn + ni*8 + (lane & 3)*2;
                    float v0 = acc[mi][ni][half*2 + 0] + bv;
                    float v1 = acc[mi][ni][half*2 + 1] + bv;
                    uint32_t hp = packbf2(v0, v1);
                    __nv_bfloat162 hb = *(__nv_bfloat162*)&hp;
                    uint32_t lp = packbf2(v0 - __bfloat162float(hb.x),
                                          v1 - __bfloat162float(hb.y));
                    *(uint32_t*)&g_vhi[vb + n] = hp;
                    *(uint32_t*)&g_vlo[vb + n] = lp;
                }
            }
        }
    } else {
        float scl = (s == 0) ? 0.125f : 1.0f;
        #pragma unroll
        for (int mi = 0; mi < 4; mi++) {
            #pragma unroll
            for (int half = 0; half < 2; half++) {
                int o = m0 + wm + mi*16 + (lane >> 2) + half*8;
                int hp = (o >> 6) & 1, d = o & 63;
                float bv = bias[o];
                __nv_bfloat16* Eb = dynsm + hp * (128 * ESTR);
                #pragma unroll
                for (int ni = 0; ni < 4; ni++) {
                    int nloc = wn + ni*8 + (lane & 3)*2;
                    float v0 = (acc[mi][ni][half*2 + 0] + bv) * scl;
                    float v1 = (acc[mi][ni][half*2 + 1] + bv) * scl;
                    __nv_bfloat16 h0 = __float2bfloat16(v0);
                    __nv_bfloat16 h1 = __float2bfloat16(v1);
                    Eb[nloc * ESTR + d]            = h0;
                    Eb[nloc * ESTR + 64 + d]       = __float2bfloat16(v0 - __bfloat162float(h0));
                    Eb[(nloc+1) * ESTR + d]        = h1;
                    Eb[(nloc+1) * ESTR + 64 + d]   = __float2bfloat16(v1 - __bfloat162float(h1));
                }
            }
        }
        __syncthreads();
        int h0g = (m0 & 511) >> 6;
        __nv_bfloat16* outp = (s == 0 ? g_qext : g_kext);
        #pragma unroll
        for (int i = 0; i < 16; i++) {
            int f = tid + i * 256;
            int hp = f >> 11, r = f & 2047, nloc = r >> 4, seg = r & 15;
            *(uint4*)(outp + (((size_t)b * NH + h0g + hp) * N_ + n0 + nloc) * 128 + seg * 8)
                = *(uint4*)(dynsm + hp * (128 * ESTR) + nloc * ESTR + seg * 8);
        }
    }
}

// ---------------------------------------------------------------------------
// 3) HMMA flash attention: 3-ring, streamed B fragments, 2 CTA/SM.
//    Softmax: deferred l-reduction + skip-rescale when max unchanged.
// ---------------------------------------------------------------------------
#define QSTR 136
#define ATTN_SMEM (52224 * 2)

__global__ __launch_bounds__(256, 2) void attn_kernel() {
    extern __shared__ __nv_bfloat16 dynsm[];
    __nv_bfloat16* Qh = dynsm;
    __nv_bfloat16* Kx[3] = { dynsm + 17408, dynsm + 34816, dynsm };
    __nv_bfloat16* Vx[3] = { dynsm + 26112, dynsm + 43520, dynsm + 8704 };

    int q0 = blockIdx.x * 128;
    int bh = blockIdx.y;
    const __nv_bfloat16* qg = g_qext + (size_t)bh * N_ * 128;
    const __nv_bfloat16* kg = g_kext + (size_t)bh * N_ * 128;
    const __nv_bfloat16* vhi = g_vhi + (size_t)bh * HD * N_;
    const __nv_bfloat16* vlo = g_vlo + (size_t)bh * HD * N_;

    int tid = threadIdx.x, w = tid >> 5, lane = tid & 31;

    #pragma unroll
    for (int i = 0; i < 8; i++) {
        int idx = tid + i * 256;
        int row = idx >> 4, seg = idx & 15;
        CPA(smem_u32(&Qh[row * QSTR + seg * 8]), qg + (size_t)(q0 + row) * 128 + seg * 8);
    }
    CPCOMMIT();

    #pragma unroll
    for (int st = 0; st < 2; st++) {
        int nb = st * 64;
        #pragma unroll
        for (int i = 0; i < 4; i++) {
            int idx = tid + i * 256;
            int row = idx >> 4, seg = idx & 15;
            CPA(smem_u32(&Kx[st][row * QSTR + seg * 8]),
                kg + (size_t)(nb + row) * 128 + seg * 8);
        }
        #pragma unroll
        for (int i = 0; i < 4; i++) {
            int idx = tid + i * 256;
            int d = idx >> 4, seg = idx & 15;
            const __nv_bfloat16* src = (seg < 8 ? vhi : vlo) + (size_t)d * N_ + nb + (seg & 7) * 8;
            CPA(smem_u32(&Vx[st][d * QSTR + seg * 8]), src);
        }
        CPCOMMIT();
    }

    CPWAIT(2);
    __syncthreads();
    uint32_t qbase = smem_u32(Qh);
    int ar = w * 16 + (lane & 15);
    int ac = (lane >> 4) * 8;
    uint32_t qh[4][4], ql[4][4];
    #pragma unroll
    for (int ks = 0; ks < 4; ks++) {
        ldsm_x4(qh[ks], qbase + (ar * QSTR + ks * 16 + ac) * 2);
        ldsm_x4(ql[ks], qbase + (ar * QSTR + 64 + ks * 16 + ac) * 2);
    }
    __syncthreads();

    float oacc[8][4];
    #pragma unroll
    for (int i = 0; i < 8; i++)
        { oacc[i][0]=0.f; oacc[i][1]=0.f; oacc[i][2]=0.f; oacc[i][3]=0.f; }
    float m0 = -1e30f, m1 = -1e30f;
    float l0p = 0.f, l1p = 0.f;        // per-thread partial row sums

    int bRowP = (lane & 7) + ((lane >> 4) * 8);
    int bColP = ((lane >> 3) & 1) * 8;

    #pragma unroll 1
    for (int ch = 0; ch < 16; ch++) {
        if (ch < 14) CPWAIT(1); else CPWAIT(0);
        __syncthreads();

        if (ch + 2 < 16) {
            int st = (ch + 2) % 3, nb = (ch + 2) * 64;
            #pragma unroll
            for (int i = 0; i < 4; i++) {
                int idx = tid + i * 256;
                int row = idx >> 4, seg = idx & 15;
                CPA(smem_u32(&Kx[st][row * QSTR + seg * 8]),
                    kg + (size_t)(nb + row) * 128 + seg * 8);
            }
            #pragma unroll
            for (int i = 0; i < 4; i++) {
                int idx = tid + i * 256;
                int d = idx >> 4, seg = idx & 15;
                const __nv_bfloat16* src = (seg < 8 ? vhi : vlo) + (size_t)d * N_ + nb + (seg & 7) * 8;
                CPA(smem_u32(&Vx[st][d * QSTR + seg * 8]), src);
            }
            CPCOMMIT();
        }

        uint32_t kbase = smem_u32(Kx[ch % 3]);
        uint32_t vbase = smem_u32(Vx[ch % 3]);

        float sacc[8][4];
        #pragma unroll
        for (int i = 0; i < 8; i++)
            { sacc[i][0]=0.f; sacc[i][1]=0.f; sacc[i][2]=0.f; sacc[i][3]=0.f; }

        #pragma unroll
        for (int n2 = 0; n2 < 4; n2++) {
            #pragma unroll
            for (int ks = 0; ks < 4; ks++) {
                uint32_t kb[4];
                ldsm_x4(kb, kbase + ((n2*16 + bRowP) * QSTR + ks*16 + bColP) * 2);
                mma_bf16(sacc[2*n2],   qh[ks], &kb[0]);
                mma_bf16(sacc[2*n2+1], qh[ks], &kb[2]);
                mma_bf16(sacc[2*n2],   ql[ks], &kb[0]);
                mma_bf16(sacc[2*n2+1], ql[ks], &kb[2]);
            }
            #pragma unroll
            for (int ks = 0; ks < 4; ks++) {
                uint32_t kb[4];
                ldsm_x4(kb, kbase + ((n2*16 + bRowP) * QSTR + 64 + ks*16 + bColP) * 2);
                mma_bf16(sacc[2*n2],   qh[ks], &kb[0]);
                mma_bf16(sacc[2*n2+1], qh[ks], &kb[2]);
            }
        }

        // ---- online softmax (deferred l-reduction; conditional rescale) ----
        float mx0 = -1e30f, mx1 = -1e30f;
        #pragma unroll
        for (int nf = 0; nf < 8; nf++) {
            mx0 = fmaxf(mx0, fmaxf(sacc[nf][0], sacc[nf][1]));
            mx1 = fmaxf(mx1, fmaxf(sacc[nf][2], sacc[nf][3]));
        }
        mx0 = fmaxf(mx0, __shfl_xor_sync(0xffffffffu, mx0, 1));
        mx0 = fmaxf(mx0, __shfl_xor_sync(0xffffffffu, mx0, 2));
        mx1 = fmaxf(mx1, __shfl_xor_sync(0xffffffffu, mx1, 1));
        mx1 = fmaxf(mx1, __shfl_xor_sync(0xffffffffu, mx1, 2));
        float mn0 = fmaxf(m0, mx0), mn1 = fmaxf(m1, mx1);
        float f0 = ex2((m0 - mn0) * LOG2E), f1 = ex2((m1 - mn1) * LOG2E);

        if (!__all_sync(0xffffffffu, (f0 == 1.f) && (f1 == 1.f))) {
            l0p *= f0; l1p *= f1;
            #pragma unroll
            for (int df = 0; df < 8; df++) {
                oacc[df][0] *= f0; oacc[df][1] *= f0;
                oacc[df][2] *= f1; oacc[df][3] *= f1;
            }
        }
        m0 = mn0; m1 = mn1;

        #pragma unroll
        for (int nf = 0; nf < 8; nf++) {
            sacc[nf][0] = ex2((sacc[nf][0] - mn0) * LOG2E);
            sacc[nf][1] = ex2((sacc[nf][1] - mn0) * LOG2E);
            sacc[nf][2] = ex2((sacc[nf][2] - mn1) * LOG2E);
            sacc[nf][3] = ex2((sacc[nf][3] - mn1) * LOG2E);
            l0p += sacc[nf][0] + sacc[nf][1];
            l1p += sacc[nf][2] + sacc[nf][3];
        }

        uint32_t phi[4][4], plo[4][4];
        #pragma unroll
        for (int ks = 0; ks < 4; ks++) {
            int j = 2 * ks;
            float p00 = sacc[j][0],   p01 = sacc[j][1];
            float p02 = sacc[j][2],   p03 = sacc[j][3];
            float p10 = sacc[j+1][0], p11 = sacc[j+1][1];
            float p12 = sacc[j+1][2], p13 = sacc[j+1][3];
            phi[ks][0] = packbf2(p00, p01);
            phi[ks][1] = packbf2(p02, p03);
            phi[ks][2] = packbf2(p10, p11);
            phi[ks][3] = packbf2(p12, p13);
            __nv_bfloat162* hp;
            hp = (__nv_bfloat162*)&phi[ks][0];
            plo[ks][0] = packbf2(p00 - __bfloat162float(hp->x), p01 - __bfloat162float(hp->y));
            hp = (__nv_bfloat162*)&phi[ks][1];
            plo[ks][1] = packbf2(p02 - __bfloat162float(hp->x), p03 - __bfloat162float(hp->y));
            hp = (__nv_bfloat162*)&phi[ks][2];
            plo[ks][2] = packbf2(p10 - __bfloat162float(hp->x), p11 - __bfloat162float(hp->y));
            hp = (__nv_bfloat162*)&phi[ks][3];
            plo[ks][3] = packbf2(p12 - __bfloat162float(hp->x), p13 - __bfloat162float(hp->y));
        }

        #pragma unroll
        for (int d2 = 0; d2 < 4; d2++) {
            #pragma unroll
            for (int ks = 0; ks < 4; ks++) {
                uint32_t vb[4];
                ldsm_x4(vb, vbase + ((d2*16 + bRowP) * QSTR + ks*16 + bColP) * 2);
                mma_bf16(oacc[2*d2],   phi[ks], &vb[0]);
                mma_bf16(oacc[2*d2+1], phi[ks], &vb[2]);
                mma_bf16(oacc[2*d2],   plo[ks], &vb[0]);
                mma_bf16(oacc[2*d2+1], plo[ks], &vb[2]);
            }
            #pragma unroll
            for (int ks = 0; ks < 4; ks++) {
                uint32_t vb[4];
                ldsm_x4(vb, vbase + ((d2*16 + bRowP) * QSTR + 64 + ks*16 + bColP) * 2);
                mma_bf16(oacc[2*d2],   phi[ks], &vb[0]);
                mma_bf16(oacc[2*d2+1], phi[ks], &vb[2]);
            }
        }
    }

    // ---- final l reduction (once) ----
    l0p += __shfl_xor_sync(0xffffffffu, l0p, 1);
    l0p += __shfl_xor_sync(0xffffffffu, l0p, 2);
    l1p += __shfl_xor_sync(0xffffffffu, l1p, 1);
    l1p += __shfl_xor_sync(0xffffffffu, l1p, 2);

    // ---- epilogue: 2-plane obuf [b][n][hi512|lo512] ----
    float inv0 = 1.f / l0p, inv1 = 1.f / l1p;
    int b = bh >> 3, h = bh & 7;
    int row0 = q0 + w * 16 + (lane >> 2);
    #pragma unroll
    for (int df = 0; df < 8; df++) {
        int chn = h * HD + df * 8 + (lane & 3) * 2;
        #pragma unroll
        for (int r = 0; r < 2; r++) {
            int row = row0 + r * 8;
            float v0 = oacc[df][r*2 + 0] * (r ? inv1 : inv0);
            float v1 = oacc[df][r*2 + 1] * (r ? inv1 : inv0);
            uint32_t hp = packbf2(v0, v1);
            __nv_bfloat162 hb = *(__nv_bfloat162*)&hp;
            uint32_t lp = packbf2(v0 - __bfloat162float(hb.x), v1 - __bfloat162float(hb.y));
            size_t eb = ((size_t)b * N_ + row) * 1024 + chn;
            *(uint32_t*)&g_obuf[eb]       = hp;
            *(uint32_t*)&g_obuf[eb + 512] = lp;
        }
    }
}

// ---------------------------------------------------------------------------
// 4) Proj GEMM + bias + residual -> out[b][c][n]
// ---------------------------------------------------------------------------
__global__ __launch_bounds__(256, 2) void proj_gemm(const float* __restrict__ bias,
                                                    const float* __restrict__ x,
                                                    float* __restrict__ out) {
    int n0 = blockIdx.x * 128, m0 = blockIdx.y * 128, b = blockIdx.z;

    float acc[4][4][4];
    #pragma unroll
    for (int i = 0; i < 4; i++)
        #pragma unroll
        for (int j = 0; j < 4; j++)
            { acc[i][j][0]=0.f; acc[i][j][1]=0.f; acc[i][j][2]=0.f; acc[i][j][3]=0.f; }

    gemm_mainloop(acc,
        g_wproj + (size_t)m0 * 1024,
        g_obuf + ((size_t)b * N_ + n0) * 1024);

    int wid = threadIdx.x >> 5, lane = threadIdx.x & 31;
    int wm = (wid >> 2) * 64, wn = (wid & 3) * 32;

    #pragma unroll
    for (int mi = 0; mi < 4; mi++) {
        #pragma unroll
        for (int half = 0; half < 2; half++) {
            int chn = m0 + wm + mi*16 + (lane >> 2) + half*8;
            float bv = bias[chn];
            size_t rowbase = ((size_t)b * C_ + chn) * N_;
            #pragma unroll
            for (int ni = 0; ni < 4; ni++) {
                int n = n0 + wn + ni*8 + (lane & 3)*2;
                float2 xv = *(const float2*)&x[rowbase + n];
                float2 v;
                v.x = acc[mi][ni][half*2 + 0] + bv + xv.x;
                v.y = acc[mi][ni][half*2 + 1] + bv + xv.y;
                *(float2*)&out[rowbase + n] = v;
            }
        }
    }
}

// ---------------------------------------------------------------------------
extern "C" void kernel_launch(void* const* d_in, const int* in_sizes, int n_in,
                              void* d_out, int out_size) {
    const float* x      = (const float*)d_in[0];
    const float* norm_w = (const float*)d_in[1];
    const float* norm_b = (const float*)d_in[2];
    const float* qkv_w  = (const float*)d_in[3];
    const float* qkv_b  = (const float*)d_in[4];
    const float* proj_w = (const float*)d_in[5];
    const float* proj_b = (const float*)d_in[6];
    float* out = (float*)d_out;

    cudaFuncSetAttribute(qkv_gemm, cudaFuncAttributeMaxDynamicSharedMemorySize, GEMM_SMEM);
    cudaFuncSetAttribute(proj_gemm, cudaFuncAttributeMaxDynamicSharedMemorySize, GEMM_SMEM);
    cudaFuncSetAttribute(attn_kernel, cudaFuncAttributeMaxDynamicSharedMemorySize, ATTN_SMEM);

    convw_kernel<<<4 * C_, 128>>>(qkv_w, proj_w);
    gn_kernel<<<B_ * G_, 256>>>(x, norm_w, norm_b);
    qkv_gemm<<<dim3(N_ / 128, (3 * C_) / 128, B_), 256, GEMM_SMEM>>>(qkv_b);
    attn_kernel<<<dim3(N_ / 128, B_ * NH), 256, ATTN_SMEM>>>();
    proj_gemm<<<dim3(N_ / 128, C_ / 128, B_), 256, GEMM_SMEM>>>(proj_b, x, out);
}

// round 11
// speedup vs baseline: 5.1695x; 1.0302x over previous
#include <cuda_runtime.h>
#include <cuda_bf16.h>
#include <cstdint>

#define B_   16
#define C_   512
#define NH   8
#define HD   64
#define N_   1024
#define G_   32
#define CPG  16
#define EPSV 1e-5f
#define LOG2E 1.4426950408889634f

// ---------------- scratch (device globals; no allocation allowed) -----------
__device__ __nv_bfloat16 g_qext[(size_t)B_ * NH * N_ * 128];   // [b][h][n][hi64|lo64], pre-scaled
__device__ __nv_bfloat16 g_kext[(size_t)B_ * NH * N_ * 128];   // [b][h][n][hi64|lo64]
__device__ __nv_bfloat16 g_vhi[(size_t)B_ * NH * HD * N_];     // [b][h][d][n]
__device__ __nv_bfloat16 g_vlo[(size_t)B_ * NH * HD * N_];
__device__ __nv_bfloat16 g_hn[(size_t)B_ * N_ * 1024];         // [b][n][hi512|lo512]
__device__ __nv_bfloat16 g_obuf[(size_t)B_ * N_ * 1024];       // [b][n][hi512|lo512]
__device__ __nv_bfloat16 g_wqkv[(size_t)(3*C_) * 1024];        // [o][hi512|lo512]
__device__ __nv_bfloat16 g_wproj[(size_t)C_ * 1024];           // [o][hi512|lo512]

// ---------------- PTX helpers (baseline-safe for compute_103) ---------------
__device__ __forceinline__ uint32_t smem_u32(const void* p) {
    uint32_t a;
    asm("{ .reg .u64 t; cvta.to.shared.u64 t, %1; cvt.u32.u64 %0, t; }" : "=r"(a) : "l"(p));
    return a;
}
__device__ __forceinline__ void ldsm_x4(uint32_t* r, uint32_t addr) {
    asm volatile("ldmatrix.sync.aligned.m8n8.x4.shared.b16 {%0,%1,%2,%3}, [%4];"
                 : "=r"(r[0]), "=r"(r[1]), "=r"(r[2]), "=r"(r[3]) : "r"(addr));
}
__device__ __forceinline__ void mma_bf16(float* c, const uint32_t* a, const uint32_t* b) {
    asm volatile("mma.sync.aligned.m16n8k16.row.col.f32.bf16.bf16.f32 "
                 "{%0,%1,%2,%3}, {%4,%5,%6,%7}, {%8,%9}, {%0,%1,%2,%3};"
                 : "+f"(c[0]), "+f"(c[1]), "+f"(c[2]), "+f"(c[3])
                 : "r"(a[0]), "r"(a[1]), "r"(a[2]), "r"(a[3]), "r"(b[0]), "r"(b[1]));
}
__device__ __forceinline__ float ex2(float x) {
    float r; asm("ex2.approx.f32 %0, %1;" : "=f"(r) : "f"(x)); return r;
}
__device__ __forceinline__ uint32_t packbf2(float a, float b) {
    __nv_bfloat162 t; t.x = __float2bfloat16(a); t.y = __float2bfloat16(b);
    return *(uint32_t*)&t;
}
#define CPA(dst, src) \
    asm volatile("cp.async.cg.shared.global [%0], [%1], 16;" :: "r"(dst), "l"(src))
#define CPCOMMIT() asm volatile("cp.async.commit_group;")
#define CPWAIT(n)  asm volatile("cp.async.wait_group %0;" :: "n"(n))

// ---------------------------------------------------------------------------
// 0) Weight split: w[o][c] fp32 -> 2-plane [o][hi512|lo512]
// ---------------------------------------------------------------------------
__global__ void convw_kernel(const float* __restrict__ wq, const float* __restrict__ wp) {
    int r = blockIdx.x;
    const float* src = (r < 3*C_) ? wq + (size_t)r * C_ : wp + (size_t)(r - 3*C_) * C_;
    __nv_bfloat16* dst = (r < 3*C_) ? g_wqkv + (size_t)r * 1024
                                    : g_wproj + (size_t)(r - 3*C_) * 1024;
    for (int c = threadIdx.x; c < C_; c += 128) {
        float v = src[c];
        __nv_bfloat16 hi = __float2bfloat16(v);
        dst[c]       = hi;
        dst[512 + c] = __float2bfloat16(v - __bfloat162float(hi));
    }
}

// ---------------------------------------------------------------------------
// 1) GroupNorm + transpose + bf16 split -> g_hn [b][n][hi512|lo512]
// ---------------------------------------------------------------------------
__global__ __launch_bounds__(256) void gn_kernel(const float* __restrict__ x,
                                                 const float* __restrict__ w,
                                                 const float* __restrict__ bb) {
    int bg = blockIdx.x;
    int g = bg & (G_ - 1), b = bg >> 5;
    const float4* x4 = (const float4*)(x + (size_t)bg * CPG * N_);
    int tid = threadIdx.x;

    float s = 0.f, s2 = 0.f;
    #pragma unroll
    for (int i = 0; i < 16; i++) {
        float4 v = x4[tid + i * 256];
        s  += v.x + v.y + v.z + v.w;
        s2 += v.x*v.x + v.y*v.y + v.z*v.z + v.w*v.w;
    }
    __shared__ float rs[256], rs2[256];
    rs[tid] = s; rs2[tid] = s2;
    __syncthreads();
    for (int off = 128; off > 0; off >>= 1) {
        if (tid < off) { rs[tid] += rs[tid+off]; rs2[tid] += rs2[tid+off]; }
        __syncthreads();
    }
    float mean = rs[0] * (1.f/16384.f);
    float var  = rs2[0] * (1.f/16384.f) - mean*mean;
    float rstd = rsqrtf(var + EPSV);

    float sc[CPG], sh[CPG];
    #pragma unroll
    for (int c16 = 0; c16 < CPG; c16++) {
        int c = g*CPG + c16;
        sc[c16] = rstd * w[c];
        sh[c16] = bb[c] - mean * sc[c16];
    }

    float4 vals[CPG];
    #pragma unroll
    for (int c16 = 0; c16 < CPG; c16++) {
        float4 v = x4[c16 * 256 + tid];
        vals[c16].x = v.x*sc[c16]+sh[c16]; vals[c16].y = v.y*sc[c16]+sh[c16];
        vals[c16].z = v.z*sc[c16]+sh[c16]; vals[c16].w = v.w*sc[c16]+sh[c16];
    }
    union Pack { __nv_bfloat16 h[CPG]; uint4 v[2]; };
    #pragma unroll
    for (int j = 0; j < 4; j++) {
        Pack hiP, loP;
        #pragma unroll
        for (int c16 = 0; c16 < CPG; c16++) {
            float v = j == 0 ? vals[c16].x : j == 1 ? vals[c16].y
                    : j == 2 ? vals[c16].z : vals[c16].w;
            __nv_bfloat16 hv = __float2bfloat16(v);
            hiP.h[c16] = hv;
            loP.h[c16] = __float2bfloat16(v - __bfloat162float(hv));
        }
        __nv_bfloat16* dst = g_hn + ((size_t)b * N_ + tid*4 + j) * 1024 + g * CPG;
        *(uint4*)(dst)         = hiP.v[0]; *(uint4*)(dst + 8)         = hiP.v[1];
        *(uint4*)(dst + 512)   = loP.v[0]; *(uint4*)(dst + 512 + 8)   = loP.v[1];
    }
}

// ---------------------------------------------------------------------------
// HMMA GEMM mainloop: term-shared 16-chunk schedule, 2-stage cp.async.
//   c = 0..7 : stage {A-hi(c), A-lo(c), B-hi(c)}; both A terms vs one B tile
//   c = 8..15: stage {A-hi(c-8), B-lo(c-8)}      ; third term
// ---------------------------------------------------------------------------
#define SSTR 72
#define TILE_U (128 * SSTR)
#define STAGE_U (3 * TILE_U)
#define GEMM_SMEM (2 * STAGE_U * 2)        // 110592 B -> 2 CTA/SM

__device__ __forceinline__ void gemm_issue(__nv_bfloat16* stage,
                                           const __nv_bfloat16* Abase,
                                           const __nv_bfloat16* Bbase,
                                           int c, int ldRow, int ldSeg) {
    __nv_bfloat16* Ahi = stage;
    __nv_bfloat16* Alo = stage + TILE_U;
    __nv_bfloat16* Bt  = stage + 2 * TILE_U;
    if (c < 8) {
        int k0 = c * 64;
        #pragma unroll
        for (int rr = 0; rr < 4; rr++) {
            int row = ldRow + rr * 32;
            CPA(smem_u32(&Ahi[row * SSTR + ldSeg * 8]),
                Abase + (size_t)row * 1024 + k0 + ldSeg * 8);
            CPA(smem_u32(&Alo[row * SSTR + ldSeg * 8]),
                Abase + (size_t)row * 1024 + 512 + k0 + ldSeg * 8);
            CPA(smem_u32(&Bt[row * SSTR + ldSeg * 8]),
                Bbase + (size_t)row * 1024 + k0 + ldSeg * 8);
        }
    } else {
        int k0 = (c - 8) * 64;
        #pragma unroll
        for (int rr = 0; rr < 4; rr++) {
            int row = ldRow + rr * 32;
            CPA(smem_u32(&Ahi[row * SSTR + ldSeg * 8]),
                Abase + (size_t)row * 1024 + k0 + ldSeg * 8);
            CPA(smem_u32(&Bt[row * SSTR + ldSeg * 8]),
                Bbase + (size_t)row * 1024 + 512 + k0 + ldSeg * 8);
        }
    }
    CPCOMMIT();
}

__device__ __forceinline__ void gemm_mainloop(float acc[4][4][4],
                                              const __nv_bfloat16* __restrict__ Abase,
                                              const __nv_bfloat16* __restrict__ Bbase) {
    extern __shared__ __nv_bfloat16 dynsm[];
    __nv_bfloat16* stg[2] = { dynsm, dynsm + STAGE_U };

    int tid = threadIdx.x, wid = tid >> 5, lane = tid & 31;
    int wm = (wid >> 2) * 64;
    int wn = (wid & 3) * 32;
    int aRow = wm + (lane & 15), aCol = (lane >> 4) * 8;
    int bRowP = (lane & 7) + ((lane >> 4) * 8);
    int bColP = ((lane >> 3) & 1) * 8;
    int ldRow = tid >> 3;
    int ldSeg = tid & 7;

    gemm_issue(stg[0], Abase, Bbase, 0, ldRow, ldSeg);

    #pragma unroll 1
    for (int c = 0; c < 16; c++) {
        if (c + 1 < 16) {
            gemm_issue(stg[(c+1)&1], Abase, Bbase, c+1, ldRow, ldSeg);
            CPWAIT(1);
        } else {
            CPWAIT(0);
        }
        __syncthreads();

        __nv_bfloat16* st = stg[c & 1];
        uint32_t smAhi = smem_u32(st);
        uint32_t smAlo = smem_u32(st + TILE_U);
        uint32_t smB   = smem_u32(st + 2 * TILE_U);
        bool dual = (c < 8);

        #pragma unroll
        for (int ks = 0; ks < 4; ks++) {
            uint32_t bf[2][4], afh[4][4];
            #pragma unroll
            for (int n2 = 0; n2 < 2; n2++)
                ldsm_x4(bf[n2], smB + ((wn + n2*16 + bRowP) * SSTR + ks*16 + bColP) * 2);
            #pragma unroll
            for (int mi = 0; mi < 4; mi++)
                ldsm_x4(afh[mi], smAhi + ((aRow + mi*16) * SSTR + ks*16 + aCol) * 2);
            #pragma unroll
            for (int mi = 0; mi < 4; mi++)
                #pragma unroll
                for (int n2 = 0; n2 < 2; n2++) {
                    mma_bf16(acc[mi][2*n2],   afh[mi], &bf[n2][0]);
                    mma_bf16(acc[mi][2*n2+1], afh[mi], &bf[n2][2]);
                }
            if (dual) {
                uint32_t afl[4][4];
                #pragma unroll
                for (int mi = 0; mi < 4; mi++)
                    ldsm_x4(afl[mi], smAlo + ((aRow + mi*16) * SSTR + ks*16 + aCol) * 2);
                #pragma unroll
                for (int mi = 0; mi < 4; mi++)
                    #pragma unroll
                    for (int n2 = 0; n2 < 2; n2++) {
                        mma_bf16(acc[mi][2*n2],   afl[mi], &bf[n2][0]);
                        mma_bf16(acc[mi][2*n2+1], afl[mi], &bf[n2][2]);
                    }
            }
        }
        __syncthreads();
    }
}

// ---------------------------------------------------------------------------
// 2) QKV GEMM -> Q,K ext bf16 [b][h][n][128] (smem-staged coalesced stores);
//    V hi/lo planes [b][h][d][n]
// ---------------------------------------------------------------------------
#define ESTR 136

__global__ __launch_bounds__(256, 2) void qkv_gemm(const float* __restrict__ bias) {
    int n0 = blockIdx.x * 128, m0 = blockIdx.y * 128, b = blockIdx.z;

    float acc[4][4][4];
    #pragma unroll
    for (int i = 0; i < 4; i++)
        #pragma unroll
        for (int j = 0; j < 4; j++)
            { acc[i][j][0]=0.f; acc[i][j][1]=0.f; acc[i][j][2]=0.f; acc[i][j][3]=0.f; }

    gemm_mainloop(acc,
        g_wqkv + (size_t)m0 * 1024,
        g_hn + ((size_t)b * N_ + n0) * 1024);

    extern __shared__ __nv_bfloat16 dynsm[];
    int tid = threadIdx.x, wid = tid >> 5, lane = tid & 31;
    int wm = (wid >> 2) * 64, wn = (wid & 3) * 32;
    int s = m0 >> 9;

    if (s == 2) {
        #pragma unroll
        for (int mi = 0; mi < 4; mi++) {
            #pragma unroll
            for (int half = 0; half < 2; half++) {
                int o = m0 + wm + mi*16 + (lane >> 2) + half*8;
                int rem = o & 511, h = rem >> 6, d = rem & 63;
                float bv = bias[o];
                size_t vb = (((size_t)b * NH + h) * HD + d) * N_;
                #pragma unroll
                for (int ni = 0; ni < 4; ni++) {
                    int n = n0 + wn + ni*8 + (lane & 3)*2;
                    float v0 = acc[mi][ni][half*2 + 0] + bv;
                    float v1 = acc[mi][ni][half*2 + 1] + bv;
                    uint32_t hp = packbf2(v0, v1);
                    __nv_bfloat162 hb = *(__nv_bfloat162*)&hp;
                    uint32_t lp = packbf2(v0 - __bfloat162float(hb.x),
                                          v1 - __bfloat162float(hb.y));
                    *(uint32_t*)&g_vhi[vb + n] = hp;
                    *(uint32_t*)&g_vlo[vb + n] = lp;
                }
            }
        }
    } else {
        float scl = (s == 0) ? 0.125f : 1.0f;
        #pragma unroll
        for (int mi = 0; mi < 4; mi++) {
            #pragma unroll
            for (int half = 0; half < 2; half++) {
                int o = m0 + wm + mi*16 + (lane >> 2) + half*8;
                int hp = (o >> 6) & 1, d = o & 63;
                float bv = bias[o];
                __nv_bfloat16* Eb = dynsm + hp * (128 * ESTR);
                #pragma unroll
                for (int ni = 0; ni < 4; ni++) {
                    int nloc = wn + ni*8 + (lane & 3)*2;
                    float v0 = (acc[mi][ni][half*2 + 0] + bv) * scl;
                    float v1 = (acc[mi][ni][half*2 + 1] + bv) * scl;
                    __nv_bfloat16 h0 = __float2bfloat16(v0);
                    __nv_bfloat16 h1 = __float2bfloat16(v1);
                    Eb[nloc * ESTR + d]            = h0;
                    Eb[nloc * ESTR + 64 + d]       = __float2bfloat16(v0 - __bfloat162float(h0));
                    Eb[(nloc+1) * ESTR + d]        = h1;
                    Eb[(nloc+1) * ESTR + 64 + d]   = __float2bfloat16(v1 - __bfloat162float(h1));
                }
            }
        }
        __syncthreads();
        int h0g = (m0 & 511) >> 6;
        __nv_bfloat16* outp = (s == 0 ? g_qext : g_kext);
        #pragma unroll
        for (int i = 0; i < 16; i++) {
            int f = tid + i * 256;
            int hp = f >> 11, r = f & 2047, nloc = r >> 4, seg = r & 15;
            *(uint4*)(outp + (((size_t)b * NH + h0g + hp) * N_ + n0 + nloc) * 128 + seg * 8)
                = *(uint4*)(dynsm + hp * (128 * ESTR) + nloc * ESTR + seg * 8);
        }
    }
}

// ---------------------------------------------------------------------------
// 3) HMMA flash attention: 3-ring, streamed B fragments, 2 CTA/SM.
//    Softmax: deferred l-reduction + skip-rescale when max unchanged.
// ---------------------------------------------------------------------------
#define QSTR 136
#define ATTN_SMEM (52224 * 2)

__global__ __launch_bounds__(256, 2) void attn_kernel() {
    extern __shared__ __nv_bfloat16 dynsm[];
    __nv_bfloat16* Qh = dynsm;
    __nv_bfloat16* Kx[3] = { dynsm + 17408, dynsm + 34816, dynsm };
    __nv_bfloat16* Vx[3] = { dynsm + 26112, dynsm + 43520, dynsm + 8704 };

    int q0 = blockIdx.x * 128;
    int bh = blockIdx.y;
    const __nv_bfloat16* qg = g_qext + (size_t)bh * N_ * 128;
    const __nv_bfloat16* kg = g_kext + (size_t)bh * N_ * 128;
    const __nv_bfloat16* vhi = g_vhi + (size_t)bh * HD * N_;
    const __nv_bfloat16* vlo = g_vlo + (size_t)bh * HD * N_;

    int tid = threadIdx.x, w = tid >> 5, lane = tid & 31;

    #pragma unroll
    for (int i = 0; i < 8; i++) {
        int idx = tid + i * 256;
        int row = idx >> 4, seg = idx & 15;
        CPA(smem_u32(&Qh[row * QSTR + seg * 8]), qg + (size_t)(q0 + row) * 128 + seg * 8);
    }
    CPCOMMIT();

    #pragma unroll
    for (int st = 0; st < 2; st++) {
        int nb = st * 64;
        #pragma unroll
        for (int i = 0; i < 4; i++) {
            int idx = tid + i * 256;
            int row = idx >> 4, seg = idx & 15;
            CPA(smem_u32(&Kx[st][row * QSTR + seg * 8]),
                kg + (size_t)(nb + row) * 128 + seg * 8);
        }
        #pragma unroll
        for (int i = 0; i < 4; i++) {
            int idx = tid + i * 256;
            int d = idx >> 4, seg = idx & 15;
            const __nv_bfloat16* src = (seg < 8 ? vhi : vlo) + (size_t)d * N_ + nb + (seg & 7) * 8;
            CPA(smem_u32(&Vx[st][d * QSTR + seg * 8]), src);
        }
        CPCOMMIT();
    }

    CPWAIT(2);
    __syncthreads();
    uint32_t qbase = smem_u32(Qh);
    int ar = w * 16 + (lane & 15);
    int ac = (lane >> 4) * 8;
    uint32_t qh[4][4], ql[4][4];
    #pragma unroll
    for (int ks = 0; ks < 4; ks++) {
        ldsm_x4(qh[ks], qbase + (ar * QSTR + ks * 16 + ac) * 2);
        ldsm_x4(ql[ks], qbase + (ar * QSTR + 64 + ks * 16 + ac) * 2);
    }
    __syncthreads();

    float oacc[8][4];
    #pragma unroll
    for (int i = 0; i < 8; i++)
        { oacc[i][0]=0.f; oacc[i][1]=0.f; oacc[i][2]=0.f; oacc[i][3]=0.f; }
    float m0 = -1e30f, m1 = -1e30f;
    float l0p = 0.f, l1p = 0.f;

    int bRowP = (lane & 7) + ((lane >> 4) * 8);
    int bColP = ((lane >> 3) & 1) * 8;

    #pragma unroll 1
    for (int ch = 0; ch < 16; ch++) {
        if (ch < 14) CPWAIT(1); else CPWAIT(0);
        __syncthreads();

        if (ch + 2 < 16) {
            int st = (ch + 2) % 3, nb = (ch + 2) * 64;
            #pragma unroll
            for (int i = 0; i < 4; i++) {
                int idx = tid + i * 256;
                int row = idx >> 4, seg = idx & 15;
                CPA(smem_u32(&Kx[st][row * QSTR + seg * 8]),
                    kg + (size_t)(nb + row) * 128 + seg * 8);
            }
            #pragma unroll
            for (int i = 0; i < 4; i++) {
                int idx = tid + i * 256;
                int d = idx >> 4, seg = idx & 15;
                const __nv_bfloat16* src = (seg < 8 ? vhi : vlo) + (size_t)d * N_ + nb + (seg & 7) * 8;
                CPA(smem_u32(&Vx[st][d * QSTR + seg * 8]), src);
            }
            CPCOMMIT();
        }

        uint32_t kbase = smem_u32(Kx[ch % 3]);
        uint32_t vbase = smem_u32(Vx[ch % 3]);

        float sacc[8][4];
        #pragma unroll
        for (int i = 0; i < 8; i++)
            { sacc[i][0]=0.f; sacc[i][1]=0.f; sacc[i][2]=0.f; sacc[i][3]=0.f; }

        #pragma unroll
        for (int n2 = 0; n2 < 4; n2++) {
            #pragma unroll
            for (int ks = 0; ks < 4; ks++) {
                uint32_t kb[4];
                ldsm_x4(kb, kbase + ((n2*16 + bRowP) * QSTR + ks*16 + bColP) * 2);
                mma_bf16(sacc[2*n2],   qh[ks], &kb[0]);
                mma_bf16(sacc[2*n2+1], qh[ks], &kb[2]);
                mma_bf16(sacc[2*n2],   ql[ks], &kb[0]);
                mma_bf16(sacc[2*n2+1], ql[ks], &kb[2]);
            }
            #pragma unroll
            for (int ks = 0; ks < 4; ks++) {
                uint32_t kb[4];
                ldsm_x4(kb, kbase + ((n2*16 + bRowP) * QSTR + 64 + ks*16 + bColP) * 2);
                mma_bf16(sacc[2*n2],   qh[ks], &kb[0]);
                mma_bf16(sacc[2*n2+1], qh[ks], &kb[2]);
            }
        }

        float mx0 = -1e30f, mx1 = -1e30f;
        #pragma unroll
        for (int nf = 0; nf < 8; nf++) {
            mx0 = fmaxf(mx0, fmaxf(sacc[nf][0], sacc[nf][1]));
            mx1 = fmaxf(mx1, fmaxf(sacc[nf][2], sacc[nf][3]));
        }
        mx0 = fmaxf(mx0, __shfl_xor_sync(0xffffffffu, mx0, 1));
        mx0 = fmaxf(mx0, __shfl_xor_sync(0xffffffffu, mx0, 2));
        mx1 = fmaxf(mx1, __shfl_xor_sync(0xffffffffu, mx1, 1));
        mx1 = fmaxf(mx1, __shfl_xor_sync(0xffffffffu, mx1, 2));
        float mn0 = fmaxf(m0, mx0), mn1 = fmaxf(m1, mx1);
        float f0 = ex2((m0 - mn0) * LOG2E), f1 = ex2((m1 - mn1) * LOG2E);

        if (!__all_sync(0xffffffffu, (f0 == 1.f) && (f1 == 1.f))) {
            l0p *= f0; l1p *= f1;
            #pragma unroll
            for (int df = 0; df < 8; df++) {
                oacc[df][0] *= f0; oacc[df][1] *= f0;
                oacc[df][2] *= f1; oacc[df][3] *= f1;
            }
        }
        m0 = mn0; m1 = mn1;

        #pragma unroll
        for (int nf = 0; nf < 8; nf++) {
            sacc[nf][0] = ex2((sacc[nf][0] - mn0) * LOG2E);
            sacc[nf][1] = ex2((sacc[nf][1] - mn0) * LOG2E);
            sacc[nf][2] = ex2((sacc[nf][2] - mn1) * LOG2E);
            sacc[nf][3] = ex2((sacc[nf][3] - mn1) * LOG2E);
            l0p += sacc[nf][0] + sacc[nf][1];
            l1p += sacc[nf][2] + sacc[nf][3];
        }

        uint32_t phi[4][4], plo[4][4];
        #pragma unroll
        for (int ks = 0; ks < 4; ks++) {
            int j = 2 * ks;
            float p00 = sacc[j][0],   p01 = sacc[j][1];
            float p02 = sacc[j][2],   p03 = sacc[j][3];
            float p10 = sacc[j+1][0], p11 = sacc[j+1][1];
            float p12 = sacc[j+1][2], p13 = sacc[j+1][3];
            phi[ks][0] = packbf2(p00, p01);
            phi[ks][1] = packbf2(p02, p03);
            phi[ks][2] = packbf2(p10, p11);
            phi[ks][3] = packbf2(p12, p13);
            __nv_bfloat162* hp;
            hp = (__nv_bfloat162*)&phi[ks][0];
            plo[ks][0] = packbf2(p00 - __bfloat162float(hp->x), p01 - __bfloat162float(hp->y));
            hp = (__nv_bfloat162*)&phi[ks][1];
            plo[ks][1] = packbf2(p02 - __bfloat162float(hp->x), p03 - __bfloat162float(hp->y));
            hp = (__nv_bfloat162*)&phi[ks][2];
            plo[ks][2] = packbf2(p10 - __bfloat162float(hp->x), p11 - __bfloat162float(hp->y));
            hp = (__nv_bfloat162*)&phi[ks][3];
            plo[ks][3] = packbf2(p12 - __bfloat162float(hp->x), p13 - __bfloat162float(hp->y));
        }

        #pragma unroll
        for (int d2 = 0; d2 < 4; d2++) {
            #pragma unroll
            for (int ks = 0; ks < 4; ks++) {
                uint32_t vb[4];
                ldsm_x4(vb, vbase + ((d2*16 + bRowP) * QSTR + ks*16 + bColP) * 2);
                mma_bf16(oacc[2*d2],   phi[ks], &vb[0]);
                mma_bf16(oacc[2*d2+1], phi[ks], &vb[2]);
                mma_bf16(oacc[2*d2],   plo[ks], &vb[0]);
                mma_bf16(oacc[2*d2+1], plo[ks], &vb[2]);
            }
            #pragma unroll
            for (int ks = 0; ks < 4; ks++) {
                uint32_t vb[4];
                ldsm_x4(vb, vbase + ((d2*16 + bRowP) * QSTR + 64 + ks*16 + bColP) * 2);
                mma_bf16(oacc[2*d2],   phi[ks], &vb[0]);
                mma_bf16(oacc[2*d2+1], phi[ks], &vb[2]);
            }
        }
    }

    l0p += __shfl_xor_sync(0xffffffffu, l0p, 1);
    l0p += __shfl_xor_sync(0xffffffffu, l0p, 2);
    l1p += __shfl_xor_sync(0xffffffffu, l1p, 1);
    l1p += __shfl_xor_sync(0xffffffffu, l1p, 2);

    float inv0 = 1.f / l0p, inv1 = 1.f / l1p;
    int b = bh >> 3, h = bh & 7;
    int row0 = q0 + w * 16 + (lane >> 2);
    #pragma unroll
    for (int df = 0; df < 8; df++) {
        int chn = h * HD + df * 8 + (lane & 3) * 2;
        #pragma unroll
        for (int r = 0; r < 2; r++) {
            int row = row0 + r * 8;
            float v0 = oacc[df][r*2 + 0] * (r ? inv1 : inv0);
            float v1 = oacc[df][r*2 + 1] * (r ? inv1 : inv0);
            uint32_t hp = packbf2(v0, v1);
            __nv_bfloat162 hb = *(__nv_bfloat162*)&hp;
            uint32_t lp = packbf2(v0 - __bfloat162float(hb.x), v1 - __bfloat162float(hb.y));
            size_t eb = ((size_t)b * N_ + row) * 1024 + chn;
            *(uint32_t*)&g_obuf[eb]       = hp;
            *(uint32_t*)&g_obuf[eb + 512] = lp;
        }
    }
}

// ---------------------------------------------------------------------------
// 4) Proj GEMM + bias + residual -> out[b][c][n]
// ---------------------------------------------------------------------------
__global__ __launch_bounds__(256, 2) void proj_gemm(const float* __restrict__ bias,
                                                    const float* __restrict__ x,
                                                    float* __restrict__ out) {
    int n0 = blockIdx.x * 128, m0 = blockIdx.y * 128, b = blockIdx.z;

    float acc[4][4][4];
    #pragma unroll
    for (int i = 0; i < 4; i++)
        #pragma unroll
        for (int j = 0; j < 4; j++)
            { acc[i][j][0]=0.f; acc[i][j][1]=0.f; acc[i][j][2]=0.f; acc[i][j][3]=0.f; }

    gemm_mainloop(acc,
        g_wproj + (size_t)m0 * 1024,
        g_obuf + ((size_t)b * N_ + n0) * 1024);

    int wid = threadIdx.x >> 5, lane = threadIdx.x & 31;
    int wm = (wid >> 2) * 64, wn = (wid & 3) * 32;

    #pragma unroll
    for (int mi = 0; mi < 4; mi++) {
        #pragma unroll
        for (int half = 0; half < 2; half++) {
            int chn = m0 + wm + mi*16 + (lane >> 2) + half*8;
            float bv = bias[chn];
            size_t rowbase = ((size_t)b * C_ + chn) * N_;
            #pragma unroll
            for (int ni = 0; ni < 4; ni++) {
                int n = n0 + wn + ni*8 + (lane & 3)*2;
                float2 xv = *(const float2*)&x[rowbase + n];
                float2 v;
                v.x = acc[mi][ni][half*2 + 0] + bv + xv.x;
                v.y = acc[mi][ni][half*2 + 1] + bv + xv.y;
                *(float2*)&out[rowbase + n] = v;
            }
        }
    }
}

// ---------------------------------------------------------------------------
extern "C" void kernel_launch(void* const* d_in, const int* in_sizes, int n_in,
                              void* d_out, int out_size) {
    const float* x      = (const float*)d_in[0];
    const float* norm_w = (const float*)d_in[1];
    const float* norm_b = (const float*)d_in[2];
    const float* qkv_w  = (const float*)d_in[3];
    const float* qkv_b  = (const float*)d_in[4];
    const float* proj_w = (const float*)d_in[5];
    const float* proj_b = (const float*)d_in[6];
    float* out = (float*)d_out;

    cudaFuncSetAttribute(qkv_gemm, cudaFuncAttributeMaxDynamicSharedMemorySize, GEMM_SMEM);
    cudaFuncSetAttribute(proj_gemm, cudaFuncAttributeMaxDynamicSharedMemorySize, GEMM_SMEM);
    cudaFuncSetAttribute(attn_kernel, cudaFuncAttributeMaxDynamicSharedMemorySize, ATTN_SMEM);

    convw_kernel<<<4 * C_, 128>>>(qkv_w, proj_w);
    gn_kernel<<<B_ * G_, 256>>>(x, norm_w, norm_b);
    qkv_gemm<<<dim3(N_ / 128, (3 * C_) / 128, B_), 256, GEMM_SMEM>>>(qkv_b);
    attn_kernel<<<dim3(N_ / 128, B_ * NH), 256, ATTN_SMEM>>>();
    proj_gemm<<<dim3(N_ / 128, C_ / 128, B_), 256, GEMM_SMEM>>>(proj_b, x, out);
}